// round 1
// baseline (speedup 1.0000x reference)
#include <cuda_runtime.h>
#include <cuda_bf16.h>

// ---------------- problem constants ----------------
#define BDIM   16
#define CH     512
#define NTOK   1024          // H*W = 32*32
#define NT     (BDIM*NTOK)   // 16384 token rows
#define NHEADS 8
#define HDIM   64
#define FFN    2048
#define EPSV   1e-6f

// ---------------- scratch (device globals: allocation-free rule) ----------------
__device__ float g_ada [BDIM*6*CH];         // (16, 3072)
__device__ float g_h   [NT*CH];             // residual stream, (B*N, C)
__device__ float g_hn  [NT*CH];             // normalized+modulated
__device__ float g_qkv [NT*3*CH];           // (B*N, 1536)
__device__ float g_att [NT*CH];             // attention out (B*N, C)
__device__ float g_tmp [NT*CH];             // proj out / ffn out (reused)
__device__ float g_x12 [NT*2*FFN];          // (B*N, 4096)
__device__ float g_gate[NT*FFN];            // silu(x1)*x2
__device__ float g_stats[BDIM*32*2];        // groupnorm mu, rstd

// ---------------- adaLN: silu(temb) @ ada_w.T + ada_b ----------------
__global__ void k_ada(const float* __restrict__ temb, const float* __restrict__ ada_w,
                      const float* __restrict__ ada_b) {
    __shared__ float s[CH];
    const int b = blockIdx.y;
    for (int i = threadIdx.x; i < CH; i += blockDim.x) {
        float v = temb[b*CH + i];
        s[i] = v / (1.f + __expf(-v));
    }
    __syncthreads();
    const int n = blockIdx.x * blockDim.x + threadIdx.x;   // 0..3071
    const float* wr = ada_w + (size_t)n * CH;
    float acc = 0.f;
    #pragma unroll 8
    for (int k = 0; k < CH; k++) acc += wr[k] * s[k];
    g_ada[b*6*CH + n] = acc + ada_b[n];
}

// ---------------- GroupNorm stats: per (b, group of 16 ch) over 16*1024 contiguous ----------------
__global__ void k_gnstats(const float* __restrict__ x) {
    const int bg = blockIdx.x;                              // b*32 + g
    const float* p = x + (size_t)bg * 16 * NTOK;
    float s = 0.f, s2 = 0.f;
    for (int i = threadIdx.x; i < 16*NTOK; i += blockDim.x) {
        float v = p[i]; s += v; s2 += v*v;
    }
    #pragma unroll
    for (int o = 16; o; o >>= 1) {
        s  += __shfl_xor_sync(0xffffffffu, s,  o);
        s2 += __shfl_xor_sync(0xffffffffu, s2, o);
    }
    __shared__ float sh[64];
    const int w = threadIdx.x >> 5, l = threadIdx.x & 31;
    if (l == 0) { sh[w] = s; sh[32 + w] = s2; }
    __syncthreads();
    if (threadIdx.x < 32) {
        const int nw = blockDim.x >> 5;
        s  = (threadIdx.x < nw) ? sh[threadIdx.x]      : 0.f;
        s2 = (threadIdx.x < nw) ? sh[32 + threadIdx.x] : 0.f;
        #pragma unroll
        for (int o = 16; o; o >>= 1) {
            s  += __shfl_xor_sync(0xffffffffu, s,  o);
            s2 += __shfl_xor_sync(0xffffffffu, s2, o);
        }
        if (threadIdx.x == 0) {
            const float inv = 1.f / (16.f * NTOK);
            float mu  = s * inv;
            float var = s2 * inv - mu * mu;
            g_stats[bg*2]     = mu;
            g_stats[bg*2 + 1] = rsqrtf(var + EPSV);
        }
    }
}

// ---------------- GroupNorm apply + NCHW -> (B*N, C) transpose via smem tiles ----------------
__global__ void k_gnapply(const float* __restrict__ x, const float* __restrict__ gw,
                          const float* __restrict__ gb) {
    __shared__ float tile[32][33];
    const int b  = blockIdx.y;
    const int n0 = blockIdx.x * 32;
    const int tx = threadIdx.x, ty = threadIdx.y;
    for (int c0 = 0; c0 < CH; c0 += 32) {
        __syncthreads();
        tile[ty][tx] = x[((size_t)b*CH + c0 + ty)*NTOK + n0 + tx];
        __syncthreads();
        const int c  = c0 + tx;
        const float mu = g_stats[(b*32 + (c >> 4))*2];
        const float rs = g_stats[(b*32 + (c >> 4))*2 + 1];
        g_h[((size_t)b*NTOK + n0 + ty)*CH + c] = (tile[tx][ty] - mu) * rs * gw[c] + gb[c];
    }
}

// ---------------- RMSNorm(h) * (1+scale) + shift -> g_hn ----------------
__global__ void k_rmsmod(const float* __restrict__ w, int shift_ch, int scale_ch) {
    const int row = blockIdx.x;
    const int b = row >> 10;
    const float* hp = g_h + (size_t)row * CH;
    const int t = threadIdx.x;                               // 128 threads, 4 elems each
    float4 v = *(const float4*)(hp + t*4);
    float ss = v.x*v.x + v.y*v.y + v.z*v.z + v.w*v.w;
    #pragma unroll
    for (int o = 16; o; o >>= 1) ss += __shfl_xor_sync(0xffffffffu, ss, o);
    __shared__ float sh[4];
    if ((t & 31) == 0) sh[t >> 5] = ss;
    __syncthreads();
    ss = sh[0] + sh[1] + sh[2] + sh[3];
    const float r = rsqrtf(ss / (float)CH + EPSV);
    const float* shf = g_ada + b*6*CH + shift_ch*CH;
    const float* scl = g_ada + b*6*CH + scale_ch*CH;
    const int c = t*4;
    float4 o4;
    o4.x = v.x * r * w[c+0] * (1.f + scl[c+0]) + shf[c+0];
    o4.y = v.y * r * w[c+1] * (1.f + scl[c+1]) + shf[c+1];
    o4.z = v.z * r * w[c+2] * (1.f + scl[c+2]) + shf[c+2];
    o4.w = v.w * r * w[c+3] * (1.f + scl[c+3]) + shf[c+3];
    *(float4*)(g_hn + (size_t)row*CH + c) = o4;
}

// ---------------- SGEMM: C[M,N] = A[M,K] @ W[N,K]^T + bias, 128x128x8, 8x8/thread ----------------
__global__ __launch_bounds__(256) void k_sgemm(
    const float* __restrict__ A, const float* __restrict__ W,
    const float* __restrict__ bias, float* __restrict__ Cm,
    int M, int N, int K)
{
    __shared__ float As[8][128];
    __shared__ float Ws[8][128];
    const int tid = threadIdx.x;
    const int bm = blockIdx.y * 128, bn = blockIdx.x * 128;
    const int trow = (tid >> 4) * 8, tcol = (tid & 15) * 8;
    float acc[8][8] = {};
    const int lrow = tid >> 1, lcol = (tid & 1) * 4;
    const float* Ap = A + (size_t)(bm + lrow) * K + lcol;
    const float* Wp = W + (size_t)(bn + lrow) * K + lcol;
    for (int k0 = 0; k0 < K; k0 += 8) {
        float4 a = *(const float4*)(Ap + k0);
        float4 w = *(const float4*)(Wp + k0);
        As[lcol+0][lrow] = a.x; As[lcol+1][lrow] = a.y;
        As[lcol+2][lrow] = a.z; As[lcol+3][lrow] = a.w;
        Ws[lcol+0][lrow] = w.x; Ws[lcol+1][lrow] = w.y;
        Ws[lcol+2][lrow] = w.z; Ws[lcol+3][lrow] = w.w;
        __syncthreads();
        #pragma unroll
        for (int k = 0; k < 8; k++) {
            float ar[8], wr[8];
            #pragma unroll
            for (int i = 0; i < 8; i++) ar[i] = As[k][trow + i];
            #pragma unroll
            for (int j = 0; j < 8; j++) wr[j] = Ws[k][tcol + j];
            #pragma unroll
            for (int i = 0; i < 8; i++)
                #pragma unroll
                for (int j = 0; j < 8; j++) acc[i][j] += ar[i] * wr[j];
        }
        __syncthreads();
    }
    #pragma unroll
    for (int i = 0; i < 8; i++) {
        float* cp = Cm + (size_t)(bm + trow + i) * N + bn + tcol;
        #pragma unroll
        for (int j = 0; j < 8; j++) cp[j] = acc[i][j] + bias[bn + tcol + j];
    }
}

// ---------------- q/k RMSNorm + 2D axial RoPE (in-place on g_qkv); q *= hd^-0.5 ----------------
__global__ void k_qkrope(const float* __restrict__ qn_w, const float* __restrict__ kn_w) {
    const int gw   = (blockIdx.x * blockDim.x + threadIdx.x) >> 5;  // global warp = token*8+head
    const int lane = threadIdx.x & 31;
    const int head = gw & 7;
    const int tok  = gw >> 3;                                        // 0..16383
    const int n = tok & 1023;
    const int rrow = n >> 5, rcol = n & 31;
    float* qp = g_qkv + (size_t)tok * (3*CH) + head * HDIM;
    float* kp = qp + CH;
    const int j = lane * 2;
    float q0 = qp[j], q1 = qp[j+1], k0 = kp[j], k1 = kp[j+1];
    float sq = q0*q0 + q1*q1, sk = k0*k0 + k1*k1;
    #pragma unroll
    for (int o = 16; o; o >>= 1) {
        sq += __shfl_xor_sync(0xffffffffu, sq, o);
        sk += __shfl_xor_sync(0xffffffffu, sk, o);
    }
    const float rq = rsqrtf(sq / 64.f + EPSV);
    const float rk = rsqrtf(sk / 64.f + EPSV);
    q0 *= rq * qn_w[j];  q1 *= rq * qn_w[j+1];
    k0 *= rk * kn_w[j];  k1 *= rk * kn_w[j+1];
    // 2D axial rope: first 32 dims use row index, last 32 use col index
    const int half = (j >= 32);
    const int idx  = (half ? (j - 32) : j) >> 1;                     // 0..15
    const float freq = exp2f(-(float)idx * (13.287712379549449f / 16.f)); // 10000^(-idx/16)
    const float f = (half ? (float)rcol : (float)rrow) * freq;
    const float cf = cosf(f), sf = sinf(f);
    const float qa = q0*cf - q1*sf, qb = q1*cf + q0*sf;
    const float ka = k0*cf - k1*sf, kb = k1*cf + k0*sf;
    const float qs = 0.125f;                                         // HD^-0.5 folded into q
    qp[j] = qa*qs;  qp[j+1] = qb*qs;
    kp[j] = ka;     kp[j+1] = kb;
}

// ---------------- flash attention: one query per thread, K/V tiles of 32 in smem ----------------
__global__ __launch_bounds__(128) void k_attn() {
    const int pair = blockIdx.x;                 // b*8 + head
    const int b = pair >> 3, hh = pair & 7;
    const int t = threadIdx.x;
    const int qn = blockIdx.y * 128 + t;
    const float* base = g_qkv + (size_t)b * NTOK * (3*CH);
    float q[64];
    {
        const float* qp = base + (size_t)qn * (3*CH) + hh * HDIM;
        #pragma unroll
        for (int d = 0; d < 64; d += 4) {
            float4 v = *(const float4*)(qp + d);
            q[d] = v.x; q[d+1] = v.y; q[d+2] = v.z; q[d+3] = v.w;
        }
    }
    float m = -1e30f, l = 0.f;
    float o[64];
    #pragma unroll
    for (int d = 0; d < 64; d++) o[d] = 0.f;

    __shared__ float Ks[32][64];
    __shared__ float Vs[32][64];
    __shared__ float Ss[32][128];

    for (int kc = 0; kc < NTOK; kc += 32) {
        __syncthreads();
        #pragma unroll
        for (int i = t; i < 32*64; i += 128) {
            const int kk = i >> 6, d = i & 63;
            const float* kp = base + (size_t)(kc + kk) * (3*CH) + CH + hh * HDIM;
            Ks[kk][d] = kp[d];
            Vs[kk][d] = kp[CH + d];          // V lives 512 floats after K
        }
        __syncthreads();
        float cmax = -1e30f;
        #pragma unroll 2
        for (int j = 0; j < 32; j++) {
            float s = 0.f;
            #pragma unroll
            for (int d = 0; d < 64; d += 4)
                s += q[d]*Ks[j][d] + q[d+1]*Ks[j][d+1] + q[d+2]*Ks[j][d+2] + q[d+3]*Ks[j][d+3];
            Ss[j][t] = s;
            cmax = fmaxf(cmax, s);
        }
        const float mnew = fmaxf(m, cmax);
        const float corr = __expf(m - mnew);
        l *= corr;
        #pragma unroll
        for (int d = 0; d < 64; d++) o[d] *= corr;
        #pragma unroll 2
        for (int j = 0; j < 32; j++) {
            const float p = __expf(Ss[j][t] - mnew);
            l += p;
            #pragma unroll
            for (int d = 0; d < 64; d++) o[d] += p * Vs[j][d];
        }
        m = mnew;
    }
    const float inv = 1.f / l;
    float* op = g_att + (size_t)(b * NTOK + qn) * CH + hh * HDIM;
    #pragma unroll
    for (int d = 0; d < 64; d++) op[d] = o[d] * inv;
}

// ---------------- gated residual: h += gate[b,c] * src ----------------
__global__ void k_resid(const float* __restrict__ src, int gate_ch) {
    const int i = blockIdx.x * blockDim.x + threadIdx.x;     // over NT*CH/4
    const int c4 = i & (CH/4 - 1);
    const int row = i >> 7;                                  // /(CH/4)
    const int b = row >> 10;
    const float* gp = g_ada + b*6*CH + gate_ch*CH + c4*4;
    const size_t off = (size_t)row*CH + c4*4;
    float4 s = *(const float4*)(src + off);
    float4 h = *(const float4*)(g_h + off);
    h.x += gp[0]*s.x; h.y += gp[1]*s.y; h.z += gp[2]*s.z; h.w += gp[3]*s.w;
    *(float4*)(g_h + off) = h;
}

// ---------------- SwiGLU gate: silu(x1) * x2 ----------------
__global__ void k_swiglu() {
    const int i = blockIdx.x * blockDim.x + threadIdx.x;     // over NT*FFN
    const int row = i >> 11;                                 // /FFN
    const int j   = i & (FFN - 1);
    const float x1 = g_x12[(size_t)row*2*FFN + j];
    const float x2 = g_x12[(size_t)row*2*FFN + FFN + j];
    g_gate[i] = (x1 / (1.f + __expf(-x1))) * x2;
}

// ---------------- final: out[b,c,n] = x + h + gp*ffo, with (N,C)->(C,N) transpose ----------------
__global__ void k_final(const float* __restrict__ x, float* __restrict__ out) {
    __shared__ float th[32][33], tf[32][33];
    const int b  = blockIdx.y;
    const int n0 = blockIdx.x * 32;
    const int tx = threadIdx.x, ty = threadIdx.y;
    for (int c0 = 0; c0 < CH; c0 += 32) {
        __syncthreads();
        const size_t ridx = ((size_t)b*NTOK + n0 + ty)*CH + c0 + tx;
        th[ty][tx] = g_h[ridx];
        tf[ty][tx] = g_tmp[ridx];
        __syncthreads();
        const int c = c0 + ty;
        const float g = g_ada[b*6*CH + 5*CH + c];
        const size_t oidx = ((size_t)b*CH + c)*NTOK + n0 + tx;
        out[oidx] = x[oidx] + th[tx][ty] + g * tf[tx][ty];
    }
}

// ---------------- launcher ----------------
extern "C" void kernel_launch(void* const* d_in, const int* in_sizes, int n_in,
                              void* d_out, int out_size) {
    const float* x      = (const float*)d_in[0];
    const float* temb   = (const float*)d_in[1];
    const float* gn_w   = (const float*)d_in[2];
    const float* gn_b   = (const float*)d_in[3];
    const float* ada_w  = (const float*)d_in[4];
    const float* ada_b  = (const float*)d_in[5];
    const float* n1_w   = (const float*)d_in[6];
    const float* n2_w   = (const float*)d_in[7];
    const float* qkv_w  = (const float*)d_in[8];
    const float* qkv_b  = (const float*)d_in[9];
    const float* qn_w   = (const float*)d_in[10];
    const float* kn_w   = (const float*)d_in[11];
    const float* proj_w = (const float*)d_in[12];
    const float* proj_b = (const float*)d_in[13];
    const float* w12    = (const float*)d_in[14];
    const float* b12    = (const float*)d_in[15];
    const float* w_out  = (const float*)d_in[16];
    const float* b_out  = (const float*)d_in[17];
    float* out = (float*)d_out;

    float *p_hn, *p_qkv, *p_att, *p_tmp, *p_x12, *p_gate;
    cudaGetSymbolAddress((void**)&p_hn,   g_hn);
    cudaGetSymbolAddress((void**)&p_qkv,  g_qkv);
    cudaGetSymbolAddress((void**)&p_att,  g_att);
    cudaGetSymbolAddress((void**)&p_tmp,  g_tmp);
    cudaGetSymbolAddress((void**)&p_x12,  g_x12);
    cudaGetSymbolAddress((void**)&p_gate, g_gate);

    // adaLN + GroupNorm
    k_ada    <<<dim3(24, BDIM), 128>>>(temb, ada_w, ada_b);
    k_gnstats<<<BDIM*32, 256>>>(x);
    k_gnapply<<<dim3(NTOK/32, BDIM), dim3(32,32)>>>(x, gn_w, gn_b);

    // attention branch
    k_rmsmod <<<NT, 128>>>(n1_w, 0, 1);
    k_sgemm  <<<dim3((3*CH)/128, NT/128), 256>>>(p_hn, qkv_w, qkv_b, p_qkv, NT, 3*CH, CH);
    k_qkrope <<<(NT*NHEADS*32)/128, 128>>>(qn_w, kn_w);
    k_attn   <<<dim3(BDIM*NHEADS, NTOK/128), 128>>>();
    k_sgemm  <<<dim3(CH/128, NT/128), 256>>>(p_att, proj_w, proj_b, p_tmp, NT, CH, CH);
    k_resid  <<<(NT*CH/4)/256, 256>>>(p_tmp, 2);

    // FFN branch
    k_rmsmod <<<NT, 128>>>(n2_w, 3, 4);
    k_sgemm  <<<dim3((2*FFN)/128, NT/128), 256>>>(p_hn, w12, b12, p_x12, NT, 2*FFN, CH);
    k_swiglu <<<(NT*FFN)/256, 256>>>();
    k_sgemm  <<<dim3(CH/128, NT/128), 256>>>(p_gate, w_out, b_out, p_tmp, NT, CH, FFN);

    // epilogue
    k_final  <<<dim3(NTOK/32, BDIM), dim3(32,32)>>>(x, out);
}

// round 2
// speedup vs baseline: 1.9566x; 1.9566x over previous
#include <cuda_runtime.h>
#include <cuda_bf16.h>
#include <cstdint>

// ---------------- problem constants ----------------
#define BDIM   16
#define CH     512
#define NTOK   1024          // H*W = 32*32
#define NT     (BDIM*NTOK)   // 16384 token rows
#define NHEADS 8
#define HDIM   64
#define FFN    2048
#define EPSV   1e-6f

// ---------------- scratch (device globals: allocation-free rule) ----------------
__device__ float g_ada [BDIM*6*CH];         // (16, 3072)
__device__ float g_h   [NT*CH];             // residual stream, (B*N, C)
__device__ float g_hn  [NT*CH];             // normalized+modulated
__device__ float g_qkv [NT*3*CH];           // (B*N, 1536)
__device__ float g_att [NT*CH];             // attention out (B*N, C)
__device__ float g_tmp [NT*CH];             // proj out / ffn out (reused)
__device__ float g_x12 [NT*2*FFN];          // (B*N, 4096)
__device__ float g_gate[NT*FFN];            // silu(x1)*x2
__device__ float g_stats[BDIM*32*2];        // groupnorm mu, rstd

// ---------------- helpers ----------------
__device__ __forceinline__ uint32_t f2tf32(float f) {
    uint32_t u;
    asm("cvt.rna.tf32.f32 %0, %1;" : "=r"(u) : "f"(f));
    return u;
}

// ---------------- adaLN: silu(temb) @ ada_w.T + ada_b ----------------
__global__ void k_ada(const float* __restrict__ temb, const float* __restrict__ ada_w,
                      const float* __restrict__ ada_b) {
    __shared__ float s[CH];
    const int b = blockIdx.y;
    for (int i = threadIdx.x; i < CH; i += blockDim.x) {
        float v = temb[b*CH + i];
        s[i] = v / (1.f + __expf(-v));
    }
    __syncthreads();
    const int n = blockIdx.x * blockDim.x + threadIdx.x;   // 0..3071
    const float* wr = ada_w + (size_t)n * CH;
    float acc = 0.f;
    #pragma unroll 8
    for (int k = 0; k < CH; k++) acc += wr[k] * s[k];
    g_ada[b*6*CH + n] = acc + ada_b[n];
}

// ---------------- GroupNorm stats ----------------
__global__ void k_gnstats(const float* __restrict__ x) {
    const int bg = blockIdx.x;                              // b*32 + g
    const float* p = x + (size_t)bg * 16 * NTOK;
    float s = 0.f, s2 = 0.f;
    for (int i = threadIdx.x; i < 16*NTOK; i += blockDim.x) {
        float v = p[i]; s += v; s2 += v*v;
    }
    #pragma unroll
    for (int o = 16; o; o >>= 1) {
        s  += __shfl_xor_sync(0xffffffffu, s,  o);
        s2 += __shfl_xor_sync(0xffffffffu, s2, o);
    }
    __shared__ float sh[64];
    const int w = threadIdx.x >> 5, l = threadIdx.x & 31;
    if (l == 0) { sh[w] = s; sh[32 + w] = s2; }
    __syncthreads();
    if (threadIdx.x < 32) {
        const int nw = blockDim.x >> 5;
        s  = (threadIdx.x < nw) ? sh[threadIdx.x]      : 0.f;
        s2 = (threadIdx.x < nw) ? sh[32 + threadIdx.x] : 0.f;
        #pragma unroll
        for (int o = 16; o; o >>= 1) {
            s  += __shfl_xor_sync(0xffffffffu, s,  o);
            s2 += __shfl_xor_sync(0xffffffffu, s2, o);
        }
        if (threadIdx.x == 0) {
            const float inv = 1.f / (16.f * NTOK);
            float mu  = s * inv;
            float var = s2 * inv - mu * mu;
            g_stats[bg*2]     = mu;
            g_stats[bg*2 + 1] = rsqrtf(var + EPSV);
        }
    }
}

// ---------------- GroupNorm apply + NCHW -> (B*N, C) transpose ----------------
__global__ void k_gnapply(const float* __restrict__ x, const float* __restrict__ gw,
                          const float* __restrict__ gb) {
    __shared__ float tile[32][33];
    const int b  = blockIdx.y;
    const int n0 = blockIdx.x * 32;
    const int tx = threadIdx.x, ty = threadIdx.y;
    for (int c0 = 0; c0 < CH; c0 += 32) {
        __syncthreads();
        tile[ty][tx] = x[((size_t)b*CH + c0 + ty)*NTOK + n0 + tx];
        __syncthreads();
        const int c  = c0 + tx;
        const float mu = g_stats[(b*32 + (c >> 4))*2];
        const float rs = g_stats[(b*32 + (c >> 4))*2 + 1];
        g_h[((size_t)b*NTOK + n0 + ty)*CH + c] = (tile[tx][ty] - mu) * rs * gw[c] + gb[c];
    }
}

// ---------------- RMSNorm(h) * (1+scale) + shift -> g_hn ----------------
__global__ void k_rmsmod(const float* __restrict__ w, int shift_ch, int scale_ch) {
    const int row = blockIdx.x;
    const int b = row >> 10;
    const float* hp = g_h + (size_t)row * CH;
    const int t = threadIdx.x;                               // 128 threads, 4 elems each
    float4 v = *(const float4*)(hp + t*4);
    float ss = v.x*v.x + v.y*v.y + v.z*v.z + v.w*v.w;
    #pragma unroll
    for (int o = 16; o; o >>= 1) ss += __shfl_xor_sync(0xffffffffu, ss, o);
    __shared__ float sh[4];
    if ((t & 31) == 0) sh[t >> 5] = ss;
    __syncthreads();
    ss = sh[0] + sh[1] + sh[2] + sh[3];
    const float r = rsqrtf(ss / (float)CH + EPSV);
    const float* shf = g_ada + b*6*CH + shift_ch*CH;
    const float* scl = g_ada + b*6*CH + scale_ch*CH;
    const int c = t*4;
    float4 o4;
    o4.x = v.x * r * w[c+0] * (1.f + scl[c+0]) + shf[c+0];
    o4.y = v.y * r * w[c+1] * (1.f + scl[c+1]) + shf[c+1];
    o4.z = v.z * r * w[c+2] * (1.f + scl[c+2]) + shf[c+2];
    o4.w = v.w * r * w[c+3] * (1.f + scl[c+3]) + shf[c+3];
    *(float4*)(g_hn + (size_t)row*CH + c) = o4;
}

// ---------------- TF32 tensor-core GEMM: C[M,N] = A[M,K] @ W[N,K]^T + bias ----------------
// 128x128x32 tiles, 8 warps, warp tile 32x64, mma.m16n8k8 tf32
#define SSTR 36   // smem row stride (floats): banks (4*gid + tig) % 32 all distinct
__global__ __launch_bounds__(256) void k_gemm_tf32(
    const float* __restrict__ A, const float* __restrict__ W,
    const float* __restrict__ bias, float* __restrict__ Cm,
    int M, int N, int K)
{
    __shared__ float As[128*SSTR];
    __shared__ float Ws[128*SSTR];
    const int tid  = threadIdx.x;
    const int lane = tid & 31;
    const int warp = tid >> 5;
    const int gid  = lane >> 2;      // 0..7
    const int tig  = lane & 3;       // 0..3
    const int wm   = warp & 3;       // 4 warps along M
    const int wn   = warp >> 2;      // 2 warps along N
    const int row0 = wm * 32;
    const int col0 = wn * 64;
    const int bm = blockIdx.y * 128, bn = blockIdx.x * 128;

    float acc[2][8][4];
    #pragma unroll
    for (int i = 0; i < 2; i++)
        #pragma unroll
        for (int j = 0; j < 8; j++)
            #pragma unroll
            for (int c = 0; c < 4; c++) acc[i][j][c] = 0.f;

    for (int k0 = 0; k0 < K; k0 += 32) {
        // load 128x32 tiles of A and W (as tf32-rounded floats)
        #pragma unroll
        for (int i = 0; i < 4; i++) {
            const int lin = tid + i*256;          // 0..1023
            const int r  = lin >> 3;
            const int c4 = (lin & 7) * 4;
            float4 a = *(const float4*)(A + (size_t)(bm + r)*K + k0 + c4);
            float4 w = *(const float4*)(W + (size_t)(bn + r)*K + k0 + c4);
            float* ap = As + r*SSTR + c4;
            float* wp = Ws + r*SSTR + c4;
            ap[0] = __uint_as_float(f2tf32(a.x)); ap[1] = __uint_as_float(f2tf32(a.y));
            ap[2] = __uint_as_float(f2tf32(a.z)); ap[3] = __uint_as_float(f2tf32(a.w));
            wp[0] = __uint_as_float(f2tf32(w.x)); wp[1] = __uint_as_float(f2tf32(w.y));
            wp[2] = __uint_as_float(f2tf32(w.z)); wp[3] = __uint_as_float(f2tf32(w.w));
        }
        __syncthreads();
        #pragma unroll
        for (int kk = 0; kk < 4; kk++) {
            const int k = kk * 8;
            // A fragments: 2 m-tiles
            uint32_t af[2][4];
            #pragma unroll
            for (int mt = 0; mt < 2; mt++) {
                const float* p = As + (row0 + mt*16 + gid)*SSTR + k + tig;
                af[mt][0] = __float_as_uint(p[0]);
                af[mt][1] = __float_as_uint(p[8*SSTR]);
                af[mt][2] = __float_as_uint(p[4]);
                af[mt][3] = __float_as_uint(p[8*SSTR + 4]);
            }
            // B fragments: 8 n-tiles
            uint32_t bf[8][2];
            #pragma unroll
            for (int nt = 0; nt < 8; nt++) {
                const float* p = Ws + (col0 + nt*8 + gid)*SSTR + k + tig;
                bf[nt][0] = __float_as_uint(p[0]);
                bf[nt][1] = __float_as_uint(p[4]);
            }
            #pragma unroll
            for (int mt = 0; mt < 2; mt++)
                #pragma unroll
                for (int nt = 0; nt < 8; nt++) {
                    asm volatile(
                        "mma.sync.aligned.m16n8k8.row.col.f32.tf32.tf32.f32 "
                        "{%0,%1,%2,%3}, {%4,%5,%6,%7}, {%8,%9}, {%0,%1,%2,%3};"
                        : "+f"(acc[mt][nt][0]), "+f"(acc[mt][nt][1]),
                          "+f"(acc[mt][nt][2]), "+f"(acc[mt][nt][3])
                        : "r"(af[mt][0]), "r"(af[mt][1]), "r"(af[mt][2]), "r"(af[mt][3]),
                          "r"(bf[nt][0]), "r"(bf[nt][1]));
                }
        }
        __syncthreads();
    }
    // epilogue
    #pragma unroll
    for (int mt = 0; mt < 2; mt++) {
        const int row = bm + row0 + mt*16 + gid;
        #pragma unroll
        for (int nt = 0; nt < 8; nt++) {
            const int col = bn + col0 + nt*8 + tig*2;
            const float b0 = bias[col], b1 = bias[col+1];
            float2 v0 = { acc[mt][nt][0] + b0, acc[mt][nt][1] + b1 };
            float2 v1 = { acc[mt][nt][2] + b0, acc[mt][nt][3] + b1 };
            *(float2*)(Cm + (size_t)row*N + col)     = v0;
            *(float2*)(Cm + (size_t)(row+8)*N + col) = v1;
        }
    }
}

// ---------------- q/k RMSNorm + 2D axial RoPE (in-place); q *= hd^-0.5 ----------------
__global__ void k_qkrope(const float* __restrict__ qn_w, const float* __restrict__ kn_w) {
    const int gw   = (blockIdx.x * blockDim.x + threadIdx.x) >> 5;  // token*8+head
    const int lane = threadIdx.x & 31;
    const int head = gw & 7;
    const int tok  = gw >> 3;
    const int n = tok & 1023;
    const int rrow = n >> 5, rcol = n & 31;
    float* qp = g_qkv + (size_t)tok * (3*CH) + head * HDIM;
    float* kp = qp + CH;
    const int j = lane * 2;
    float q0 = qp[j], q1 = qp[j+1], k0 = kp[j], k1 = kp[j+1];
    float sq = q0*q0 + q1*q1, sk = k0*k0 + k1*k1;
    #pragma unroll
    for (int o = 16; o; o >>= 1) {
        sq += __shfl_xor_sync(0xffffffffu, sq, o);
        sk += __shfl_xor_sync(0xffffffffu, sk, o);
    }
    const float rq = rsqrtf(sq / 64.f + EPSV);
    const float rk = rsqrtf(sk / 64.f + EPSV);
    q0 *= rq * qn_w[j];  q1 *= rq * qn_w[j+1];
    k0 *= rk * kn_w[j];  k1 *= rk * kn_w[j+1];
    const int half = (j >= 32);
    const int idx  = (half ? (j - 32) : j) >> 1;
    const float freq = exp2f(-(float)idx * (13.287712379549449f / 16.f)); // 10000^(-idx/16)
    const float f = (half ? (float)rcol : (float)rrow) * freq;
    const float cf = cosf(f), sf = sinf(f);
    const float qa = q0*cf - q1*sf, qb = q1*cf + q0*sf;
    const float ka = k0*cf - k1*sf, kb = k1*cf + k0*sf;
    const float qs = 0.125f;
    qp[j] = qa*qs;  qp[j+1] = qb*qs;
    kp[j] = ka;     kp[j+1] = kb;
}

// ---------------- flash attention (SIMT, fp32) ----------------
__global__ __launch_bounds__(128) void k_attn() {
    const int pair = blockIdx.x;                 // b*8 + head
    const int b = pair >> 3, hh = pair & 7;
    const int t = threadIdx.x;
    const int qn = blockIdx.y * 128 + t;
    const float* base = g_qkv + (size_t)b * NTOK * (3*CH);
    float q[64];
    {
        const float* qp = base + (size_t)qn * (3*CH) + hh * HDIM;
        #pragma unroll
        for (int d = 0; d < 64; d += 4) {
            float4 v = *(const float4*)(qp + d);
            q[d] = v.x; q[d+1] = v.y; q[d+2] = v.z; q[d+3] = v.w;
        }
    }
    float m = -1e30f, l = 0.f;
    float o[64];
    #pragma unroll
    for (int d = 0; d < 64; d++) o[d] = 0.f;

    __shared__ float Ks[32][64];
    __shared__ float Vs[32][64];
    __shared__ float Ss[32][128];

    for (int kc = 0; kc < NTOK; kc += 32) {
        __syncthreads();
        #pragma unroll
        for (int i = t; i < 32*64; i += 128) {
            const int kk = i >> 6, d = i & 63;
            const float* kp = base + (size_t)(kc + kk) * (3*CH) + CH + hh * HDIM;
            Ks[kk][d] = kp[d];
            Vs[kk][d] = kp[CH + d];
        }
        __syncthreads();
        float cmax = -1e30f;
        #pragma unroll 2
        for (int j = 0; j < 32; j++) {
            float s = 0.f;
            #pragma unroll
            for (int d = 0; d < 64; d += 4)
                s += q[d]*Ks[j][d] + q[d+1]*Ks[j][d+1] + q[d+2]*Ks[j][d+2] + q[d+3]*Ks[j][d+3];
            Ss[j][t] = s;
            cmax = fmaxf(cmax, s);
        }
        const float mnew = fmaxf(m, cmax);
        const float corr = __expf(m - mnew);
        l *= corr;
        #pragma unroll
        for (int d = 0; d < 64; d++) o[d] *= corr;
        #pragma unroll 2
        for (int j = 0; j < 32; j++) {
            const float p = __expf(Ss[j][t] - mnew);
            l += p;
            #pragma unroll
            for (int d = 0; d < 64; d++) o[d] += p * Vs[j][d];
        }
        m = mnew;
    }
    const float inv = 1.f / l;
    float* op = g_att + (size_t)(b * NTOK + qn) * CH + hh * HDIM;
    #pragma unroll
    for (int d = 0; d < 64; d++) op[d] = o[d] * inv;
}

// ---------------- gated residual: h += gate[b,c] * src ----------------
__global__ void k_resid(const float* __restrict__ src, int gate_ch) {
    const int i = blockIdx.x * blockDim.x + threadIdx.x;     // over NT*CH/4
    const int c4 = i & (CH/4 - 1);
    const int row = i >> 7;
    const int b = row >> 10;
    const float* gp = g_ada + b*6*CH + gate_ch*CH + c4*4;
    const size_t off = (size_t)row*CH + c4*4;
    float4 s = *(const float4*)(src + off);
    float4 h = *(const float4*)(g_h + off);
    h.x += gp[0]*s.x; h.y += gp[1]*s.y; h.z += gp[2]*s.z; h.w += gp[3]*s.w;
    *(float4*)(g_h + off) = h;
}

// ---------------- SwiGLU gate: silu(x1) * x2 ----------------
__global__ void k_swiglu() {
    const int i = blockIdx.x * blockDim.x + threadIdx.x;     // over NT*FFN
    const int row = i >> 11;
    const int j   = i & (FFN - 1);
    const float x1 = g_x12[(size_t)row*2*FFN + j];
    const float x2 = g_x12[(size_t)row*2*FFN + FFN + j];
    g_gate[i] = (x1 / (1.f + __expf(-x1))) * x2;
}

// ---------------- final: out[b,c,n] = x + h + gp*ffo, (N,C)->(C,N) ----------------
__global__ void k_final(const float* __restrict__ x, float* __restrict__ out) {
    __shared__ float th[32][33], tf[32][33];
    const int b  = blockIdx.y;
    const int n0 = blockIdx.x * 32;
    const int tx = threadIdx.x, ty = threadIdx.y;
    for (int c0 = 0; c0 < CH; c0 += 32) {
        __syncthreads();
        const size_t ridx = ((size_t)b*NTOK + n0 + ty)*CH + c0 + tx;
        th[ty][tx] = g_h[ridx];
        tf[ty][tx] = g_tmp[ridx];
        __syncthreads();
        const int c = c0 + ty;
        const float g = g_ada[b*6*CH + 5*CH + c];
        const size_t oidx = ((size_t)b*CH + c)*NTOK + n0 + tx;
        out[oidx] = x[oidx] + th[tx][ty] + g * tf[tx][ty];
    }
}

// ---------------- launcher ----------------
extern "C" void kernel_launch(void* const* d_in, const int* in_sizes, int n_in,
                              void* d_out, int out_size) {
    const float* x      = (const float*)d_in[0];
    const float* temb   = (const float*)d_in[1];
    const float* gn_w   = (const float*)d_in[2];
    const float* gn_b   = (const float*)d_in[3];
    const float* ada_w  = (const float*)d_in[4];
    const float* ada_b  = (const float*)d_in[5];
    const float* n1_w   = (const float*)d_in[6];
    const float* n2_w   = (const float*)d_in[7];
    const float* qkv_w  = (const float*)d_in[8];
    const float* qkv_b  = (const float*)d_in[9];
    const float* qn_w   = (const float*)d_in[10];
    const float* kn_w   = (const float*)d_in[11];
    const float* proj_w = (const float*)d_in[12];
    const float* proj_b = (const float*)d_in[13];
    const float* w12    = (const float*)d_in[14];
    const float* b12    = (const float*)d_in[15];
    const float* w_out  = (const float*)d_in[16];
    const float* b_out  = (const float*)d_in[17];
    float* out = (float*)d_out;

    float *p_hn, *p_qkv, *p_att, *p_tmp, *p_x12, *p_gate;
    cudaGetSymbolAddress((void**)&p_hn,   g_hn);
    cudaGetSymbolAddress((void**)&p_qkv,  g_qkv);
    cudaGetSymbolAddress((void**)&p_att,  g_att);
    cudaGetSymbolAddress((void**)&p_tmp,  g_tmp);
    cudaGetSymbolAddress((void**)&p_x12,  g_x12);
    cudaGetSymbolAddress((void**)&p_gate, g_gate);

    // adaLN + GroupNorm
    k_ada    <<<dim3(24, BDIM), 128>>>(temb, ada_w, ada_b);
    k_gnstats<<<BDIM*32, 256>>>(x);
    k_gnapply<<<dim3(NTOK/32, BDIM), dim3(32,32)>>>(x, gn_w, gn_b);

    // attention branch
    k_rmsmod <<<NT, 128>>>(n1_w, 0, 1);
    k_gemm_tf32<<<dim3((3*CH)/128, NT/128), 256>>>(p_hn, qkv_w, qkv_b, p_qkv, NT, 3*CH, CH);
    k_qkrope <<<(NT*NHEADS*32)/128, 128>>>(qn_w, kn_w);
    k_attn   <<<dim3(BDIM*NHEADS, NTOK/128), 128>>>();
    k_gemm_tf32<<<dim3(CH/128, NT/128), 256>>>(p_att, proj_w, proj_b, p_tmp, NT, CH, CH);
    k_resid  <<<(NT*CH/4)/256, 256>>>(p_tmp, 2);

    // FFN branch
    k_rmsmod <<<NT, 128>>>(n2_w, 3, 4);
    k_gemm_tf32<<<dim3((2*FFN)/128, NT/128), 256>>>(p_hn, w12, b12, p_x12, NT, 2*FFN, CH);
    k_swiglu <<<(NT*FFN)/256, 256>>>();
    k_gemm_tf32<<<dim3(CH/128, NT/128), 256>>>(p_gate, w_out, b_out, p_tmp, NT, CH, FFN);

    // epilogue
    k_final  <<<dim3(NTOK/32, BDIM), dim3(32,32)>>>(x, out);
}

// round 3
// speedup vs baseline: 3.1645x; 1.6173x over previous
#include <cuda_runtime.h>
#include <cuda_bf16.h>
#include <cstdint>

// ---------------- problem constants ----------------
#define BDIM   16
#define CH     512
#define NTOK   1024          // H*W = 32*32
#define NT     (BDIM*NTOK)   // 16384 token rows
#define NHEADS 8
#define HDIM   64
#define FFN    2048
#define EPSV   1e-6f

// ---------------- scratch (device globals) ----------------
__device__ float g_ada [BDIM*6*CH];
__device__ float g_h   [NT*CH];
__device__ float g_hn  [NT*CH];             // tf32-rounded
__device__ float g_qkv [NT*3*CH];           // q/k/v tf32-rounded by k_qkrope
__device__ float g_att [NT*CH];             // tf32-rounded
__device__ float g_tmp [NT*CH];
__device__ float g_x12 [NT*2*FFN];
__device__ float g_gate[NT*FFN];            // tf32-rounded
__device__ float g_stats[BDIM*32*2];
// tf32-rounded weight copies
__device__ float g_wqkv [3*CH*CH];
__device__ float g_wproj[CH*CH];
__device__ float g_w12c [2*FFN*CH];
__device__ float g_woc  [CH*FFN];

// ---------------- helpers ----------------
__device__ __forceinline__ uint32_t f2tf32(float f) {
    uint32_t u;
    asm("cvt.rna.tf32.f32 %0, %1;" : "=r"(u) : "f"(f));
    return u;
}
__device__ __forceinline__ float rtf(float f) { return __uint_as_float(f2tf32(f)); }
__device__ __forceinline__ void cpa16(float* s, const float* g) {
    uint32_t sa = (uint32_t)__cvta_generic_to_shared(s);
    asm volatile("cp.async.cg.shared.global [%0], [%1], 16;\n" :: "r"(sa), "l"(g));
}
__device__ __forceinline__ int swz(int r, int c4) { return r*32 + (((c4) ^ (r & 7)) << 2); }

// ---------------- tf32 rounding of weights ----------------
__global__ void k_cvt(const float* __restrict__ s, float* __restrict__ d, int n) {
    const int i = (blockIdx.x * blockDim.x + threadIdx.x) * 4;
    if (i >= n) return;
    float4 v = *(const float4*)(s + i);
    v.x = rtf(v.x); v.y = rtf(v.y); v.z = rtf(v.z); v.w = rtf(v.w);
    *(float4*)(d + i) = v;
}

// ---------------- adaLN ----------------
__global__ void k_ada(const float* __restrict__ temb, const float* __restrict__ ada_w,
                      const float* __restrict__ ada_b) {
    __shared__ float s[CH];
    const int b = blockIdx.y;
    for (int i = threadIdx.x; i < CH; i += blockDim.x) {
        float v = temb[b*CH + i];
        s[i] = v / (1.f + __expf(-v));
    }
    __syncthreads();
    const int n = blockIdx.x * blockDim.x + threadIdx.x;
    const float* wr = ada_w + (size_t)n * CH;
    float acc = 0.f;
    #pragma unroll 8
    for (int k = 0; k < CH; k++) acc += wr[k] * s[k];
    g_ada[b*6*CH + n] = acc + ada_b[n];
}

// ---------------- GroupNorm stats ----------------
__global__ void k_gnstats(const float* __restrict__ x) {
    const int bg = blockIdx.x;
    const float* p = x + (size_t)bg * 16 * NTOK;
    float s = 0.f, s2 = 0.f;
    for (int i = threadIdx.x; i < 16*NTOK; i += blockDim.x) {
        float v = p[i]; s += v; s2 += v*v;
    }
    #pragma unroll
    for (int o = 16; o; o >>= 1) {
        s  += __shfl_xor_sync(0xffffffffu, s,  o);
        s2 += __shfl_xor_sync(0xffffffffu, s2, o);
    }
    __shared__ float sh[64];
    const int w = threadIdx.x >> 5, l = threadIdx.x & 31;
    if (l == 0) { sh[w] = s; sh[32 + w] = s2; }
    __syncthreads();
    if (threadIdx.x < 32) {
        const int nw = blockDim.x >> 5;
        s  = (threadIdx.x < nw) ? sh[threadIdx.x]      : 0.f;
        s2 = (threadIdx.x < nw) ? sh[32 + threadIdx.x] : 0.f;
        #pragma unroll
        for (int o = 16; o; o >>= 1) {
            s  += __shfl_xor_sync(0xffffffffu, s,  o);
            s2 += __shfl_xor_sync(0xffffffffu, s2, o);
        }
        if (threadIdx.x == 0) {
            const float inv = 1.f / (16.f * NTOK);
            float mu  = s * inv;
            float var = s2 * inv - mu * mu;
            g_stats[bg*2]     = mu;
            g_stats[bg*2 + 1] = rsqrtf(var + EPSV);
        }
    }
}

// ---------------- GroupNorm apply + transpose ----------------
__global__ void k_gnapply(const float* __restrict__ x, const float* __restrict__ gw,
                          const float* __restrict__ gb) {
    __shared__ float tile[32][33];
    const int b  = blockIdx.y;
    const int n0 = blockIdx.x * 32;
    const int tx = threadIdx.x, ty = threadIdx.y;
    for (int c0 = 0; c0 < CH; c0 += 32) {
        __syncthreads();
        tile[ty][tx] = x[((size_t)b*CH + c0 + ty)*NTOK + n0 + tx];
        __syncthreads();
        const int c  = c0 + tx;
        const float mu = g_stats[(b*32 + (c >> 4))*2];
        const float rs = g_stats[(b*32 + (c >> 4))*2 + 1];
        g_h[((size_t)b*NTOK + n0 + ty)*CH + c] = (tile[tx][ty] - mu) * rs * gw[c] + gb[c];
    }
}

// ---------------- RMSNorm + modulation (tf32-rounded output) ----------------
__global__ void k_rmsmod(const float* __restrict__ w, int shift_ch, int scale_ch) {
    const int row = blockIdx.x;
    const int b = row >> 10;
    const float* hp = g_h + (size_t)row * CH;
    const int t = threadIdx.x;
    float4 v = *(const float4*)(hp + t*4);
    float ss = v.x*v.x + v.y*v.y + v.z*v.z + v.w*v.w;
    #pragma unroll
    for (int o = 16; o; o >>= 1) ss += __shfl_xor_sync(0xffffffffu, ss, o);
    __shared__ float sh[4];
    if ((t & 31) == 0) sh[t >> 5] = ss;
    __syncthreads();
    ss = sh[0] + sh[1] + sh[2] + sh[3];
    const float r = rsqrtf(ss / (float)CH + EPSV);
    const float* shf = g_ada + b*6*CH + shift_ch*CH;
    const float* scl = g_ada + b*6*CH + scale_ch*CH;
    const int c = t*4;
    float4 o4;
    o4.x = rtf(v.x * r * w[c+0] * (1.f + scl[c+0]) + shf[c+0]);
    o4.y = rtf(v.y * r * w[c+1] * (1.f + scl[c+1]) + shf[c+1]);
    o4.z = rtf(v.z * r * w[c+2] * (1.f + scl[c+2]) + shf[c+2]);
    o4.w = rtf(v.w * r * w[c+3] * (1.f + scl[c+3]) + shf[c+3]);
    *(float4*)(g_hn + (size_t)row*CH + c) = o4;
}

// ---------------- TF32 GEMM, 3-stage cp.async, swizzled smem ----------------
// C[M,N] = A[M,K] @ W[N,K]^T + bias. 128x128x32, 8 warps, warp tile 32x64.
// Inputs A, W must already be tf32-rounded values.
__global__ __launch_bounds__(256) void k_gemm(
    const float* __restrict__ A, const float* __restrict__ W,
    const float* __restrict__ bias, float* __restrict__ Cm,
    int M, int N, int K)
{
    extern __shared__ float sm[];          // 3 stages * (A 4096 + W 4096) floats
    const int tid  = threadIdx.x;
    const int lane = tid & 31;
    const int warp = tid >> 5;
    const int gid  = lane >> 2;
    const int tig  = lane & 3;
    const int wm   = warp & 3;
    const int wn   = warp >> 2;
    const int row0 = wm * 32;
    const int col0 = wn * 64;
    const int bm = blockIdx.y * 128, bn = blockIdx.x * 128;
    const int KT = K >> 5;

    auto load_body = [&](int kt, int s) {
        float* As = sm + s * 8192;
        float* Ws = As + 4096;
        const int k0 = kt << 5;
        #pragma unroll
        for (int i = 0; i < 4; i++) {
            const int lin = tid + i*256;
            const int r = lin >> 3, c4 = lin & 7;
            const int dst = swz(r, c4);
            cpa16(As + dst, A + (size_t)(bm + r)*K + k0 + c4*4);
            cpa16(Ws + dst, W + (size_t)(bn + r)*K + k0 + c4*4);
        }
    };

    load_body(0, 0);
    asm volatile("cp.async.commit_group;\n");
    load_body(1, 1);
    asm volatile("cp.async.commit_group;\n");

    float acc[2][8][4];
    #pragma unroll
    for (int i = 0; i < 2; i++)
        #pragma unroll
        for (int j = 0; j < 8; j++)
            #pragma unroll
            for (int c = 0; c < 4; c++) acc[i][j][c] = 0.f;

    for (int kt = 0; kt < KT; kt++) {
        asm volatile("cp.async.wait_group 1;\n");
        __syncthreads();
        if (kt + 2 < KT) load_body(kt + 2, (kt + 2) % 3);
        asm volatile("cp.async.commit_group;\n");

        const float* As = sm + (kt % 3) * 8192;
        const float* Ws = As + 4096;
        #pragma unroll
        for (int kk = 0; kk < 4; kk++) {
            const int k4 = kk * 2;
            uint32_t af[2][4];
            #pragma unroll
            for (int mt = 0; mt < 2; mt++) {
                const int r = row0 + mt*16 + gid;
                af[mt][0] = __float_as_uint(As[swz(r,   k4)   + tig]);
                af[mt][1] = __float_as_uint(As[swz(r+8, k4)   + tig]);
                af[mt][2] = __float_as_uint(As[swz(r,   k4+1) + tig]);
                af[mt][3] = __float_as_uint(As[swz(r+8, k4+1) + tig]);
            }
            uint32_t bf[8][2];
            #pragma unroll
            for (int nt = 0; nt < 8; nt++) {
                const int r = col0 + nt*8 + gid;
                bf[nt][0] = __float_as_uint(Ws[swz(r, k4)   + tig]);
                bf[nt][1] = __float_as_uint(Ws[swz(r, k4+1) + tig]);
            }
            #pragma unroll
            for (int mt = 0; mt < 2; mt++)
                #pragma unroll
                for (int nt = 0; nt < 8; nt++) {
                    asm volatile(
                        "mma.sync.aligned.m16n8k8.row.col.f32.tf32.tf32.f32 "
                        "{%0,%1,%2,%3}, {%4,%5,%6,%7}, {%8,%9}, {%0,%1,%2,%3};"
                        : "+f"(acc[mt][nt][0]), "+f"(acc[mt][nt][1]),
                          "+f"(acc[mt][nt][2]), "+f"(acc[mt][nt][3])
                        : "r"(af[mt][0]), "r"(af[mt][1]), "r"(af[mt][2]), "r"(af[mt][3]),
                          "r"(bf[nt][0]), "r"(bf[nt][1]));
                }
        }
    }
    #pragma unroll
    for (int mt = 0; mt < 2; mt++) {
        const int row = bm + row0 + mt*16 + gid;
        #pragma unroll
        for (int nt = 0; nt < 8; nt++) {
            const int col = bn + col0 + nt*8 + tig*2;
            const float b0 = bias[col], b1 = bias[col+1];
            float2 v0 = { acc[mt][nt][0] + b0, acc[mt][nt][1] + b1 };
            float2 v1 = { acc[mt][nt][2] + b0, acc[mt][nt][3] + b1 };
            *(float2*)(Cm + (size_t)row*N + col)     = v0;
            *(float2*)(Cm + (size_t)(row+8)*N + col) = v1;
        }
    }
}

// ---------------- q/k RMSNorm + RoPE + tf32 rounding of q,k,v ----------------
__global__ void k_qkrope(const float* __restrict__ qn_w, const float* __restrict__ kn_w) {
    const int gw   = (blockIdx.x * blockDim.x + threadIdx.x) >> 5;
    const int lane = threadIdx.x & 31;
    const int head = gw & 7;
    const int tok  = gw >> 3;
    const int n = tok & 1023;
    const int rrow = n >> 5, rcol = n & 31;
    float* qp = g_qkv + (size_t)tok * (3*CH) + head * HDIM;
    float* kp = qp + CH;
    float* vp = qp + 2*CH;
    const int j = lane * 2;
    float q0 = qp[j], q1 = qp[j+1], k0 = kp[j], k1 = kp[j+1];
    float sq = q0*q0 + q1*q1, sk = k0*k0 + k1*k1;
    #pragma unroll
    for (int o = 16; o; o >>= 1) {
        sq += __shfl_xor_sync(0xffffffffu, sq, o);
        sk += __shfl_xor_sync(0xffffffffu, sk, o);
    }
    const float rq = rsqrtf(sq / 64.f + EPSV);
    const float rk = rsqrtf(sk / 64.f + EPSV);
    q0 *= rq * qn_w[j];  q1 *= rq * qn_w[j+1];
    k0 *= rk * kn_w[j];  k1 *= rk * kn_w[j+1];
    const int half = (j >= 32);
    const int idx  = (half ? (j - 32) : j) >> 1;
    const float freq = exp2f(-(float)idx * (13.287712379549449f / 16.f));
    const float f = (half ? (float)rcol : (float)rrow) * freq;
    const float cf = cosf(f), sf = sinf(f);
    const float qa = q0*cf - q1*sf, qb = q1*cf + q0*sf;
    const float ka = k0*cf - k1*sf, kb = k1*cf + k0*sf;
    const float qs = 0.125f;
    qp[j] = rtf(qa*qs);  qp[j+1] = rtf(qb*qs);
    kp[j] = rtf(ka);     kp[j+1] = rtf(kb);
    vp[j] = rtf(vp[j]);  vp[j+1] = rtf(vp[j+1]);
}

// ---------------- flash attention, tf32 mma ----------------
// block = (b,h) x 128-query tile; 8 warps x 16 rows; key chunks of 64
#define ASTR 68
__global__ __launch_bounds__(256) void k_attn_mma() {
    extern __shared__ float sm[];
    float* Ks = sm;                  // 64 x ASTR
    float* Vt = sm + 64*ASTR;        // 64 x ASTR (transposed V: [d][key])
    float* Ps = sm + 128*ASTR;       // 128 x ASTR (Q staging, then P)
    const int bh = blockIdx.x;
    const int b = bh >> 3, hh = bh & 7;
    const int q0 = blockIdx.y * 128;
    const int tid = threadIdx.x, lane = tid & 31, warp = tid >> 5;
    const int gid = lane >> 2, tig = lane & 3;
    const float* base = g_qkv + (size_t)b * NTOK * (3*CH);

    // stage Q tile into Ps
    #pragma unroll
    for (int it = 0; it < 8; it++) {
        const int lin = tid + it*256;            // 2048 float4s
        const int r = lin >> 4, c4 = lin & 15;
        float4 v = *(const float4*)(base + (size_t)(q0 + r)*(3*CH) + hh*HDIM + c4*4);
        float* p = Ps + r*ASTR + c4*4;
        p[0]=v.x; p[1]=v.y; p[2]=v.z; p[3]=v.w;
    }
    __syncthreads();
    const int rA = warp*16 + gid;                // warp-local row (0..127)
    uint32_t qf[8][4];
    #pragma unroll
    for (int kk = 0; kk < 8; kk++) {
        const float* p = Ps + rA*ASTR + kk*8 + tig;
        qf[kk][0] = __float_as_uint(p[0]);
        qf[kk][1] = __float_as_uint(p[8*ASTR]);
        qf[kk][2] = __float_as_uint(p[4]);
        qf[kk][3] = __float_as_uint(p[8*ASTR + 4]);
    }
    __syncthreads();

    float m0 = -1e30f, m1 = -1e30f, l0 = 0.f, l1 = 0.f;
    float oacc[8][4];
    #pragma unroll
    for (int nt = 0; nt < 8; nt++)
        #pragma unroll
        for (int c = 0; c < 4; c++) oacc[nt][c] = 0.f;

    for (int kc = 0; kc < NTOK; kc += 64) {
        // load K chunk (row-major) and V chunk (transposed)
        #pragma unroll
        for (int it = 0; it < 4; it++) {
            const int lin = tid + it*256;        // 1024 float4s
            const int r = lin >> 4, c4 = lin & 15;
            const float* kp = base + (size_t)(kc + r)*(3*CH) + CH + hh*HDIM + c4*4;
            float4 kv = *(const float4*)kp;
            float* kd = Ks + r*ASTR + c4*4;
            kd[0]=kv.x; kd[1]=kv.y; kd[2]=kv.z; kd[3]=kv.w;
            float4 vv = *(const float4*)(kp + CH);
            Vt[(c4*4+0)*ASTR + r] = vv.x;
            Vt[(c4*4+1)*ASTR + r] = vv.y;
            Vt[(c4*4+2)*ASTR + r] = vv.z;
            Vt[(c4*4+3)*ASTR + r] = vv.w;
        }
        __syncthreads();

        // S = Q @ K^T
        float sacc[8][4];
        #pragma unroll
        for (int nt = 0; nt < 8; nt++)
            #pragma unroll
            for (int c = 0; c < 4; c++) sacc[nt][c] = 0.f;
        #pragma unroll
        for (int kk = 0; kk < 8; kk++) {
            uint32_t bf[8][2];
            #pragma unroll
            for (int nt = 0; nt < 8; nt++) {
                const float* p = Ks + (nt*8 + gid)*ASTR + kk*8 + tig;
                bf[nt][0] = __float_as_uint(p[0]);
                bf[nt][1] = __float_as_uint(p[4]);
            }
            #pragma unroll
            for (int nt = 0; nt < 8; nt++) {
                asm volatile(
                    "mma.sync.aligned.m16n8k8.row.col.f32.tf32.tf32.f32 "
                    "{%0,%1,%2,%3}, {%4,%5,%6,%7}, {%8,%9}, {%0,%1,%2,%3};"
                    : "+f"(sacc[nt][0]), "+f"(sacc[nt][1]),
                      "+f"(sacc[nt][2]), "+f"(sacc[nt][3])
                    : "r"(qf[kk][0]), "r"(qf[kk][1]), "r"(qf[kk][2]), "r"(qf[kk][3]),
                      "r"(bf[nt][0]), "r"(bf[nt][1]));
            }
        }

        // online softmax (rows gid -> m0/l0, gid+8 -> m1/l1)
        float cm0 = -1e30f, cm1 = -1e30f;
        #pragma unroll
        for (int nt = 0; nt < 8; nt++) {
            cm0 = fmaxf(cm0, fmaxf(sacc[nt][0], sacc[nt][1]));
            cm1 = fmaxf(cm1, fmaxf(sacc[nt][2], sacc[nt][3]));
        }
        #pragma unroll
        for (int o = 1; o <= 2; o <<= 1) {
            cm0 = fmaxf(cm0, __shfl_xor_sync(0xffffffffu, cm0, o));
            cm1 = fmaxf(cm1, __shfl_xor_sync(0xffffffffu, cm1, o));
        }
        const float mn0 = fmaxf(m0, cm0), mn1 = fmaxf(m1, cm1);
        const float cr0 = __expf(m0 - mn0), cr1 = __expf(m1 - mn1);
        l0 *= cr0; l1 *= cr1;
        #pragma unroll
        for (int nt = 0; nt < 8; nt++) {
            oacc[nt][0] *= cr0; oacc[nt][1] *= cr0;
            oacc[nt][2] *= cr1; oacc[nt][3] *= cr1;
        }
        float al0 = 0.f, al1 = 0.f;
        #pragma unroll
        for (int nt = 0; nt < 8; nt++) {
            float p00 = rtf(__expf(sacc[nt][0] - mn0));
            float p01 = rtf(__expf(sacc[nt][1] - mn0));
            float p10 = rtf(__expf(sacc[nt][2] - mn1));
            float p11 = rtf(__expf(sacc[nt][3] - mn1));
            al0 += p00 + p01;  al1 += p10 + p11;
            *(float2*)(Ps + rA*ASTR     + nt*8 + tig*2) = make_float2(p00, p01);
            *(float2*)(Ps + (rA+8)*ASTR + nt*8 + tig*2) = make_float2(p10, p11);
        }
        #pragma unroll
        for (int o = 1; o <= 2; o <<= 1) {
            al0 += __shfl_xor_sync(0xffffffffu, al0, o);
            al1 += __shfl_xor_sync(0xffffffffu, al1, o);
        }
        l0 += al0; l1 += al1;
        m0 = mn0; m1 = mn1;
        __syncwarp();

        // O += P @ V   (contraction over 64 keys)
        #pragma unroll
        for (int kk = 0; kk < 8; kk++) {
            uint32_t af[4];
            {
                const float* p = Ps + rA*ASTR + kk*8 + tig;
                af[0] = __float_as_uint(p[0]);
                af[1] = __float_as_uint(p[8*ASTR]);
                af[2] = __float_as_uint(p[4]);
                af[3] = __float_as_uint(p[8*ASTR + 4]);
            }
            #pragma unroll
            for (int nt = 0; nt < 8; nt++) {
                uint32_t bf0, bf1;
                const float* p = Vt + (nt*8 + gid)*ASTR + kk*8 + tig;
                bf0 = __float_as_uint(p[0]);
                bf1 = __float_as_uint(p[4]);
                asm volatile(
                    "mma.sync.aligned.m16n8k8.row.col.f32.tf32.tf32.f32 "
                    "{%0,%1,%2,%3}, {%4,%5,%6,%7}, {%8,%9}, {%0,%1,%2,%3};"
                    : "+f"(oacc[nt][0]), "+f"(oacc[nt][1]),
                      "+f"(oacc[nt][2]), "+f"(oacc[nt][3])
                    : "r"(af[0]), "r"(af[1]), "r"(af[2]), "r"(af[3]),
                      "r"(bf0), "r"(bf1));
            }
        }
        __syncthreads();
    }

    const float inv0 = 1.f / l0, inv1 = 1.f / l1;
    const size_t row = (size_t)b*NTOK + q0 + rA;
    #pragma unroll
    for (int nt = 0; nt < 8; nt++) {
        const int col = hh*HDIM + nt*8 + tig*2;
        *(float2*)(g_att + row*CH + col) =
            make_float2(rtf(oacc[nt][0]*inv0), rtf(oacc[nt][1]*inv0));
        *(float2*)(g_att + (row+8)*CH + col) =
            make_float2(rtf(oacc[nt][2]*inv1), rtf(oacc[nt][3]*inv1));
    }
}

// ---------------- gated residual ----------------
__global__ void k_resid(const float* __restrict__ src, int gate_ch) {
    const int i = blockIdx.x * blockDim.x + threadIdx.x;
    const int c4 = i & (CH/4 - 1);
    const int row = i >> 7;
    const int b = row >> 10;
    const float* gp = g_ada + b*6*CH + gate_ch*CH + c4*4;
    const size_t off = (size_t)row*CH + c4*4;
    float4 s = *(const float4*)(src + off);
    float4 h = *(const float4*)(g_h + off);
    h.x += gp[0]*s.x; h.y += gp[1]*s.y; h.z += gp[2]*s.z; h.w += gp[3]*s.w;
    *(float4*)(g_h + off) = h;
}

// ---------------- SwiGLU (tf32-rounded output) ----------------
__global__ void k_swiglu() {
    const int i = blockIdx.x * blockDim.x + threadIdx.x;
    const int row = i >> 11;
    const int j   = i & (FFN - 1);
    const float x1 = g_x12[(size_t)row*2*FFN + j];
    const float x2 = g_x12[(size_t)row*2*FFN + FFN + j];
    g_gate[i] = rtf((x1 / (1.f + __expf(-x1))) * x2);
}

// ---------------- final epilogue ----------------
__global__ void k_final(const float* __restrict__ x, float* __restrict__ out) {
    __shared__ float th[32][33], tf[32][33];
    const int b  = blockIdx.y;
    const int n0 = blockIdx.x * 32;
    const int tx = threadIdx.x, ty = threadIdx.y;
    for (int c0 = 0; c0 < CH; c0 += 32) {
        __syncthreads();
        const size_t ridx = ((size_t)b*NTOK + n0 + ty)*CH + c0 + tx;
        th[ty][tx] = g_h[ridx];
        tf[ty][tx] = g_tmp[ridx];
        __syncthreads();
        const int c = c0 + ty;
        const float g = g_ada[b*6*CH + 5*CH + c];
        const size_t oidx = ((size_t)b*CH + c)*NTOK + n0 + tx;
        out[oidx] = x[oidx] + th[tx][ty] + g * tf[tx][ty];
    }
}

// ---------------- launcher ----------------
extern "C" void kernel_launch(void* const* d_in, const int* in_sizes, int n_in,
                              void* d_out, int out_size) {
    const float* x      = (const float*)d_in[0];
    const float* temb   = (const float*)d_in[1];
    const float* gn_w   = (const float*)d_in[2];
    const float* gn_b   = (const float*)d_in[3];
    const float* ada_w  = (const float*)d_in[4];
    const float* ada_b  = (const float*)d_in[5];
    const float* n1_w   = (const float*)d_in[6];
    const float* n2_w   = (const float*)d_in[7];
    const float* qkv_w  = (const float*)d_in[8];
    const float* qkv_b  = (const float*)d_in[9];
    const float* qn_w   = (const float*)d_in[10];
    const float* kn_w   = (const float*)d_in[11];
    const float* proj_w = (const float*)d_in[12];
    const float* proj_b = (const float*)d_in[13];
    const float* w12    = (const float*)d_in[14];
    const float* b12    = (const float*)d_in[15];
    const float* w_out  = (const float*)d_in[16];
    const float* b_out  = (const float*)d_in[17];
    float* out = (float*)d_out;

    float *p_hn, *p_qkv, *p_att, *p_tmp, *p_x12, *p_gate;
    float *p_wqkv, *p_wproj, *p_w12c, *p_woc;
    cudaGetSymbolAddress((void**)&p_hn,    g_hn);
    cudaGetSymbolAddress((void**)&p_qkv,   g_qkv);
    cudaGetSymbolAddress((void**)&p_att,   g_att);
    cudaGetSymbolAddress((void**)&p_tmp,   g_tmp);
    cudaGetSymbolAddress((void**)&p_x12,   g_x12);
    cudaGetSymbolAddress((void**)&p_gate,  g_gate);
    cudaGetSymbolAddress((void**)&p_wqkv,  g_wqkv);
    cudaGetSymbolAddress((void**)&p_wproj, g_wproj);
    cudaGetSymbolAddress((void**)&p_w12c,  g_w12c);
    cudaGetSymbolAddress((void**)&p_woc,   g_woc);

    cudaFuncSetAttribute(k_gemm,     cudaFuncAttributeMaxDynamicSharedMemorySize, 3*8192*4);
    cudaFuncSetAttribute(k_attn_mma, cudaFuncAttributeMaxDynamicSharedMemorySize, 256*ASTR*4);

    // weight tf32 rounding
    k_cvt<<<(3*CH*CH/4 + 255)/256, 256>>>(qkv_w,  p_wqkv,  3*CH*CH);
    k_cvt<<<(CH*CH/4   + 255)/256, 256>>>(proj_w, p_wproj, CH*CH);
    k_cvt<<<(2*FFN*CH/4+ 255)/256, 256>>>(w12,    p_w12c,  2*FFN*CH);
    k_cvt<<<(CH*FFN/4  + 255)/256, 256>>>(w_out,  p_woc,   CH*FFN);

    // adaLN + GroupNorm
    k_ada    <<<dim3(24, BDIM), 128>>>(temb, ada_w, ada_b);
    k_gnstats<<<BDIM*32, 256>>>(x);
    k_gnapply<<<dim3(NTOK/32, BDIM), dim3(32,32)>>>(x, gn_w, gn_b);

    // attention branch
    k_rmsmod <<<NT, 128>>>(n1_w, 0, 1);
    k_gemm   <<<dim3((3*CH)/128, NT/128), 256, 3*8192*4>>>(p_hn, p_wqkv, qkv_b, p_qkv, NT, 3*CH, CH);
    k_qkrope <<<(NT*NHEADS*32)/128, 128>>>(qn_w, kn_w);
    k_attn_mma<<<dim3(BDIM*NHEADS, NTOK/128), 256, 256*ASTR*4>>>();
    k_gemm   <<<dim3(CH/128, NT/128), 256, 3*8192*4>>>(p_att, p_wproj, proj_b, p_tmp, NT, CH, CH);
    k_resid  <<<(NT*CH/4)/256, 256>>>(p_tmp, 2);

    // FFN branch
    k_rmsmod <<<NT, 128>>>(n2_w, 3, 4);
    k_gemm   <<<dim3((2*FFN)/128, NT/128), 256, 3*8192*4>>>(p_hn, p_w12c, b12, p_x12, NT, 2*FFN, CH);
    k_swiglu <<<(NT*FFN)/256, 256>>>();
    k_gemm   <<<dim3(CH/128, NT/128), 256, 3*8192*4>>>(p_gate, p_woc, b_out, p_tmp, NT, CH, FFN);

    // epilogue
    k_final  <<<dim3(NTOK/32, BDIM), dim3(32,32)>>>(x, out);
}

// round 4
// speedup vs baseline: 4.4948x; 1.4204x over previous
#include <cuda_runtime.h>
#include <cuda_bf16.h>
#include <cstdint>

// ---------------- problem constants ----------------
#define BDIM   16
#define CH     512
#define NTOK   1024
#define NT     (BDIM*NTOK)
#define NHEADS 8
#define HDIM   64
#define FFN    2048
#define EPSV   1e-6f

// ---------------- scratch ----------------
__device__ float g_ada [BDIM*6*CH];
__device__ float g_h   [NT*CH];
__device__ float g_qkv [NT*3*CH];           // fp32 QKV gemm output
__device__ float g_stats[BDIM*32*2];
__device__ __nv_bfloat16 g_hnb [NT*CH];     // normalized+modulated, bf16
__device__ __nv_bfloat16 g_qkb [NT*2*CH];   // q,k after rope, bf16 interleaved
__device__ __nv_bfloat16 g_vtb [BDIM*NHEADS*HDIM*NTOK]; // V transposed [b,h,d,tok]
__device__ __nv_bfloat16 g_attb[NT*CH];     // attention out bf16
__device__ __nv_bfloat16 g_x12b[NT*2*FFN];
__device__ __nv_bfloat16 g_gateb[NT*FFN];
// bf16 weights
__device__ __nv_bfloat16 g_wqkv [3*CH*CH];
__device__ __nv_bfloat16 g_wproj[CH*CH];
__device__ __nv_bfloat16 g_w12c [2*FFN*CH];
__device__ __nv_bfloat16 g_woc  [CH*FFN];

// ---------------- helpers ----------------
__device__ __forceinline__ uint32_t pack2bf(float lo, float hi) {
    uint32_t r;
    asm("cvt.rn.bf16x2.f32 %0, %1, %2;" : "=r"(r) : "f"(hi), "f"(lo));
    return r;
}
__device__ __forceinline__ void cpa16(void* s, const void* g) {
    uint32_t sa = (uint32_t)__cvta_generic_to_shared(s);
    asm volatile("cp.async.cg.shared.global [%0], [%1], 16;\n" :: "r"(sa), "l"(g));
}

// ---------------- weight fp32 -> bf16 ----------------
__global__ void k_cvt(const float* __restrict__ s, __nv_bfloat16* __restrict__ d, int n) {
    const int i = (blockIdx.x * blockDim.x + threadIdx.x) * 4;
    if (i >= n) return;
    float4 v = *(const float4*)(s + i);
    uint32_t w0 = pack2bf(v.x, v.y), w1 = pack2bf(v.z, v.w);
    *(uint32_t*)(d + i)     = w0;
    *(uint32_t*)(d + i + 2) = w1;
}

// ---------------- adaLN ----------------
__global__ void k_ada(const float* __restrict__ temb, const float* __restrict__ ada_w,
                      const float* __restrict__ ada_b) {
    __shared__ float s[CH];
    const int b = blockIdx.y;
    for (int i = threadIdx.x; i < CH; i += blockDim.x) {
        float v = temb[b*CH + i];
        s[i] = v / (1.f + __expf(-v));
    }
    __syncthreads();
    const int n = blockIdx.x * blockDim.x + threadIdx.x;
    const float* wr = ada_w + (size_t)n * CH;
    float acc = 0.f;
    #pragma unroll 8
    for (int k = 0; k < CH; k++) acc += wr[k] * s[k];
    g_ada[b*6*CH + n] = acc + ada_b[n];
}

// ---------------- GroupNorm stats ----------------
__global__ void k_gnstats(const float* __restrict__ x) {
    const int bg = blockIdx.x;
    const float* p = x + (size_t)bg * 16 * NTOK;
    float s = 0.f, s2 = 0.f;
    for (int i = threadIdx.x; i < 16*NTOK; i += blockDim.x) {
        float v = p[i]; s += v; s2 += v*v;
    }
    #pragma unroll
    for (int o = 16; o; o >>= 1) {
        s  += __shfl_xor_sync(0xffffffffu, s,  o);
        s2 += __shfl_xor_sync(0xffffffffu, s2, o);
    }
    __shared__ float sh[64];
    const int w = threadIdx.x >> 5, l = threadIdx.x & 31;
    if (l == 0) { sh[w] = s; sh[32 + w] = s2; }
    __syncthreads();
    if (threadIdx.x < 32) {
        const int nw = blockDim.x >> 5;
        s  = (threadIdx.x < nw) ? sh[threadIdx.x]      : 0.f;
        s2 = (threadIdx.x < nw) ? sh[32 + threadIdx.x] : 0.f;
        #pragma unroll
        for (int o = 16; o; o >>= 1) {
            s  += __shfl_xor_sync(0xffffffffu, s,  o);
            s2 += __shfl_xor_sync(0xffffffffu, s2, o);
        }
        if (threadIdx.x == 0) {
            const float inv = 1.f / (16.f * NTOK);
            float mu  = s * inv;
            float var = s2 * inv - mu * mu;
            g_stats[bg*2]     = mu;
            g_stats[bg*2 + 1] = rsqrtf(var + EPSV);
        }
    }
}

// ---------------- GroupNorm apply + transpose ----------------
__global__ void k_gnapply(const float* __restrict__ x, const float* __restrict__ gw,
                          const float* __restrict__ gb) {
    __shared__ float tile[32][33];
    const int b  = blockIdx.y;
    const int n0 = blockIdx.x * 32;
    const int tx = threadIdx.x, ty = threadIdx.y;
    for (int c0 = 0; c0 < CH; c0 += 32) {
        __syncthreads();
        tile[ty][tx] = x[((size_t)b*CH + c0 + ty)*NTOK + n0 + tx];
        __syncthreads();
        const int c  = c0 + tx;
        const float mu = g_stats[(b*32 + (c >> 4))*2];
        const float rs = g_stats[(b*32 + (c >> 4))*2 + 1];
        g_h[((size_t)b*NTOK + n0 + ty)*CH + c] = (tile[tx][ty] - mu) * rs * gw[c] + gb[c];
    }
}

// ---------------- RMSNorm + modulation -> bf16 ----------------
__global__ void k_rmsmod(const float* __restrict__ w, int shift_ch, int scale_ch) {
    const int row = blockIdx.x;
    const int b = row >> 10;
    const float* hp = g_h + (size_t)row * CH;
    const int t = threadIdx.x;
    float4 v = *(const float4*)(hp + t*4);
    float ss = v.x*v.x + v.y*v.y + v.z*v.z + v.w*v.w;
    #pragma unroll
    for (int o = 16; o; o >>= 1) ss += __shfl_xor_sync(0xffffffffu, ss, o);
    __shared__ float sh[4];
    if ((t & 31) == 0) sh[t >> 5] = ss;
    __syncthreads();
    ss = sh[0] + sh[1] + sh[2] + sh[3];
    const float r = rsqrtf(ss / (float)CH + EPSV);
    const float* shf = g_ada + b*6*CH + shift_ch*CH;
    const float* scl = g_ada + b*6*CH + scale_ch*CH;
    const int c = t*4;
    float o0 = v.x * r * w[c+0] * (1.f + scl[c+0]) + shf[c+0];
    float o1 = v.y * r * w[c+1] * (1.f + scl[c+1]) + shf[c+1];
    float o2 = v.z * r * w[c+2] * (1.f + scl[c+2]) + shf[c+2];
    float o3 = v.w * r * w[c+3] * (1.f + scl[c+3]) + shf[c+3];
    uint32_t* dp = (uint32_t*)(g_hnb + (size_t)row*CH + c);
    dp[0] = pack2bf(o0, o1);
    dp[1] = pack2bf(o2, o3);
}

// ---------------- BF16 GEMM: C[M,N] = A[M,K] @ W[N,K]^T + bias ----------------
// 128x128x32 tiles, 8 warps, warp tile 32x64, mma.m16n8k16.bf16, 3-stage cp.async.
// mode 0: fp32 store to Cf; mode 1: bf16 store to Cb; mode 2: g_h += gate*(acc+bias)
#define WSTR 20   // words per 16-word smem row (bank-perfect: (20r+w)%32 all distinct)
__global__ __launch_bounds__(256) void k_gemm(
    const __nv_bfloat16* __restrict__ A, const __nv_bfloat16* __restrict__ W,
    const float* __restrict__ bias, float* __restrict__ Cf, uint32_t* __restrict__ Cb,
    const float* __restrict__ ada, int gch, int mode, int M, int N, int K)
{
    extern __shared__ uint32_t sm[];     // 3 stages * 5120 words
    const int tid  = threadIdx.x;
    const int lane = tid & 31;
    const int warp = tid >> 5;
    const int gid  = lane >> 2;
    const int tig  = lane & 3;
    const int row0 = (warp & 3) * 32;
    const int col0 = (warp >> 2) * 64;
    const int bm = blockIdx.y * 128, bn = blockIdx.x * 128;
    const int KT = K >> 5;

    auto load_body = [&](int kt, int s) {
        uint32_t* As = sm + s * 5120;
        uint32_t* Ws = As + 2560;
        const int k0 = kt << 5;
        #pragma unroll
        for (int i = 0; i < 2; i++) {
            const int lin = tid + i*256;
            const int r = lin >> 2, c4 = lin & 3;
            cpa16(As + r*WSTR + c4*4, A + (size_t)(bm + r)*K + k0 + c4*8);
            cpa16(Ws + r*WSTR + c4*4, W + (size_t)(bn + r)*K + k0 + c4*8);
        }
    };

    load_body(0, 0);
    asm volatile("cp.async.commit_group;\n");
    load_body(1, 1);
    asm volatile("cp.async.commit_group;\n");

    float acc[2][8][4];
    #pragma unroll
    for (int i = 0; i < 2; i++)
        #pragma unroll
        for (int j = 0; j < 8; j++)
            #pragma unroll
            for (int c = 0; c < 4; c++) acc[i][j][c] = 0.f;

    for (int kt = 0; kt < KT; kt++) {
        asm volatile("cp.async.wait_group 1;\n");
        __syncthreads();
        if (kt + 2 < KT) load_body(kt + 2, (kt + 2) % 3);
        asm volatile("cp.async.commit_group;\n");

        const uint32_t* As = sm + (kt % 3) * 5120;
        const uint32_t* Ws = As + 2560;
        #pragma unroll
        for (int kk = 0; kk < 2; kk++) {
            const int w0 = kk * 8;
            uint32_t af[2][4];
            #pragma unroll
            for (int mt = 0; mt < 2; mt++) {
                const int r = row0 + mt*16 + gid;
                af[mt][0] = As[r*WSTR     + w0 + tig];
                af[mt][1] = As[(r+8)*WSTR + w0 + tig];
                af[mt][2] = As[r*WSTR     + w0 + 4 + tig];
                af[mt][3] = As[(r+8)*WSTR + w0 + 4 + tig];
            }
            uint32_t bf[8][2];
            #pragma unroll
            for (int nt = 0; nt < 8; nt++) {
                const int r = col0 + nt*8 + gid;
                bf[nt][0] = Ws[r*WSTR + w0 + tig];
                bf[nt][1] = Ws[r*WSTR + w0 + 4 + tig];
            }
            #pragma unroll
            for (int mt = 0; mt < 2; mt++)
                #pragma unroll
                for (int nt = 0; nt < 8; nt++) {
                    asm volatile(
                        "mma.sync.aligned.m16n8k16.row.col.f32.bf16.bf16.f32 "
                        "{%0,%1,%2,%3}, {%4,%5,%6,%7}, {%8,%9}, {%0,%1,%2,%3};"
                        : "+f"(acc[mt][nt][0]), "+f"(acc[mt][nt][1]),
                          "+f"(acc[mt][nt][2]), "+f"(acc[mt][nt][3])
                        : "r"(af[mt][0]), "r"(af[mt][1]), "r"(af[mt][2]), "r"(af[mt][3]),
                          "r"(bf[nt][0]), "r"(bf[nt][1]));
                }
        }
    }

    #pragma unroll
    for (int mt = 0; mt < 2; mt++) {
        const int row = bm + row0 + mt*16 + gid;
        const int b   = row >> 10;
        const float* gp = ada + b*6*CH + gch*CH;
        #pragma unroll
        for (int nt = 0; nt < 8; nt++) {
            const int col = bn + col0 + nt*8 + tig*2;
            const float b0 = bias[col], b1 = bias[col+1];
            float v00 = acc[mt][nt][0] + b0, v01 = acc[mt][nt][1] + b1;
            float v10 = acc[mt][nt][2] + b0, v11 = acc[mt][nt][3] + b1;
            if (mode == 0) {
                *(float2*)(Cf + (size_t)row*N + col)     = make_float2(v00, v01);
                *(float2*)(Cf + (size_t)(row+8)*N + col) = make_float2(v10, v11);
            } else if (mode == 1) {
                Cb[((size_t)row*N + col) >> 1]     = pack2bf(v00, v01);
                Cb[((size_t)(row+8)*N + col) >> 1] = pack2bf(v10, v11);
            } else {
                const float gg0 = gp[col], gg1 = gp[col+1];
                float2 h0 = *(float2*)(Cf + (size_t)row*N + col);
                float2 h1 = *(float2*)(Cf + (size_t)(row+8)*N + col);
                h0.x += gg0*v00; h0.y += gg1*v01;
                h1.x += gg0*v10; h1.y += gg1*v11;
                *(float2*)(Cf + (size_t)row*N + col)     = h0;
                *(float2*)(Cf + (size_t)(row+8)*N + col) = h1;
            }
        }
    }
}

// ---------------- q/k RMSNorm + RoPE -> bf16; V -> transposed bf16 ----------------
__global__ void k_qkrope(const float* __restrict__ qn_w, const float* __restrict__ kn_w) {
    const int gw   = (blockIdx.x * blockDim.x + threadIdx.x) >> 5;
    const int lane = threadIdx.x & 31;
    const int head = gw & 7;
    const int tok  = gw >> 3;
    const int b = tok >> 10;
    const int n = tok & 1023;
    const int rrow = n >> 5, rcol = n & 31;
    const float* qp = g_qkv + (size_t)tok * (3*CH) + head * HDIM;
    const float* kp = qp + CH;
    const float* vp = qp + 2*CH;
    const int j = lane * 2;
    float q0 = qp[j], q1 = qp[j+1], k0 = kp[j], k1 = kp[j+1];
    float sq = q0*q0 + q1*q1, sk = k0*k0 + k1*k1;
    #pragma unroll
    for (int o = 16; o; o >>= 1) {
        sq += __shfl_xor_sync(0xffffffffu, sq, o);
        sk += __shfl_xor_sync(0xffffffffu, sk, o);
    }
    const float rq = rsqrtf(sq / 64.f + EPSV);
    const float rk = rsqrtf(sk / 64.f + EPSV);
    q0 *= rq * qn_w[j];  q1 *= rq * qn_w[j+1];
    k0 *= rk * kn_w[j];  k1 *= rk * kn_w[j+1];
    const int half = (j >= 32);
    const int idx  = (half ? (j - 32) : j) >> 1;
    const float freq = exp2f(-(float)idx * (13.287712379549449f / 16.f));
    const float f = (half ? (float)rcol : (float)rrow) * freq;
    const float cf = cosf(f), sf = sinf(f);
    const float qa = q0*cf - q1*sf, qb = q1*cf + q0*sf;
    const float ka = k0*cf - k1*sf, kb = k1*cf + k0*sf;
    const float qs = 0.125f;
    uint32_t* qkw = (uint32_t*)g_qkb;
    qkw[(size_t)tok*512 + head*32 + lane]       = pack2bf(qa*qs, qb*qs);
    qkw[(size_t)tok*512 + 256 + head*32 + lane] = pack2bf(ka, kb);
    const int bh = b*8 + head;
    g_vtb[((size_t)bh*64 + j)  *NTOK + n] = __float2bfloat16(vp[j]);
    g_vtb[((size_t)bh*64 + j+1)*NTOK + n] = __float2bfloat16(vp[j+1]);
}

// ---------------- flash attention, bf16 mma ----------------
// block = (b,h) x 128-query tile; 8 warps x 16 rows; key chunks of 64
#define QSTR 36  // words per 32-word row; banks (36r+w)%32=(4r+w)%32 all distinct
__global__ __launch_bounds__(256) void k_attn_mma() {
    extern __shared__ uint32_t smw[];
    uint32_t* Ks = smw;                  // 64 rows x QSTR
    uint32_t* Vt = smw + 64*QSTR;        // 64 rows x QSTR
    uint32_t* Ps = smw + 128*QSTR;       // 128 rows x QSTR (Q then P)
    const int bh = blockIdx.x;
    const int b = bh >> 3, hh = bh & 7;
    const int q0 = blockIdx.y * 128;
    const int tid = threadIdx.x, lane = tid & 31, warp = tid >> 5;
    const int gid = lane >> 2, tig = lane & 3;
    const __nv_bfloat16* qk = g_qkb + (size_t)b * NTOK * 1024;
    const __nv_bfloat16* vt = g_vtb + (size_t)bh * 64 * NTOK;

    // stage Q tile
    #pragma unroll
    for (int i = 0; i < 4; i++) {
        const int lin = tid + i*256;         // 1024 chunks
        const int r = lin >> 3, c4 = lin & 7;
        cpa16(Ps + r*QSTR + c4*4, qk + (size_t)(q0 + r)*1024 + hh*64 + c4*8);
    }
    asm volatile("cp.async.commit_group;\n");
    asm volatile("cp.async.wait_group 0;\n");
    __syncthreads();
    const int rA = warp*16 + gid;
    uint32_t qf[4][4];
    #pragma unroll
    for (int kk = 0; kk < 4; kk++) {
        const int w0 = kk*8;
        qf[kk][0] = Ps[rA*QSTR     + w0 + tig];
        qf[kk][1] = Ps[(rA+8)*QSTR + w0 + tig];
        qf[kk][2] = Ps[rA*QSTR     + w0 + 4 + tig];
        qf[kk][3] = Ps[(rA+8)*QSTR + w0 + 4 + tig];
    }
    __syncthreads();

    float m0 = -1e30f, m1 = -1e30f, l0 = 0.f, l1 = 0.f;
    float oacc[8][4];
    #pragma unroll
    for (int nt = 0; nt < 8; nt++)
        #pragma unroll
        for (int c = 0; c < 4; c++) oacc[nt][c] = 0.f;

    for (int kc = 0; kc < NTOK; kc += 64) {
        // K rows (64 x 64 halves) and V^T rows (64 x 64 halves, contiguous in gmem)
        #pragma unroll
        for (int i = 0; i < 2; i++) {
            const int lin = tid + i*256;     // 512 chunks
            const int r = lin >> 3, c4 = lin & 7;
            cpa16(Ks + r*QSTR + c4*4, qk + (size_t)(kc + r)*1024 + 512 + hh*64 + c4*8);
            cpa16(Vt + r*QSTR + c4*4, vt + (size_t)r*NTOK + kc + c4*8);
        }
        asm volatile("cp.async.commit_group;\n");
        asm volatile("cp.async.wait_group 0;\n");
        __syncthreads();

        // S = Q @ K^T
        float sacc[8][4];
        #pragma unroll
        for (int nt = 0; nt < 8; nt++)
            #pragma unroll
            for (int c = 0; c < 4; c++) sacc[nt][c] = 0.f;
        #pragma unroll
        for (int kk = 0; kk < 4; kk++) {
            const int w0 = kk*8;
            uint32_t bf[8][2];
            #pragma unroll
            for (int nt = 0; nt < 8; nt++) {
                const int r = nt*8 + gid;
                bf[nt][0] = Ks[r*QSTR + w0 + tig];
                bf[nt][1] = Ks[r*QSTR + w0 + 4 + tig];
            }
            #pragma unroll
            for (int nt = 0; nt < 8; nt++) {
                asm volatile(
                    "mma.sync.aligned.m16n8k16.row.col.f32.bf16.bf16.f32 "
                    "{%0,%1,%2,%3}, {%4,%5,%6,%7}, {%8,%9}, {%0,%1,%2,%3};"
                    : "+f"(sacc[nt][0]), "+f"(sacc[nt][1]),
                      "+f"(sacc[nt][2]), "+f"(sacc[nt][3])
                    : "r"(qf[kk][0]), "r"(qf[kk][1]), "r"(qf[kk][2]), "r"(qf[kk][3]),
                      "r"(bf[nt][0]), "r"(bf[nt][1]));
            }
        }

        // online softmax
        float cm0 = -1e30f, cm1 = -1e30f;
        #pragma unroll
        for (int nt = 0; nt < 8; nt++) {
            cm0 = fmaxf(cm0, fmaxf(sacc[nt][0], sacc[nt][1]));
            cm1 = fmaxf(cm1, fmaxf(sacc[nt][2], sacc[nt][3]));
        }
        #pragma unroll
        for (int o = 1; o <= 2; o <<= 1) {
            cm0 = fmaxf(cm0, __shfl_xor_sync(0xffffffffu, cm0, o));
            cm1 = fmaxf(cm1, __shfl_xor_sync(0xffffffffu, cm1, o));
        }
        const float mn0 = fmaxf(m0, cm0), mn1 = fmaxf(m1, cm1);
        const float cr0 = __expf(m0 - mn0), cr1 = __expf(m1 - mn1);
        l0 *= cr0; l1 *= cr1;
        #pragma unroll
        for (int nt = 0; nt < 8; nt++) {
            oacc[nt][0] *= cr0; oacc[nt][1] *= cr0;
            oacc[nt][2] *= cr1; oacc[nt][3] *= cr1;
        }
        float al0 = 0.f, al1 = 0.f;
        #pragma unroll
        for (int nt = 0; nt < 8; nt++) {
            float p00 = __expf(sacc[nt][0] - mn0);
            float p01 = __expf(sacc[nt][1] - mn0);
            float p10 = __expf(sacc[nt][2] - mn1);
            float p11 = __expf(sacc[nt][3] - mn1);
            al0 += p00 + p01;  al1 += p10 + p11;
            Ps[rA*QSTR     + nt*4 + tig] = pack2bf(p00, p01);
            Ps[(rA+8)*QSTR + nt*4 + tig] = pack2bf(p10, p11);
        }
        #pragma unroll
        for (int o = 1; o <= 2; o <<= 1) {
            al0 += __shfl_xor_sync(0xffffffffu, al0, o);
            al1 += __shfl_xor_sync(0xffffffffu, al1, o);
        }
        l0 += al0; l1 += al1;
        m0 = mn0; m1 = mn1;
        __syncwarp();

        // O += P @ V  (k = 64 keys, 4 ksteps)
        #pragma unroll
        for (int kk = 0; kk < 4; kk++) {
            const int w0 = kk*8;
            uint32_t af[4];
            af[0] = Ps[rA*QSTR     + w0 + tig];
            af[1] = Ps[(rA+8)*QSTR + w0 + tig];
            af[2] = Ps[rA*QSTR     + w0 + 4 + tig];
            af[3] = Ps[(rA+8)*QSTR + w0 + 4 + tig];
            #pragma unroll
            for (int nt = 0; nt < 8; nt++) {
                const int r = nt*8 + gid;
                uint32_t bf0 = Vt[r*QSTR + w0 + tig];
                uint32_t bf1 = Vt[r*QSTR + w0 + 4 + tig];
                asm volatile(
                    "mma.sync.aligned.m16n8k16.row.col.f32.bf16.bf16.f32 "
                    "{%0,%1,%2,%3}, {%4,%5,%6,%7}, {%8,%9}, {%0,%1,%2,%3};"
                    : "+f"(oacc[nt][0]), "+f"(oacc[nt][1]),
                      "+f"(oacc[nt][2]), "+f"(oacc[nt][3])
                    : "r"(af[0]), "r"(af[1]), "r"(af[2]), "r"(af[3]),
                      "r"(bf0), "r"(bf1));
            }
        }
        __syncthreads();
    }

    const float inv0 = 1.f / l0, inv1 = 1.f / l1;
    uint32_t* ow = (uint32_t*)g_attb;
    const size_t row = (size_t)b*NTOK + q0 + rA;
    #pragma unroll
    for (int nt = 0; nt < 8; nt++) {
        const int cw = hh*32 + nt*4 + tig;           // word index within row
        ow[row*256 + cw]     = pack2bf(oacc[nt][0]*inv0, oacc[nt][1]*inv0);
        ow[(row+8)*256 + cw] = pack2bf(oacc[nt][2]*inv1, oacc[nt][3]*inv1);
    }
}

// ---------------- SwiGLU: silu(x1)*x2, bf16 in/out ----------------
__global__ void k_swiglu() {
    const int i = blockIdx.x * blockDim.x + threadIdx.x;   // over NT*FFN/2 words
    const int row = i >> 10;                               // /(FFN/2)
    const int jw  = i & (FFN/2 - 1);
    const uint32_t* xw = (const uint32_t*)g_x12b;
    float2 x1 = __bfloat1622float2(*(__nv_bfloat162*)&xw[(size_t)row*(2*FFN/2) + jw]);
    float2 x2 = __bfloat1622float2(*(__nv_bfloat162*)&xw[(size_t)row*(2*FFN/2) + FFN/2 + jw]);
    float r0 = (x1.x / (1.f + __expf(-x1.x))) * x2.x;
    float r1 = (x1.y / (1.f + __expf(-x1.y))) * x2.y;
    ((uint32_t*)g_gateb)[(size_t)row*(FFN/2) + jw] = pack2bf(r0, r1);
}

// ---------------- final: out[b,c,n] = x + h^T ----------------
__global__ void k_final(const float* __restrict__ x, float* __restrict__ out) {
    __shared__ float th[32][33];
    const int b  = blockIdx.y;
    const int n0 = blockIdx.x * 32;
    const int tx = threadIdx.x, ty = threadIdx.y;
    for (int c0 = 0; c0 < CH; c0 += 32) {
        __syncthreads();
        th[ty][tx] = g_h[((size_t)b*NTOK + n0 + ty)*CH + c0 + tx];
        __syncthreads();
        const size_t oidx = ((size_t)b*CH + c0 + ty)*NTOK + n0 + tx;
        out[oidx] = x[oidx] + th[tx][ty];
    }
}

// ---------------- launcher ----------------
extern "C" void kernel_launch(void* const* d_in, const int* in_sizes, int n_in,
                              void* d_out, int out_size) {
    const float* x      = (const float*)d_in[0];
    const float* temb   = (const float*)d_in[1];
    const float* gn_w   = (const float*)d_in[2];
    const float* gn_b   = (const float*)d_in[3];
    const float* ada_w  = (const float*)d_in[4];
    const float* ada_b  = (const float*)d_in[5];
    const float* n1_w   = (const float*)d_in[6];
    const float* n2_w   = (const float*)d_in[7];
    const float* qkv_w  = (const float*)d_in[8];
    const float* qkv_b  = (const float*)d_in[9];
    const float* qn_w   = (const float*)d_in[10];
    const float* kn_w   = (const float*)d_in[11];
    const float* proj_w = (const float*)d_in[12];
    const float* proj_b = (const float*)d_in[13];
    const float* w12    = (const float*)d_in[14];
    const float* b12    = (const float*)d_in[15];
    const float* w_out  = (const float*)d_in[16];
    const float* b_out  = (const float*)d_in[17];
    float* out = (float*)d_out;

    float *p_h, *p_qkv, *p_ada;
    __nv_bfloat16 *p_hnb, *p_attb, *p_x12b, *p_gateb;
    __nv_bfloat16 *p_wqkv, *p_wproj, *p_w12c, *p_woc;
    cudaGetSymbolAddress((void**)&p_h,     g_h);
    cudaGetSymbolAddress((void**)&p_qkv,   g_qkv);
    cudaGetSymbolAddress((void**)&p_ada,   g_ada);
    cudaGetSymbolAddress((void**)&p_hnb,   g_hnb);
    cudaGetSymbolAddress((void**)&p_attb,  g_attb);
    cudaGetSymbolAddress((void**)&p_x12b,  g_x12b);
    cudaGetSymbolAddress((void**)&p_gateb, g_gateb);
    cudaGetSymbolAddress((void**)&p_wqkv,  g_wqkv);
    cudaGetSymbolAddress((void**)&p_wproj, g_wproj);
    cudaGetSymbolAddress((void**)&p_w12c,  g_w12c);
    cudaGetSymbolAddress((void**)&p_woc,   g_woc);

    const int gemm_smem = 3*5120*4;          // 61440 B
    const int attn_smem = 256*QSTR*4;        // 36864 B
    cudaFuncSetAttribute(k_gemm,     cudaFuncAttributeMaxDynamicSharedMemorySize, gemm_smem);
    cudaFuncSetAttribute(k_attn_mma, cudaFuncAttributeMaxDynamicSharedMemorySize, attn_smem);

    // weight conversion
    k_cvt<<<(3*CH*CH/4 + 255)/256, 256>>>(qkv_w,  p_wqkv,  3*CH*CH);
    k_cvt<<<(CH*CH/4   + 255)/256, 256>>>(proj_w, p_wproj, CH*CH);
    k_cvt<<<(2*FFN*CH/4+ 255)/256, 256>>>(w12,    p_w12c,  2*FFN*CH);
    k_cvt<<<(CH*FFN/4  + 255)/256, 256>>>(w_out,  p_woc,   CH*FFN);

    // adaLN + GroupNorm
    k_ada    <<<dim3(24, BDIM), 128>>>(temb, ada_w, ada_b);
    k_gnstats<<<BDIM*32, 256>>>(x);
    k_gnapply<<<dim3(NTOK/32, BDIM), dim3(32,32)>>>(x, gn_w, gn_b);

    // attention branch
    k_rmsmod <<<NT, 128>>>(n1_w, 0, 1);
    k_gemm   <<<dim3((3*CH)/128, NT/128), 256, gemm_smem>>>(
        p_hnb, p_wqkv, qkv_b, p_qkv, nullptr, p_ada, 0, 0, NT, 3*CH, CH);
    k_qkrope <<<(NT*NHEADS*32)/128, 128>>>(qn_w, kn_w);
    k_attn_mma<<<dim3(BDIM*NHEADS, NTOK/128), 256, attn_smem>>>();
    k_gemm   <<<dim3(CH/128, NT/128), 256, gemm_smem>>>(
        p_attb, p_wproj, proj_b, p_h, nullptr, p_ada, 2, 2, NT, CH, CH);

    // FFN branch
    k_rmsmod <<<NT, 128>>>(n2_w, 3, 4);
    k_gemm   <<<dim3((2*FFN)/128, NT/128), 256, gemm_smem>>>(
        p_hnb, p_w12c, b12, nullptr, (uint32_t*)p_x12b, p_ada, 0, 1, NT, 2*FFN, CH);
    k_swiglu <<<(NT*FFN/2)/256, 256>>>();
    k_gemm   <<<dim3(CH/128, NT/128), 256, gemm_smem>>>(
        p_gateb, p_woc, b_out, p_h, nullptr, p_ada, 5, 2, NT, CH, FFN);

    // epilogue
    k_final  <<<dim3(NTOK/32, BDIM), dim3(32,32)>>>(x, out);
}

// round 5
// speedup vs baseline: 5.3235x; 1.1844x over previous
#include <cuda_runtime.h>
#include <cuda_bf16.h>
#include <cstdint>

// ---------------- problem constants ----------------
#define BDIM   16
#define CH     512
#define NTOK   1024
#define NT     (BDIM*NTOK)
#define NHEADS 8
#define HDIM   64
#define FFN    2048
#define EPSV   1e-6f

// ---------------- scratch ----------------
__device__ float g_ada [BDIM*6*CH];
__device__ float g_h   [NT*CH];
__device__ float g_qkv [NT*3*CH];
__device__ float g_stats[BDIM*32*2];
__device__ float g_b12p[2*FFN];
__device__ __nv_bfloat16 g_hnb [NT*CH];
__device__ __nv_bfloat16 g_qkb [NT*2*CH];
__device__ __nv_bfloat16 g_vtb [BDIM*NHEADS*HDIM*NTOK];
__device__ __nv_bfloat16 g_attb[NT*CH];
__device__ __nv_bfloat16 g_gateb[NT*FFN];
__device__ __nv_bfloat16 g_wqkv [3*CH*CH];
__device__ __nv_bfloat16 g_wproj[CH*CH];
__device__ __nv_bfloat16 g_w12c [2*FFN*CH];   // row-permuted: 2j<-w1_j, 2j+1<-w2_j
__device__ __nv_bfloat16 g_woc  [CH*FFN];

// ---------------- helpers ----------------
__device__ __forceinline__ uint32_t pack2bf(float lo, float hi) {
    uint32_t r;
    asm("cvt.rn.bf16x2.f32 %0, %1, %2;" : "=r"(r) : "f"(hi), "f"(lo));
    return r;
}
__device__ __forceinline__ void cpa16(void* s, const void* g) {
    uint32_t sa = (uint32_t)__cvta_generic_to_shared(s);
    asm volatile("cp.async.cg.shared.global [%0], [%1], 16;\n" :: "r"(sa), "l"(g));
}
__device__ __forceinline__ void ldm4(uint32_t addr, uint32_t& r0, uint32_t& r1,
                                     uint32_t& r2, uint32_t& r3) {
    asm volatile("ldmatrix.sync.aligned.m8n8.x4.shared.b16 {%0,%1,%2,%3}, [%4];"
                 : "=r"(r0), "=r"(r1), "=r"(r2), "=r"(r3) : "r"(addr));
}
#define MMA_BF16(d, a, b) \
    asm volatile("mma.sync.aligned.m16n8k16.row.col.f32.bf16.bf16.f32 " \
                 "{%0,%1,%2,%3}, {%4,%5,%6,%7}, {%8,%9}, {%0,%1,%2,%3};" \
                 : "+f"(d[0]), "+f"(d[1]), "+f"(d[2]), "+f"(d[3]) \
                 : "r"(a[0]), "r"(a[1]), "r"(a[2]), "r"(a[3]), "r"(b[0]), "r"(b[1]))

// ---------------- weight conversions ----------------
__global__ void k_cvt(const float* __restrict__ s, __nv_bfloat16* __restrict__ d, int n) {
    const int i = (blockIdx.x * blockDim.x + threadIdx.x) * 4;
    if (i >= n) return;
    float4 v = *(const float4*)(s + i);
    *(uint32_t*)(d + i)     = pack2bf(v.x, v.y);
    *(uint32_t*)(d + i + 2) = pack2bf(v.z, v.w);
}
// w12 row-permuting conversion
__global__ void k_cvtw12(const float* __restrict__ s, __nv_bfloat16* __restrict__ d) {
    const int i = (blockIdx.x * blockDim.x + threadIdx.x) * 4;   // over 2*FFN*CH
    const int r = i >> 9;
    const int k = i & (CH - 1);
    const int sr = (r & 1) ? (FFN + (r >> 1)) : (r >> 1);
    float4 v = *(const float4*)(s + (size_t)sr*CH + k);
    *(uint32_t*)(d + i)     = pack2bf(v.x, v.y);
    *(uint32_t*)(d + i + 2) = pack2bf(v.z, v.w);
}
__global__ void k_permb(const float* __restrict__ b12) {
    const int j = blockIdx.x * blockDim.x + threadIdx.x;   // 0..FFN-1
    g_b12p[2*j]   = b12[j];
    g_b12p[2*j+1] = b12[FFN + j];
}

// ---------------- adaLN ----------------
__global__ void k_ada(const float* __restrict__ temb, const float* __restrict__ ada_w,
                      const float* __restrict__ ada_b) {
    __shared__ float s[CH];
    const int b = blockIdx.y;
    for (int i = threadIdx.x; i < CH; i += blockDim.x) {
        float v = temb[b*CH + i];
        s[i] = v / (1.f + __expf(-v));
    }
    __syncthreads();
    const int n = blockIdx.x * blockDim.x + threadIdx.x;
    const float* wr = ada_w + (size_t)n * CH;
    float acc = 0.f;
    #pragma unroll 8
    for (int k = 0; k < CH; k++) acc += wr[k] * s[k];
    g_ada[b*6*CH + n] = acc + ada_b[n];
}

// ---------------- GroupNorm stats ----------------
__global__ void k_gnstats(const float* __restrict__ x) {
    const int bg = blockIdx.x;
    const float* p = x + (size_t)bg * 16 * NTOK;
    float s = 0.f, s2 = 0.f;
    for (int i = threadIdx.x; i < 16*NTOK; i += blockDim.x) {
        float v = p[i]; s += v; s2 += v*v;
    }
    #pragma unroll
    for (int o = 16; o; o >>= 1) {
        s  += __shfl_xor_sync(0xffffffffu, s,  o);
        s2 += __shfl_xor_sync(0xffffffffu, s2, o);
    }
    __shared__ float sh[64];
    const int w = threadIdx.x >> 5, l = threadIdx.x & 31;
    if (l == 0) { sh[w] = s; sh[32 + w] = s2; }
    __syncthreads();
    if (threadIdx.x < 32) {
        const int nw = blockDim.x >> 5;
        s  = (threadIdx.x < nw) ? sh[threadIdx.x]      : 0.f;
        s2 = (threadIdx.x < nw) ? sh[32 + threadIdx.x] : 0.f;
        #pragma unroll
        for (int o = 16; o; o >>= 1) {
            s  += __shfl_xor_sync(0xffffffffu, s,  o);
            s2 += __shfl_xor_sync(0xffffffffu, s2, o);
        }
        if (threadIdx.x == 0) {
            const float inv = 1.f / (16.f * NTOK);
            float mu  = s * inv;
            float var = s2 * inv - mu * mu;
            g_stats[bg*2]     = mu;
            g_stats[bg*2 + 1] = rsqrtf(var + EPSV);
        }
    }
}

// ---------------- GroupNorm apply + transpose ----------------
__global__ void k_gnapply(const float* __restrict__ x, const float* __restrict__ gw,
                          const float* __restrict__ gb) {
    __shared__ float tile[32][33];
    const int b  = blockIdx.y;
    const int n0 = blockIdx.x * 32;
    const int tx = threadIdx.x, ty = threadIdx.y;
    for (int c0 = 0; c0 < CH; c0 += 32) {
        __syncthreads();
        tile[ty][tx] = x[((size_t)b*CH + c0 + ty)*NTOK + n0 + tx];
        __syncthreads();
        const int c  = c0 + tx;
        const float mu = g_stats[(b*32 + (c >> 4))*2];
        const float rs = g_stats[(b*32 + (c >> 4))*2 + 1];
        g_h[((size_t)b*NTOK + n0 + ty)*CH + c] = (tile[tx][ty] - mu) * rs * gw[c] + gb[c];
    }
}

// ---------------- RMSNorm + modulation -> bf16 ----------------
__global__ void k_rmsmod(const float* __restrict__ w, int shift_ch, int scale_ch) {
    const int row = blockIdx.x;
    const int b = row >> 10;
    const float* hp = g_h + (size_t)row * CH;
    const int t = threadIdx.x;
    float4 v = *(const float4*)(hp + t*4);
    float ss = v.x*v.x + v.y*v.y + v.z*v.z + v.w*v.w;
    #pragma unroll
    for (int o = 16; o; o >>= 1) ss += __shfl_xor_sync(0xffffffffu, ss, o);
    __shared__ float sh[4];
    if ((t & 31) == 0) sh[t >> 5] = ss;
    __syncthreads();
    ss = sh[0] + sh[1] + sh[2] + sh[3];
    const float r = rsqrtf(ss / (float)CH + EPSV);
    const float* shf = g_ada + b*6*CH + shift_ch*CH;
    const float* scl = g_ada + b*6*CH + scale_ch*CH;
    const int c = t*4;
    float o0 = v.x * r * w[c+0] * (1.f + scl[c+0]) + shf[c+0];
    float o1 = v.y * r * w[c+1] * (1.f + scl[c+1]) + shf[c+1];
    float o2 = v.z * r * w[c+2] * (1.f + scl[c+2]) + shf[c+2];
    float o3 = v.w * r * w[c+3] * (1.f + scl[c+3]) + shf[c+3];
    uint32_t* dp = (uint32_t*)(g_hnb + (size_t)row*CH + c);
    dp[0] = pack2bf(o0, o1);
    dp[1] = pack2bf(o2, o3);
}

// ---------------- BF16 GEMM with ldmatrix ----------------
// modes: 0 = fp32 store to Cf; 2 = g_h(Cf) += gate*(acc+bias); 3 = fused swiglu -> Gb
#define WSTR 20
__global__ __launch_bounds__(256) void k_gemm(
    const __nv_bfloat16* __restrict__ A, const __nv_bfloat16* __restrict__ W,
    const float* __restrict__ bias, float* __restrict__ Cf, __nv_bfloat16* __restrict__ Gb,
    const float* __restrict__ ada, int gch, int mode, int M, int N, int K)
{
    extern __shared__ uint32_t sm[];     // 3 stages * 5120 words
    const int tid  = threadIdx.x;
    const int lane = tid & 31;
    const int warp = tid >> 5;
    const int gid  = lane >> 2;
    const int tig  = lane & 3;
    const int row0 = (warp & 3) * 32;
    const int col0 = (warp >> 2) * 64;
    const int bm = blockIdx.y * 128, bn = blockIdx.x * 128;
    const int KT = K >> 5;
    const int lr   = lane & 7;
    const int sel8 = (lane >> 3) & 1;
    const int sel4 = (lane >> 4) & 1;

    const uint32_t sbase = (uint32_t)__cvta_generic_to_shared(sm);
    const uint32_t aoff  = ((row0 + sel8*8 + lr)*WSTR + sel4*4) * 4;
    const uint32_t boff  = ((col0 + sel8*8 + lr)*WSTR + sel4*4) * 4 + 2560*4;

    auto load_body = [&](int kt, int s) {
        uint32_t* As = sm + s * 5120;
        uint32_t* Ws = As + 2560;
        const int k0 = kt << 5;
        #pragma unroll
        for (int i = 0; i < 2; i++) {
            const int lin = tid + i*256;
            const int r = lin >> 2, c4 = lin & 3;
            cpa16(As + r*WSTR + c4*4, A + (size_t)(bm + r)*K + k0 + c4*8);
            cpa16(Ws + r*WSTR + c4*4, W + (size_t)(bn + r)*K + k0 + c4*8);
        }
    };

    load_body(0, 0);
    asm volatile("cp.async.commit_group;\n");
    load_body(1, 1);
    asm volatile("cp.async.commit_group;\n");

    float acc[2][8][4];
    #pragma unroll
    for (int i = 0; i < 2; i++)
        #pragma unroll
        for (int j = 0; j < 8; j++)
            #pragma unroll
            for (int c = 0; c < 4; c++) acc[i][j][c] = 0.f;

    for (int kt = 0; kt < KT; kt++) {
        asm volatile("cp.async.wait_group 1;\n");
        __syncthreads();
        if (kt + 2 < KT) load_body(kt + 2, (kt + 2) % 3);
        asm volatile("cp.async.commit_group;\n");

        const uint32_t stb = sbase + (uint32_t)((kt % 3) * 5120 * 4);
        #pragma unroll
        for (int kk = 0; kk < 2; kk++) {
            const uint32_t kb = kk * 32;           // 8 words * 4B
            uint32_t af[2][4], bf[8][2];
            const uint32_t aa = stb + aoff + kb;
            ldm4(aa,                af[0][0], af[0][1], af[0][2], af[0][3]);
            ldm4(aa + 16*WSTR*4,    af[1][0], af[1][1], af[1][2], af[1][3]);
            const uint32_t bb = stb + boff + kb;
            #pragma unroll
            for (int nt2 = 0; nt2 < 4; nt2++) {
                ldm4(bb + nt2*16*WSTR*4,
                     bf[2*nt2][0], bf[2*nt2+1][0], bf[2*nt2][1], bf[2*nt2+1][1]);
            }
            #pragma unroll
            for (int mt = 0; mt < 2; mt++)
                #pragma unroll
                for (int nt = 0; nt < 8; nt++)
                    MMA_BF16(acc[mt][nt], af[mt], bf[nt]);
        }
    }

    #pragma unroll
    for (int mt = 0; mt < 2; mt++) {
        const int row = bm + row0 + mt*16 + gid;
        const int b   = row >> 10;
        const float* gp = ada + b*6*CH + gch*CH;
        #pragma unroll
        for (int nt = 0; nt < 8; nt++) {
            const int col = bn + col0 + nt*8 + tig*2;
            const float b0 = bias[col], b1 = bias[col+1];
            float v00 = acc[mt][nt][0] + b0, v01 = acc[mt][nt][1] + b1;
            float v10 = acc[mt][nt][2] + b0, v11 = acc[mt][nt][3] + b1;
            if (mode == 0) {
                *(float2*)(Cf + (size_t)row*N + col)     = make_float2(v00, v01);
                *(float2*)(Cf + (size_t)(row+8)*N + col) = make_float2(v10, v11);
            } else if (mode == 2) {
                const float gg0 = gp[col], gg1 = gp[col+1];
                float2 h0 = *(float2*)(Cf + (size_t)row*N + col);
                float2 h1 = *(float2*)(Cf + (size_t)(row+8)*N + col);
                h0.x += gg0*v00; h0.y += gg1*v01;
                h1.x += gg0*v10; h1.y += gg1*v11;
                *(float2*)(Cf + (size_t)row*N + col)     = h0;
                *(float2*)(Cf + (size_t)(row+8)*N + col) = h1;
            } else {  // mode 3: fused swiglu; (v00,v01) = (x1_j, x2_j)
                const int j = col >> 1;
                const float s0 = (v00 / (1.f + __expf(-v00))) * v01;
                const float s1 = (v10 / (1.f + __expf(-v10))) * v11;
                Gb[(size_t)row*(N>>1) + j]     = __float2bfloat16(s0);
                Gb[(size_t)(row+8)*(N>>1) + j] = __float2bfloat16(s1);
            }
        }
    }
}

// ---------------- q/k RMSNorm + RoPE -> bf16; V -> transposed bf16 ----------------
__global__ void k_qkrope(const float* __restrict__ qn_w, const float* __restrict__ kn_w) {
    const int gw   = (blockIdx.x * blockDim.x + threadIdx.x) >> 5;
    const int lane = threadIdx.x & 31;
    const int head = gw & 7;
    const int tok  = gw >> 3;
    const int b = tok >> 10;
    const int n = tok & 1023;
    const int rrow = n >> 5, rcol = n & 31;
    const float* qp = g_qkv + (size_t)tok * (3*CH) + head * HDIM;
    const float* kp = qp + CH;
    const float* vp = qp + 2*CH;
    const int j = lane * 2;
    float q0 = qp[j], q1 = qp[j+1], k0 = kp[j], k1 = kp[j+1];
    float sq = q0*q0 + q1*q1, sk = k0*k0 + k1*k1;
    #pragma unroll
    for (int o = 16; o; o >>= 1) {
        sq += __shfl_xor_sync(0xffffffffu, sq, o);
        sk += __shfl_xor_sync(0xffffffffu, sk, o);
    }
    const float rq = rsqrtf(sq / 64.f + EPSV);
    const float rk = rsqrtf(sk / 64.f + EPSV);
    q0 *= rq * qn_w[j];  q1 *= rq * qn_w[j+1];
    k0 *= rk * kn_w[j];  k1 *= rk * kn_w[j+1];
    const int half = (j >= 32);
    const int idx  = (half ? (j - 32) : j) >> 1;
    const float freq = exp2f(-(float)idx * (13.287712379549449f / 16.f));
    const float f = (half ? (float)rcol : (float)rrow) * freq;
    const float cf = cosf(f), sf = sinf(f);
    const float qa = q0*cf - q1*sf, qb = q1*cf + q0*sf;
    const float ka = k0*cf - k1*sf, kb = k1*cf + k0*sf;
    const float qs = 0.125f;
    uint32_t* qkw = (uint32_t*)g_qkb;
    qkw[(size_t)tok*512 + head*32 + lane]       = pack2bf(qa*qs, qb*qs);
    qkw[(size_t)tok*512 + 256 + head*32 + lane] = pack2bf(ka, kb);
    const int bh = b*8 + head;
    g_vtb[((size_t)bh*64 + j)  *NTOK + n] = __float2bfloat16(vp[j]);
    g_vtb[((size_t)bh*64 + j+1)*NTOK + n] = __float2bfloat16(vp[j+1]);
}

// ---------------- flash attention, bf16 mma + ldmatrix + double-buffered K/V ----------------
#define QSTR 36
__global__ __launch_bounds__(256) void k_attn_mma() {
    extern __shared__ uint32_t smw[];
    // stage s: K at s*128*QSTR, V at s*128*QSTR + 64*QSTR ; P/Q at 256*QSTR
    uint32_t* Ps = smw + 256*QSTR;
    const int bh = blockIdx.x;
    const int b = bh >> 3, hh = bh & 7;
    const int q0 = blockIdx.y * 128;
    const int tid = threadIdx.x, lane = tid & 31, warp = tid >> 5;
    const int gid = lane >> 2, tig = lane & 3;
    const int lr = lane & 7, sel8 = (lane >> 3) & 1, sel4 = (lane >> 4) & 1;
    const __nv_bfloat16* qk = g_qkb + (size_t)b * NTOK * 1024;
    const __nv_bfloat16* vt = g_vtb + (size_t)bh * 64 * NTOK;

    const uint32_t sbase = (uint32_t)__cvta_generic_to_shared(smw);
    const uint32_t pbase = sbase + 256*QSTR*4;
    const uint32_t rowoff = ((warp*16 + sel8*8 + lr)*QSTR + sel4*4) * 4;  // A/P/Q frag
    const uint32_t kvoff  = ((sel8*8 + lr)*QSTR + sel4*4) * 4;            // K/V frag

    // stage Q
    #pragma unroll
    for (int i = 0; i < 4; i++) {
        const int lin = tid + i*256;
        const int r = lin >> 3, c4 = lin & 7;
        cpa16(Ps + r*QSTR + c4*4, qk + (size_t)(q0 + r)*1024 + hh*64 + c4*8);
    }
    asm volatile("cp.async.commit_group;\n");
    asm volatile("cp.async.wait_group 0;\n");
    __syncthreads();
    const int rA = warp*16 + gid;
    uint32_t qf[4][4];
    #pragma unroll
    for (int kk = 0; kk < 4; kk++) {
        const uint32_t a = pbase + rowoff + kk*32;
        ldm4(a, qf[kk][0], qf[kk][1], qf[kk][2], qf[kk][3]);
    }
    __syncthreads();

    auto load_kv = [&](int kc, int s) {
        uint32_t* Ks = smw + s*128*QSTR;
        uint32_t* Vs = Ks + 64*QSTR;
        #pragma unroll
        for (int i = 0; i < 2; i++) {
            const int lin = tid + i*256;
            const int r = lin >> 3, c4 = lin & 7;
            cpa16(Ks + r*QSTR + c4*4, qk + (size_t)(kc + r)*1024 + 512 + hh*64 + c4*8);
            cpa16(Vs + r*QSTR + c4*4, vt + (size_t)r*NTOK + kc + c4*8);
        }
    };

    float m0 = -1e30f, m1 = -1e30f, l0 = 0.f, l1 = 0.f;
    float oacc[8][4];
    #pragma unroll
    for (int nt = 0; nt < 8; nt++)
        #pragma unroll
        for (int c = 0; c < 4; c++) oacc[nt][c] = 0.f;

    load_kv(0, 0);
    asm volatile("cp.async.commit_group;\n");

    for (int it = 0; it < NTOK/64; it++) {
        const int s = it & 1;
        if (it + 1 < NTOK/64) {
            load_kv((it+1)*64, s ^ 1);
            asm volatile("cp.async.commit_group;\n");
            asm volatile("cp.async.wait_group 1;\n");
        } else {
            asm volatile("cp.async.wait_group 0;\n");
        }
        __syncthreads();
        const uint32_t kbase = sbase + (uint32_t)(s*128*QSTR*4);
        const uint32_t vbase = kbase + 64*QSTR*4;

        // S = Q @ K^T
        float sacc[8][4];
        #pragma unroll
        for (int nt = 0; nt < 8; nt++)
            #pragma unroll
            for (int c = 0; c < 4; c++) sacc[nt][c] = 0.f;
        #pragma unroll
        for (int kk = 0; kk < 4; kk++) {
            uint32_t bf[8][2];
            const uint32_t kb = kbase + kvoff + kk*32;
            #pragma unroll
            for (int nt2 = 0; nt2 < 4; nt2++)
                ldm4(kb + nt2*16*QSTR*4,
                     bf[2*nt2][0], bf[2*nt2+1][0], bf[2*nt2][1], bf[2*nt2+1][1]);
            #pragma unroll
            for (int nt = 0; nt < 8; nt++)
                MMA_BF16(sacc[nt], qf[kk], bf[nt]);
        }

        // online softmax
        float cm0 = -1e30f, cm1 = -1e30f;
        #pragma unroll
        for (int nt = 0; nt < 8; nt++) {
            cm0 = fmaxf(cm0, fmaxf(sacc[nt][0], sacc[nt][1]));
            cm1 = fmaxf(cm1, fmaxf(sacc[nt][2], sacc[nt][3]));
        }
        #pragma unroll
        for (int o = 1; o <= 2; o <<= 1) {
            cm0 = fmaxf(cm0, __shfl_xor_sync(0xffffffffu, cm0, o));
            cm1 = fmaxf(cm1, __shfl_xor_sync(0xffffffffu, cm1, o));
        }
        const float mn0 = fmaxf(m0, cm0), mn1 = fmaxf(m1, cm1);
        const float cr0 = __expf(m0 - mn0), cr1 = __expf(m1 - mn1);
        l0 *= cr0; l1 *= cr1;
        #pragma unroll
        for (int nt = 0; nt < 8; nt++) {
            oacc[nt][0] *= cr0; oacc[nt][1] *= cr0;
            oacc[nt][2] *= cr1; oacc[nt][3] *= cr1;
        }
        float al0 = 0.f, al1 = 0.f;
        #pragma unroll
        for (int nt = 0; nt < 8; nt++) {
            float p00 = __expf(sacc[nt][0] - mn0);
            float p01 = __expf(sacc[nt][1] - mn0);
            float p10 = __expf(sacc[nt][2] - mn1);
            float p11 = __expf(sacc[nt][3] - mn1);
            al0 += p00 + p01;  al1 += p10 + p11;
            Ps[rA*QSTR     + nt*4 + tig] = pack2bf(p00, p01);
            Ps[(rA+8)*QSTR + nt*4 + tig] = pack2bf(p10, p11);
        }
        #pragma unroll
        for (int o = 1; o <= 2; o <<= 1) {
            al0 += __shfl_xor_sync(0xffffffffu, al0, o);
            al1 += __shfl_xor_sync(0xffffffffu, al1, o);
        }
        l0 += al0; l1 += al1;
        m0 = mn0; m1 = mn1;
        __syncwarp();

        // O += P @ V
        #pragma unroll
        for (int kk = 0; kk < 4; kk++) {
            uint32_t af[4];
            ldm4(pbase + rowoff + kk*32, af[0], af[1], af[2], af[3]);
            uint32_t bf[8][2];
            const uint32_t vb = vbase + kvoff + kk*32;
            #pragma unroll
            for (int nt2 = 0; nt2 < 4; nt2++)
                ldm4(vb + nt2*16*QSTR*4,
                     bf[2*nt2][0], bf[2*nt2+1][0], bf[2*nt2][1], bf[2*nt2+1][1]);
            #pragma unroll
            for (int nt = 0; nt < 8; nt++)
                MMA_BF16(oacc[nt], af, bf[nt]);
        }
        __syncthreads();
    }

    const float inv0 = 1.f / l0, inv1 = 1.f / l1;
    uint32_t* ow = (uint32_t*)g_attb;
    const size_t row = (size_t)b*NTOK + q0 + rA;
    #pragma unroll
    for (int nt = 0; nt < 8; nt++) {
        const int cw = hh*32 + nt*4 + tig;
        ow[row*256 + cw]     = pack2bf(oacc[nt][0]*inv0, oacc[nt][1]*inv0);
        ow[(row+8)*256 + cw] = pack2bf(oacc[nt][2]*inv1, oacc[nt][3]*inv1);
    }
}

// ---------------- final: out[b,c,n] = x + h^T ----------------
__global__ void k_final(const float* __restrict__ x, float* __restrict__ out) {
    __shared__ float th[32][33];
    const int b  = blockIdx.y;
    const int n0 = blockIdx.x * 32;
    const int tx = threadIdx.x, ty = threadIdx.y;
    for (int c0 = 0; c0 < CH; c0 += 32) {
        __syncthreads();
        th[ty][tx] = g_h[((size_t)b*NTOK + n0 + ty)*CH + c0 + tx];
        __syncthreads();
        const size_t oidx = ((size_t)b*CH + c0 + ty)*NTOK + n0 + tx;
        out[oidx] = x[oidx] + th[tx][ty];
    }
}

// ---------------- launcher ----------------
extern "C" void kernel_launch(void* const* d_in, const int* in_sizes, int n_in,
                              void* d_out, int out_size) {
    const float* x      = (const float*)d_in[0];
    const float* temb   = (const float*)d_in[1];
    const float* gn_w   = (const float*)d_in[2];
    const float* gn_b   = (const float*)d_in[3];
    const float* ada_w  = (const float*)d_in[4];
    const float* ada_b  = (const float*)d_in[5];
    const float* n1_w   = (const float*)d_in[6];
    const float* n2_w   = (const float*)d_in[7];
    const float* qkv_w  = (const float*)d_in[8];
    const float* qkv_b  = (const float*)d_in[9];
    const float* qn_w   = (const float*)d_in[10];
    const float* kn_w   = (const float*)d_in[11];
    const float* proj_w = (const float*)d_in[12];
    const float* proj_b = (const float*)d_in[13];
    const float* w12    = (const float*)d_in[14];
    const float* b12    = (const float*)d_in[15];
    const float* w_out  = (const float*)d_in[16];
    const float* b_out  = (const float*)d_in[17];
    float* out = (float*)d_out;

    float *p_h, *p_qkv, *p_ada, *p_b12p;
    __nv_bfloat16 *p_hnb, *p_attb, *p_gateb;
    __nv_bfloat16 *p_wqkv, *p_wproj, *p_w12c, *p_woc;
    cudaGetSymbolAddress((void**)&p_h,     g_h);
    cudaGetSymbolAddress((void**)&p_qkv,   g_qkv);
    cudaGetSymbolAddress((void**)&p_ada,   g_ada);
    cudaGetSymbolAddress((void**)&p_b12p,  g_b12p);
    cudaGetSymbolAddress((void**)&p_hnb,   g_hnb);
    cudaGetSymbolAddress((void**)&p_attb,  g_attb);
    cudaGetSymbolAddress((void**)&p_gateb, g_gateb);
    cudaGetSymbolAddress((void**)&p_wqkv,  g_wqkv);
    cudaGetSymbolAddress((void**)&p_wproj, g_wproj);
    cudaGetSymbolAddress((void**)&p_w12c,  g_w12c);
    cudaGetSymbolAddress((void**)&p_woc,   g_woc);

    const int gemm_smem = 3*5120*4;          // 61440 B
    const int attn_smem = 384*QSTR*4;        // 55296 B
    cudaFuncSetAttribute(k_gemm,     cudaFuncAttributeMaxDynamicSharedMemorySize, gemm_smem);
    cudaFuncSetAttribute(k_attn_mma, cudaFuncAttributeMaxDynamicSharedMemorySize, attn_smem);

    // weight conversion (+ w12 permute, bias permute)
    k_cvt   <<<(3*CH*CH/4 + 255)/256, 256>>>(qkv_w,  p_wqkv,  3*CH*CH);
    k_cvt   <<<(CH*CH/4   + 255)/256, 256>>>(proj_w, p_wproj, CH*CH);
    k_cvtw12<<<(2*FFN*CH/4+ 255)/256, 256>>>(w12,    p_w12c);
    k_permb <<<FFN/256, 256>>>(b12);
    k_cvt   <<<(CH*FFN/4  + 255)/256, 256>>>(w_out,  p_woc,   CH*FFN);

    // adaLN + GroupNorm
    k_ada    <<<dim3(24, BDIM), 128>>>(temb, ada_w, ada_b);
    k_gnstats<<<BDIM*32, 256>>>(x);
    k_gnapply<<<dim3(NTOK/32, BDIM), dim3(32,32)>>>(x, gn_w, gn_b);

    // attention branch
    k_rmsmod <<<NT, 128>>>(n1_w, 0, 1);
    k_gemm   <<<dim3((3*CH)/128, NT/128), 256, gemm_smem>>>(
        p_hnb, p_wqkv, qkv_b, p_qkv, nullptr, p_ada, 0, 0, NT, 3*CH, CH);
    k_qkrope <<<(NT*NHEADS*32)/128, 128>>>(qn_w, kn_w);
    k_attn_mma<<<dim3(BDIM*NHEADS, NTOK/128), 256, attn_smem>>>();
    k_gemm   <<<dim3(CH/128, NT/128), 256, gemm_smem>>>(
        p_attb, p_wproj, proj_b, p_h, nullptr, p_ada, 2, 2, NT, CH, CH);

    // FFN branch (swiglu fused into w12 epilogue via permuted weights)
    k_rmsmod <<<NT, 128>>>(n2_w, 3, 4);
    k_gemm   <<<dim3((2*FFN)/128, NT/128), 256, gemm_smem>>>(
        p_hnb, p_w12c, p_b12p, nullptr, p_gateb, p_ada, 0, 3, NT, 2*FFN, CH);
    k_gemm   <<<dim3(CH/128, NT/128), 256, gemm_smem>>>(
        p_gateb, p_woc, b_out, p_h, nullptr, p_ada, 5, 2, NT, CH, FFN);

    // epilogue
    k_final  <<<dim3(NTOK/32, BDIM), dim3(32,32)>>>(x, out);
}

// round 7
// speedup vs baseline: 5.4265x; 1.0193x over previous
#include <cuda_runtime.h>
#include <cuda_bf16.h>
#include <cstdint>

// ---------------- problem constants ----------------
#define BDIM   16
#define CH     512
#define NTOK   1024
#define NT     (BDIM*NTOK)
#define NHEADS 8
#define HDIM   64
#define FFN    2048
#define EPSV   1e-6f

// ---------------- scratch ----------------
__device__ float g_ada [BDIM*6*CH];
__device__ float g_h   [NT*CH];
__device__ float g_stats[BDIM*32*2];
__device__ float g_b12p[2*FFN];
__device__ __nv_bfloat16 g_hnb [NT*CH];
__device__ __nv_bfloat16 g_qkvb[NT*3*CH];   // QKV gemm output, bf16
__device__ __nv_bfloat16 g_qkb [NT*2*CH];   // q,k after rope, bf16
__device__ __nv_bfloat16 g_vtb [BDIM*NHEADS*HDIM*NTOK]; // V transposed [b,h,d,tok]
__device__ __nv_bfloat16 g_attb[NT*CH];
__device__ __nv_bfloat16 g_gateb[NT*FFN];
__device__ __nv_bfloat16 g_wqkv [3*CH*CH];
__device__ __nv_bfloat16 g_wproj[CH*CH];
__device__ __nv_bfloat16 g_w12c [2*FFN*CH];   // row-permuted: 2j<-w1_j, 2j+1<-w2_j
__device__ __nv_bfloat16 g_woc  [CH*FFN];

// ---------------- helpers ----------------
__device__ __forceinline__ uint32_t pack2bf(float lo, float hi) {
    uint32_t r;
    asm("cvt.rn.bf16x2.f32 %0, %1, %2;" : "=r"(r) : "f"(hi), "f"(lo));
    return r;
}
__device__ __forceinline__ void cpa16(void* s, const void* g) {
    uint32_t sa = (uint32_t)__cvta_generic_to_shared(s);
    asm volatile("cp.async.cg.shared.global [%0], [%1], 16;\n" :: "r"(sa), "l"(g));
}
__device__ __forceinline__ void ldm4(uint32_t addr, uint32_t& r0, uint32_t& r1,
                                     uint32_t& r2, uint32_t& r3) {
    asm volatile("ldmatrix.sync.aligned.m8n8.x4.shared.b16 {%0,%1,%2,%3}, [%4];"
                 : "=r"(r0), "=r"(r1), "=r"(r2), "=r"(r3) : "r"(addr));
}
#define MMA_BF16(d, a, b) \
    asm volatile("mma.sync.aligned.m16n8k16.row.col.f32.bf16.bf16.f32 " \
                 "{%0,%1,%2,%3}, {%4,%5,%6,%7}, {%8,%9}, {%0,%1,%2,%3};" \
                 : "+f"(d[0]), "+f"(d[1]), "+f"(d[2]), "+f"(d[3]) \
                 : "r"(a[0]), "r"(a[1]), "r"(a[2]), "r"(a[3]), "r"(b[0]), "r"(b[1]))

// ---------------- merged weight conversion (1 launch) ----------------
__device__ __forceinline__ void cvt4(const float* __restrict__ s,
                                     __nv_bfloat16* __restrict__ d, int i) {
    float4 v = *(const float4*)(s + i);
    *(uint32_t*)(d + i)     = pack2bf(v.x, v.y);
    *(uint32_t*)(d + i + 2) = pack2bf(v.z, v.w);
}
__global__ void k_cvtall(const float* __restrict__ qkv_w, const float* __restrict__ proj_w,
                         const float* __restrict__ w_out, const float* __restrict__ w12,
                         const float* __restrict__ b12) {
    const int gi = blockIdx.x * blockDim.x + threadIdx.x;
    if (gi < 196608) {                       // qkv: 3*CH*CH/4
        cvt4(qkv_w, g_wqkv, gi * 4);
    } else if (gi < 262144) {                // proj: CH*CH/4
        cvt4(proj_w, g_wproj, (gi - 196608) * 4);
    } else if (gi < 524288) {                // w_out: CH*FFN/4
        cvt4(w_out, g_woc, (gi - 262144) * 4);
    } else if (gi < 1048576) {               // w12 permuted: 2*FFN*CH/4
        const int i = (gi - 524288) * 4;
        const int r = i >> 9;
        const int k = i & (CH - 1);
        const int sr = (r & 1) ? (FFN + (r >> 1)) : (r >> 1);
        float4 v = *(const float4*)(w12 + (size_t)sr*CH + k);
        *(uint32_t*)(g_w12c + i)     = pack2bf(v.x, v.y);
        *(uint32_t*)(g_w12c + i + 2) = pack2bf(v.z, v.w);
    } else if (gi < 1048576 + FFN) {         // b12 permute
        const int j = gi - 1048576;
        g_b12p[2*j]   = b12[j];
        g_b12p[2*j+1] = b12[FFN + j];
    }
}

// ---------------- adaLN ----------------
__global__ void k_ada(const float* __restrict__ temb, const float* __restrict__ ada_w,
                      const float* __restrict__ ada_b) {
    __shared__ float s[CH];
    const int b = blockIdx.y;
    for (int i = threadIdx.x; i < CH; i += blockDim.x) {
        float v = temb[b*CH + i];
        s[i] = v / (1.f + __expf(-v));
    }
    __syncthreads();
    const int n = blockIdx.x * blockDim.x + threadIdx.x;
    const float* wr = ada_w + (size_t)n * CH;
    float acc = 0.f;
    #pragma unroll 8
    for (int k = 0; k < CH; k++) acc += wr[k] * s[k];
    g_ada[b*6*CH + n] = acc + ada_b[n];
}

// ---------------- GroupNorm stats ----------------
__global__ void k_gnstats(const float* __restrict__ x) {
    const int bg = blockIdx.x;
    const float* p = x + (size_t)bg * 16 * NTOK;
    float s = 0.f, s2 = 0.f;
    for (int i = threadIdx.x; i < 16*NTOK; i += blockDim.x) {
        float v = p[i]; s += v; s2 += v*v;
    }
    #pragma unroll
    for (int o = 16; o; o >>= 1) {
        s  += __shfl_xor_sync(0xffffffffu, s,  o);
        s2 += __shfl_xor_sync(0xffffffffu, s2, o);
    }
    __shared__ float sh[64];
    const int w = threadIdx.x >> 5, l = threadIdx.x & 31;
    if (l == 0) { sh[w] = s; sh[32 + w] = s2; }
    __syncthreads();
    if (threadIdx.x < 32) {
        const int nw = blockDim.x >> 5;
        s  = (threadIdx.x < nw) ? sh[threadIdx.x]      : 0.f;
        s2 = (threadIdx.x < nw) ? sh[32 + threadIdx.x] : 0.f;
        #pragma unroll
        for (int o = 16; o; o >>= 1) {
            s  += __shfl_xor_sync(0xffffffffu, s,  o);
            s2 += __shfl_xor_sync(0xffffffffu, s2, o);
        }
        if (threadIdx.x == 0) {
            const float inv = 1.f / (16.f * NTOK);
            float mu  = s * inv;
            float var = s2 * inv - mu * mu;
            g_stats[bg*2]     = mu;
            g_stats[bg*2 + 1] = rsqrtf(var + EPSV);
        }
    }
}

// ---------------- GroupNorm apply + transpose ----------------
__global__ void k_gnapply(const float* __restrict__ x, const float* __restrict__ gw,
                          const float* __restrict__ gb) {
    __shared__ float tile[32][33];
    const int b  = blockIdx.y;
    const int n0 = blockIdx.x * 32;
    const int tx = threadIdx.x, ty = threadIdx.y;
    for (int c0 = 0; c0 < CH; c0 += 32) {
        __syncthreads();
        tile[ty][tx] = x[((size_t)b*CH + c0 + ty)*NTOK + n0 + tx];
        __syncthreads();
        const int c  = c0 + tx;
        const float mu = g_stats[(b*32 + (c >> 4))*2];
        const float rs = g_stats[(b*32 + (c >> 4))*2 + 1];
        g_h[((size_t)b*NTOK + n0 + ty)*CH + c] = (tile[tx][ty] - mu) * rs * gw[c] + gb[c];
    }
}

// ---------------- RMSNorm + modulation -> bf16 ----------------
__global__ void k_rmsmod(const float* __restrict__ w, int shift_ch, int scale_ch) {
    const int row = blockIdx.x;
    const int b = row >> 10;
    const float* hp = g_h + (size_t)row * CH;
    const int t = threadIdx.x;
    float4 v = *(const float4*)(hp + t*4);
    float ss = v.x*v.x + v.y*v.y + v.z*v.z + v.w*v.w;
    #pragma unroll
    for (int o = 16; o; o >>= 1) ss += __shfl_xor_sync(0xffffffffu, ss, o);
    __shared__ float sh[4];
    if ((t & 31) == 0) sh[t >> 5] = ss;
    __syncthreads();
    ss = sh[0] + sh[1] + sh[2] + sh[3];
    const float r = rsqrtf(ss / (float)CH + EPSV);
    const float* shf = g_ada + b*6*CH + shift_ch*CH;
    const float* scl = g_ada + b*6*CH + scale_ch*CH;
    const int c = t*4;
    float o0 = v.x * r * w[c+0] * (1.f + scl[c+0]) + shf[c+0];
    float o1 = v.y * r * w[c+1] * (1.f + scl[c+1]) + shf[c+1];
    float o2 = v.z * r * w[c+2] * (1.f + scl[c+2]) + shf[c+2];
    float o3 = v.w * r * w[c+3] * (1.f + scl[c+3]) + shf[c+3];
    uint32_t* dp = (uint32_t*)(g_hnb + (size_t)row*CH + c);
    dp[0] = pack2bf(o0, o1);
    dp[1] = pack2bf(o2, o3);
}

// ---------------- BF16 GEMM, ldmatrix, 4-stage cp.async ----------------
// modes: 1 = bf16 store to Cb; 2 = g_h(Cf) += gate*(acc+bias); 3 = fused swiglu -> Gb
#define WSTR 20
__global__ __launch_bounds__(256) void k_gemm(
    const __nv_bfloat16* __restrict__ A, const __nv_bfloat16* __restrict__ W,
    const float* __restrict__ bias, float* __restrict__ Cf, uint32_t* __restrict__ Cb,
    __nv_bfloat16* __restrict__ Gb, const float* __restrict__ ada,
    int gch, int mode, int M, int N, int K)
{
    extern __shared__ uint32_t sm[];     // 4 stages * 5120 words
    const int tid  = threadIdx.x;
    const int lane = tid & 31;
    const int warp = tid >> 5;
    const int gid  = lane >> 2;
    const int tig  = lane & 3;
    const int row0 = (warp & 3) * 32;
    const int col0 = (warp >> 2) * 64;
    const int bm = blockIdx.y * 128, bn = blockIdx.x * 128;
    const int KT = K >> 5;
    const int lr   = lane & 7;
    const int sel8 = (lane >> 3) & 1;
    const int sel4 = (lane >> 4) & 1;

    const uint32_t sbase = (uint32_t)__cvta_generic_to_shared(sm);
    const uint32_t aoff  = ((row0 + sel8*8 + lr)*WSTR + sel4*4) * 4;
    const uint32_t boff  = ((col0 + sel8*8 + lr)*WSTR + sel4*4) * 4 + 2560*4;

    auto load_body = [&](int kt, int s) {
        uint32_t* As = sm + s * 5120;
        uint32_t* Ws = As + 2560;
        const int k0 = kt << 5;
        #pragma unroll
        for (int i = 0; i < 2; i++) {
            const int lin = tid + i*256;
            const int r = lin >> 2, c4 = lin & 3;
            cpa16(As + r*WSTR + c4*4, A + (size_t)(bm + r)*K + k0 + c4*8);
            cpa16(Ws + r*WSTR + c4*4, W + (size_t)(bn + r)*K + k0 + c4*8);
        }
    };

    load_body(0, 0);
    asm volatile("cp.async.commit_group;\n");
    load_body(1, 1);
    asm volatile("cp.async.commit_group;\n");
    load_body(2, 2);
    asm volatile("cp.async.commit_group;\n");

    float acc[2][8][4];
    #pragma unroll
    for (int i = 0; i < 2; i++)
        #pragma unroll
        for (int j = 0; j < 8; j++)
            #pragma unroll
            for (int c = 0; c < 4; c++) acc[i][j][c] = 0.f;

    for (int kt = 0; kt < KT; kt++) {
        asm volatile("cp.async.wait_group 2;\n");
        __syncthreads();
        if (kt + 3 < KT) load_body(kt + 3, (kt + 3) & 3);
        asm volatile("cp.async.commit_group;\n");

        const uint32_t stb = sbase + (uint32_t)((kt & 3) * 5120 * 4);
        #pragma unroll
        for (int kk = 0; kk < 2; kk++) {
            const uint32_t kb = kk * 32;
            uint32_t af[2][4], bf[8][2];
            const uint32_t aa = stb + aoff + kb;
            ldm4(aa,             af[0][0], af[0][1], af[0][2], af[0][3]);
            ldm4(aa + 16*WSTR*4, af[1][0], af[1][1], af[1][2], af[1][3]);
            const uint32_t bb = stb + boff + kb;
            #pragma unroll
            for (int nt2 = 0; nt2 < 4; nt2++) {
                ldm4(bb + nt2*16*WSTR*4,
                     bf[2*nt2][0], bf[2*nt2+1][0], bf[2*nt2][1], bf[2*nt2+1][1]);
            }
            #pragma unroll
            for (int mt = 0; mt < 2; mt++)
                #pragma unroll
                for (int nt = 0; nt < 8; nt++)
                    MMA_BF16(acc[mt][nt], af[mt], bf[nt]);
        }
    }

    #pragma unroll
    for (int mt = 0; mt < 2; mt++) {
        const int row = bm + row0 + mt*16 + gid;
        const int b   = row >> 10;
        const float* gp = ada + b*6*CH + gch*CH;
        #pragma unroll
        for (int nt = 0; nt < 8; nt++) {
            const int col = bn + col0 + nt*8 + tig*2;
            const float b0 = bias[col], b1 = bias[col+1];
            float v00 = acc[mt][nt][0] + b0, v01 = acc[mt][nt][1] + b1;
            float v10 = acc[mt][nt][2] + b0, v11 = acc[mt][nt][3] + b1;
            if (mode == 1) {
                Cb[((size_t)row*N + col) >> 1]     = pack2bf(v00, v01);
                Cb[((size_t)(row+8)*N + col) >> 1] = pack2bf(v10, v11);
            } else if (mode == 2) {
                const float gg0 = gp[col], gg1 = gp[col+1];
                float2 h0 = *(float2*)(Cf + (size_t)row*N + col);
                float2 h1 = *(float2*)(Cf + (size_t)(row+8)*N + col);
                h0.x += gg0*v00; h0.y += gg1*v01;
                h1.x += gg0*v10; h1.y += gg1*v11;
                *(float2*)(Cf + (size_t)row*N + col)     = h0;
                *(float2*)(Cf + (size_t)(row+8)*N + col) = h1;
            } else {  // mode 3: fused swiglu; (v00,v01) = (x1_j, x2_j)
                const int j = col >> 1;
                const float s0 = (v00 / (1.f + __expf(-v00))) * v01;
                const float s1 = (v10 / (1.f + __expf(-v10))) * v11;
                Gb[(size_t)row*(N>>1) + j]     = __float2bfloat16(s0);
                Gb[(size_t)(row+8)*(N>>1) + j] = __float2bfloat16(s1);
            }
        }
    }
}

// ---------------- q/k RMSNorm + RoPE (bf16 in) -> bf16; V -> transposed bf16 ----------------
__global__ void k_qkrope(const float* __restrict__ qn_w, const float* __restrict__ kn_w) {
    const int gw   = (blockIdx.x * blockDim.x + threadIdx.x) >> 5;
    const int lane = threadIdx.x & 31;
    const int head = gw & 7;
    const int tok  = gw >> 3;
    const int b = tok >> 10;
    const int n = tok & 1023;
    const int rrow = n >> 5, rcol = n & 31;
    const uint32_t* qkvw = (const uint32_t*)g_qkvb;
    const size_t base = (size_t)tok * 768;          // 1536 bf16 = 768 words
    float2 qv = __bfloat1622float2(*(const __nv_bfloat162*)&qkvw[base + head*32 + lane]);
    float2 kv = __bfloat1622float2(*(const __nv_bfloat162*)&qkvw[base + 256 + head*32 + lane]);
    float2 vv = __bfloat1622float2(*(const __nv_bfloat162*)&qkvw[base + 512 + head*32 + lane]);
    float q0 = qv.x, q1 = qv.y, k0 = kv.x, k1 = kv.y;
    const int j = lane * 2;
    float sq = q0*q0 + q1*q1, sk = k0*k0 + k1*k1;
    #pragma unroll
    for (int o = 16; o; o >>= 1) {
        sq += __shfl_xor_sync(0xffffffffu, sq, o);
        sk += __shfl_xor_sync(0xffffffffu, sk, o);
    }
    const float rq = rsqrtf(sq / 64.f + EPSV);
    const float rk = rsqrtf(sk / 64.f + EPSV);
    q0 *= rq * qn_w[j];  q1 *= rq * qn_w[j+1];
    k0 *= rk * kn_w[j];  k1 *= rk * kn_w[j+1];
    const int half = (j >= 32);
    const int idx  = (half ? (j - 32) : j) >> 1;
    const float freq = exp2f(-(float)idx * (13.287712379549449f / 16.f));
    const float f = (half ? (float)rcol : (float)rrow) * freq;
    const float cf = cosf(f), sf = sinf(f);
    const float qa = q0*cf - q1*sf, qb = q1*cf + q0*sf;
    const float ka = k0*cf - k1*sf, kb = k1*cf + k0*sf;
    const float qs = 0.125f;
    uint32_t* qkw = (uint32_t*)g_qkb;
    qkw[(size_t)tok*512 + head*32 + lane]       = pack2bf(qa*qs, qb*qs);
    qkw[(size_t)tok*512 + 256 + head*32 + lane] = pack2bf(ka, kb);
    const int bh = b*8 + head;
    g_vtb[((size_t)bh*64 + j)  *NTOK + n] = __float2bfloat16(vv.x);
    g_vtb[((size_t)bh*64 + j+1)*NTOK + n] = __float2bfloat16(vv.y);
}

// ---------------- flash attention: no-max softmax (|s|<=8.3 guaranteed) ----------------
#define QSTR 36
__global__ __launch_bounds__(256) void k_attn_mma() {
    extern __shared__ uint32_t smw[];
    uint32_t* Ps = smw + 256*QSTR;
    const int bh = blockIdx.x;
    const int b = bh >> 3, hh = bh & 7;
    const int q0 = blockIdx.y * 128;
    const int tid = threadIdx.x, lane = tid & 31, warp = tid >> 5;
    const int gid = lane >> 2, tig = lane & 3;
    const int lr = lane & 7, sel8 = (lane >> 3) & 1, sel4 = (lane >> 4) & 1;
    const __nv_bfloat16* qk = g_qkb + (size_t)b * NTOK * 1024;
    const __nv_bfloat16* vt = g_vtb + (size_t)bh * 64 * NTOK;

    const uint32_t sbase = (uint32_t)__cvta_generic_to_shared(smw);
    const uint32_t pbase = sbase + 256*QSTR*4;
    const uint32_t rowoff = ((warp*16 + sel8*8 + lr)*QSTR + sel4*4) * 4;
    const uint32_t kvoff  = ((sel8*8 + lr)*QSTR + sel4*4) * 4;

    #pragma unroll
    for (int i = 0; i < 4; i++) {
        const int lin = tid + i*256;
        const int r = lin >> 3, c4 = lin & 7;
        cpa16(Ps + r*QSTR + c4*4, qk + (size_t)(q0 + r)*1024 + hh*64 + c4*8);
    }
    asm volatile("cp.async.commit_group;\n");
    asm volatile("cp.async.wait_group 0;\n");
    __syncthreads();
    const int rA = warp*16 + gid;
    uint32_t qf[4][4];
    #pragma unroll
    for (int kk = 0; kk < 4; kk++) {
        const uint32_t a = pbase + rowoff + kk*32;
        ldm4(a, qf[kk][0], qf[kk][1], qf[kk][2], qf[kk][3]);
    }
    __syncthreads();

    auto load_kv = [&](int kc, int s) {
        uint32_t* Ks = smw + s*128*QSTR;
        uint32_t* Vs = Ks + 64*QSTR;
        #pragma unroll
        for (int i = 0; i < 2; i++) {
            const int lin = tid + i*256;
            const int r = lin >> 3, c4 = lin & 7;
            cpa16(Ks + r*QSTR + c4*4, qk + (size_t)(kc + r)*1024 + 512 + hh*64 + c4*8);
            cpa16(Vs + r*QSTR + c4*4, vt + (size_t)r*NTOK + kc + c4*8);
        }
    };

    // |s| <= 8*(1+bf16 slack); fixed shift by 8 replaces online max
    float l0 = 0.f, l1 = 0.f;
    float oacc[8][4];
    #pragma unroll
    for (int nt = 0; nt < 8; nt++)
        #pragma unroll
        for (int c = 0; c < 4; c++) oacc[nt][c] = 0.f;

    load_kv(0, 0);
    asm volatile("cp.async.commit_group;\n");

    for (int it = 0; it < NTOK/64; it++) {
        const int s = it & 1;
        if (it + 1 < NTOK/64) {
            load_kv((it+1)*64, s ^ 1);
            asm volatile("cp.async.commit_group;\n");
            asm volatile("cp.async.wait_group 1;\n");
        } else {
            asm volatile("cp.async.wait_group 0;\n");
        }
        __syncthreads();
        const uint32_t kbase = sbase + (uint32_t)(s*128*QSTR*4);
        const uint32_t vbase = kbase + 64*QSTR*4;

        // S = Q @ K^T
        float sacc[8][4];
        #pragma unroll
        for (int nt = 0; nt < 8; nt++)
            #pragma unroll
            for (int c = 0; c < 4; c++) sacc[nt][c] = 0.f;
        #pragma unroll
        for (int kk = 0; kk < 4; kk++) {
            uint32_t bf[8][2];
            const uint32_t kb = kbase + kvoff + kk*32;
            #pragma unroll
            for (int nt2 = 0; nt2 < 4; nt2++)
                ldm4(kb + nt2*16*QSTR*4,
                     bf[2*nt2][0], bf[2*nt2+1][0], bf[2*nt2][1], bf[2*nt2+1][1]);
            #pragma unroll
            for (int nt = 0; nt < 8; nt++)
                MMA_BF16(sacc[nt], qf[kk], bf[nt]);
        }

        // P = exp(S - 8); accumulate per-thread partial row sums
        #pragma unroll
        for (int nt = 0; nt < 8; nt++) {
            float p00 = __expf(sacc[nt][0] - 8.f);
            float p01 = __expf(sacc[nt][1] - 8.f);
            float p10 = __expf(sacc[nt][2] - 8.f);
            float p11 = __expf(sacc[nt][3] - 8.f);
            l0 += p00 + p01;  l1 += p10 + p11;
            Ps[rA*QSTR     + nt*4 + tig] = pack2bf(p00, p01);
            Ps[(rA+8)*QSTR + nt*4 + tig] = pack2bf(p10, p11);
        }
        __syncwarp();

        // O += P @ V
        #pragma unroll
        for (int kk = 0; kk < 4; kk++) {
            uint32_t af[4];
            ldm4(pbase + rowoff + kk*32, af[0], af[1], af[2], af[3]);
            uint32_t bf[8][2];
            const uint32_t vb = vbase + kvoff + kk*32;
            #pragma unroll
            for (int nt2 = 0; nt2 < 4; nt2++)
                ldm4(vb + nt2*16*QSTR*4,
                     bf[2*nt2][0], bf[2*nt2+1][0], bf[2*nt2][1], bf[2*nt2+1][1]);
            #pragma unroll
            for (int nt = 0; nt < 8; nt++)
                MMA_BF16(oacc[nt], af, bf[nt]);
        }
        __syncthreads();
    }

    // one-time row-sum reduction across the quad
    #pragma unroll
    for (int o = 1; o <= 2; o <<= 1) {
        l0 += __shfl_xor_sync(0xffffffffu, l0, o);
        l1 += __shfl_xor_sync(0xffffffffu, l1, o);
    }
    const float inv0 = 1.f / l0, inv1 = 1.f / l1;
    uint32_t* ow = (uint32_t*)g_attb;
    const size_t row = (size_t)b*NTOK + q0 + rA;
    #pragma unroll
    for (int nt = 0; nt < 8; nt++) {
        const int cw = hh*32 + nt*4 + tig;
        ow[row*256 + cw]     = pack2bf(oacc[nt][0]*inv0, oacc[nt][1]*inv0);
        ow[(row+8)*256 + cw] = pack2bf(oacc[nt][2]*inv1, oacc[nt][3]*inv1);
    }
}

// ---------------- final: out[b,c,n] = x + h^T ----------------
__global__ void k_final(const float* __restrict__ x, float* __restrict__ out) {
    __shared__ float th[32][33];
    const int b  = blockIdx.y;
    const int n0 = blockIdx.x * 32;
    const int tx = threadIdx.x, ty = threadIdx.y;
    for (int c0 = 0; c0 < CH; c0 += 32) {
        __syncthreads();
        th[ty][tx] = g_h[((size_t)b*NTOK + n0 + ty)*CH + c0 + tx];
        __syncthreads();
        const size_t oidx = ((size_t)b*CH + c0 + ty)*NTOK + n0 + tx;
        out[oidx] = x[oidx] + th[tx][ty];
    }
}

// ---------------- launcher ----------------
extern "C" void kernel_launch(void* const* d_in, const int* in_sizes, int n_in,
                              void* d_out, int out_size) {
    const float* x      = (const float*)d_in[0];
    const float* temb   = (const float*)d_in[1];
    const float* gn_w   = (const float*)d_in[2];
    const float* gn_b   = (const float*)d_in[3];
    const float* ada_w  = (const float*)d_in[4];
    const float* ada_b  = (const float*)d_in[5];
    const float* n1_w   = (const float*)d_in[6];
    const float* n2_w   = (const float*)d_in[7];
    const float* qkv_w  = (const float*)d_in[8];
    const float* qkv_b  = (const float*)d_in[9];
    const float* qn_w   = (const float*)d_in[10];
    const float* kn_w   = (const float*)d_in[11];
    const float* proj_w = (const float*)d_in[12];
    const float* proj_b = (const float*)d_in[13];
    const float* w12    = (const float*)d_in[14];
    const float* b12    = (const float*)d_in[15];
    const float* w_out  = (const float*)d_in[16];
    const float* b_out  = (const float*)d_in[17];
    float* out = (float*)d_out;

    float *p_h, *p_ada, *p_b12p;
    __nv_bfloat16 *p_hnb, *p_qkvb, *p_attb, *p_gateb;
    __nv_bfloat16 *p_wqkv, *p_wproj, *p_w12c, *p_woc;
    cudaGetSymbolAddress((void**)&p_h,     g_h);
    cudaGetSymbolAddress((void**)&p_ada,   g_ada);
    cudaGetSymbolAddress((void**)&p_b12p,  g_b12p);
    cudaGetSymbolAddress((void**)&p_hnb,   g_hnb);
    cudaGetSymbolAddress((void**)&p_qkvb,  g_qkvb);
    cudaGetSymbolAddress((void**)&p_attb,  g_attb);
    cudaGetSymbolAddress((void**)&p_gateb, g_gateb);
    cudaGetSymbolAddress((void**)&p_wqkv,  g_wqkv);
    cudaGetSymbolAddress((void**)&p_wproj, g_wproj);
    cudaGetSymbolAddress((void**)&p_w12c,  g_w12c);
    cudaGetSymbolAddress((void**)&p_woc,   g_woc);

    const int gemm_smem = 4*5120*4;          // 81920 B
    const int attn_smem = 384*QSTR*4;        // 55296 B
    cudaFuncSetAttribute(k_gemm,     cudaFuncAttributeMaxDynamicSharedMemorySize, gemm_smem);
    cudaFuncSetAttribute(k_attn_mma, cudaFuncAttributeMaxDynamicSharedMemorySize, attn_smem);

    // single merged weight conversion launch
    k_cvtall <<<(1048576 + FFN + 255)/256, 256>>>(qkv_w, proj_w, w_out, w12, b12);

    // adaLN + GroupNorm
    k_ada    <<<dim3(24, BDIM), 128>>>(temb, ada_w, ada_b);
    k_gnstats<<<BDIM*32, 256>>>(x);
    k_gnapply<<<dim3(NTOK/32, BDIM), dim3(32,32)>>>(x, gn_w, gn_b);

    // attention branch
    k_rmsmod <<<NT, 128>>>(n1_w, 0, 1);
    k_gemm   <<<dim3((3*CH)/128, NT/128), 256, gemm_smem>>>(
        p_hnb, p_wqkv, qkv_b, nullptr, (uint32_t*)p_qkvb, nullptr, p_ada, 0, 1, NT, 3*CH, CH);
    k_qkrope <<<(NT*NHEADS*32)/128, 128>>>(qn_w, kn_w);
    k_attn_mma<<<dim3(BDIM*NHEADS, NTOK/128), 256, attn_smem>>>();
    k_gemm   <<<dim3(CH/128, NT/128), 256, gemm_smem>>>(
        p_attb, p_wproj, proj_b, p_h, nullptr, nullptr, p_ada, 2, 2, NT, CH, CH);

    // FFN branch (swiglu fused into w12 epilogue via permuted weights)
    k_rmsmod <<<NT, 128>>>(n2_w, 3, 4);
    k_gemm   <<<dim3((2*FFN)/128, NT/128), 256, gemm_smem>>>(
        p_hnb, p_w12c, p_b12p, nullptr, nullptr, p_gateb, p_ada, 0, 3, NT, 2*FFN, CH);
    k_gemm   <<<dim3(CH/128, NT/128), 256, gemm_smem>>>(
        p_gateb, p_woc, b_out, p_h, nullptr, nullptr, p_ada, 5, 2, NT, CH, FFN);

    // epilogue
    k_final  <<<dim3(NTOK/32, BDIM), dim3(32,32)>>>(x, out);
}

// round 8
// speedup vs baseline: 5.5984x; 1.0317x over previous
#include <cuda_runtime.h>
#include <cuda_bf16.h>
#include <cstdint>

// ---------------- problem constants ----------------
#define BDIM   16
#define CH     512
#define NTOK   1024
#define NT     (BDIM*NTOK)
#define NHEADS 8
#define HDIM   64
#define FFN    2048
#define EPSV   1e-6f

// ---------------- scratch ----------------
__device__ float g_ada [BDIM*6*CH];
__device__ float g_h   [NT*CH];
__device__ float g_stats[BDIM*32*2];
__device__ float g_b12p[2*FFN];
__device__ __nv_bfloat16 g_hnb [NT*CH];
__device__ __nv_bfloat16 g_qkvb[NT*3*CH];
__device__ __nv_bfloat16 g_qkb [NT*2*CH];
__device__ __nv_bfloat16 g_vtb [BDIM*NHEADS*HDIM*NTOK];
__device__ __nv_bfloat16 g_attb[NT*CH];
__device__ __nv_bfloat16 g_gateb[NT*FFN];
__device__ __nv_bfloat16 g_wqkv [3*CH*CH];
__device__ __nv_bfloat16 g_wproj[CH*CH];
__device__ __nv_bfloat16 g_w12c [2*FFN*CH];
__device__ __nv_bfloat16 g_woc  [CH*FFN];

// ---------------- helpers ----------------
__device__ __forceinline__ uint32_t pack2bf(float lo, float hi) {
    uint32_t r;
    asm("cvt.rn.bf16x2.f32 %0, %1, %2;" : "=r"(r) : "f"(hi), "f"(lo));
    return r;
}
__device__ __forceinline__ void cpa16(void* s, const void* g) {
    uint32_t sa = (uint32_t)__cvta_generic_to_shared(s);
    asm volatile("cp.async.cg.shared.global [%0], [%1], 16;\n" :: "r"(sa), "l"(g));
}
__device__ __forceinline__ void ldm4(uint32_t addr, uint32_t& r0, uint32_t& r1,
                                     uint32_t& r2, uint32_t& r3) {
    asm volatile("ldmatrix.sync.aligned.m8n8.x4.shared.b16 {%0,%1,%2,%3}, [%4];"
                 : "=r"(r0), "=r"(r1), "=r"(r2), "=r"(r3) : "r"(addr));
}
#define MMA_BF16(d, a, b) \
    asm volatile("mma.sync.aligned.m16n8k16.row.col.f32.bf16.bf16.f32 " \
                 "{%0,%1,%2,%3}, {%4,%5,%6,%7}, {%8,%9}, {%0,%1,%2,%3};" \
                 : "+f"(d[0]), "+f"(d[1]), "+f"(d[2]), "+f"(d[3]) \
                 : "r"(a[0]), "r"(a[1]), "r"(a[2]), "r"(a[3]), "r"(b[0]), "r"(b[1]))

// ---------------- merged weight conversion ----------------
__device__ __forceinline__ void cvt4(const float* __restrict__ s,
                                     __nv_bfloat16* __restrict__ d, int i) {
    float4 v = *(const float4*)(s + i);
    *(uint32_t*)(d + i)     = pack2bf(v.x, v.y);
    *(uint32_t*)(d + i + 2) = pack2bf(v.z, v.w);
}
__global__ void k_cvtall(const float* __restrict__ qkv_w, const float* __restrict__ proj_w,
                         const float* __restrict__ w_out, const float* __restrict__ w12,
                         const float* __restrict__ b12) {
    const int gi = blockIdx.x * blockDim.x + threadIdx.x;
    if (gi < 196608) {
        cvt4(qkv_w, g_wqkv, gi * 4);
    } else if (gi < 262144) {
        cvt4(proj_w, g_wproj, (gi - 196608) * 4);
    } else if (gi < 524288) {
        cvt4(w_out, g_woc, (gi - 262144) * 4);
    } else if (gi < 1048576) {
        const int i = (gi - 524288) * 4;
        const int r = i >> 9;
        const int k = i & (CH - 1);
        const int sr = (r & 1) ? (FFN + (r >> 1)) : (r >> 1);
        float4 v = *(const float4*)(w12 + (size_t)sr*CH + k);
        *(uint32_t*)(g_w12c + i)     = pack2bf(v.x, v.y);
        *(uint32_t*)(g_w12c + i + 2) = pack2bf(v.z, v.w);
    } else if (gi < 1048576 + FFN) {
        const int j = gi - 1048576;
        g_b12p[2*j]   = b12[j];
        g_b12p[2*j+1] = b12[FFN + j];
    }
}

// ---------------- adaLN ----------------
__global__ void k_ada(const float* __restrict__ temb, const float* __restrict__ ada_w,
                      const float* __restrict__ ada_b) {
    __shared__ float s[CH];
    const int b = blockIdx.y;
    for (int i = threadIdx.x; i < CH; i += blockDim.x) {
        float v = temb[b*CH + i];
        s[i] = v / (1.f + __expf(-v));
    }
    __syncthreads();
    const int n = blockIdx.x * blockDim.x + threadIdx.x;
    const float* wr = ada_w + (size_t)n * CH;
    float acc = 0.f;
    #pragma unroll 8
    for (int k = 0; k < CH; k++) acc += wr[k] * s[k];
    g_ada[b*6*CH + n] = acc + ada_b[n];
}

// ---------------- GroupNorm stats ----------------
__global__ void k_gnstats(const float* __restrict__ x) {
    const int bg = blockIdx.x;
    const float* p = x + (size_t)bg * 16 * NTOK;
    float s = 0.f, s2 = 0.f;
    for (int i = threadIdx.x; i < 16*NTOK; i += blockDim.x) {
        float v = p[i]; s += v; s2 += v*v;
    }
    #pragma unroll
    for (int o = 16; o; o >>= 1) {
        s  += __shfl_xor_sync(0xffffffffu, s,  o);
        s2 += __shfl_xor_sync(0xffffffffu, s2, o);
    }
    __shared__ float sh[64];
    const int w = threadIdx.x >> 5, l = threadIdx.x & 31;
    if (l == 0) { sh[w] = s; sh[32 + w] = s2; }
    __syncthreads();
    if (threadIdx.x < 32) {
        const int nw = blockDim.x >> 5;
        s  = (threadIdx.x < nw) ? sh[threadIdx.x]      : 0.f;
        s2 = (threadIdx.x < nw) ? sh[32 + threadIdx.x] : 0.f;
        #pragma unroll
        for (int o = 16; o; o >>= 1) {
            s  += __shfl_xor_sync(0xffffffffu, s,  o);
            s2 += __shfl_xor_sync(0xffffffffu, s2, o);
        }
        if (threadIdx.x == 0) {
            const float inv = 1.f / (16.f * NTOK);
            float mu  = s * inv;
            float var = s2 * inv - mu * mu;
            g_stats[bg*2]     = mu;
            g_stats[bg*2 + 1] = rsqrtf(var + EPSV);
        }
    }
}

// ---------------- fused GroupNorm-apply + transpose + RMSNorm(n1) + mod ----------------
// one block = 32 tokens; h strip (32 x 512) staged in smem (stride 513: conflict-free)
#define HSTR 513
__global__ __launch_bounds__(256) void k_gnrms(
    const float* __restrict__ x, const float* __restrict__ gw, const float* __restrict__ gb,
    const float* __restrict__ n1w) {
    extern __shared__ float hb[];            // 32*HSTR + 32
    float* rms = hb + 32*HSTR;
    const int b  = blockIdx.y;
    const int n0 = blockIdx.x * 32;
    const int t  = threadIdx.x;
    // phase 1: gather x (transposed) + groupnorm into smem
    for (int c0 = 0; c0 < CH; c0 += 32) {
        #pragma unroll
        for (int i = 0; i < 4; i++) {
            const int cl = (t >> 5) + i*8;   // 0..31
            const int nl = t & 31;
            const int c  = c0 + cl;
            const float mu = g_stats[(b*32 + (c >> 4))*2];
            const float rs = g_stats[(b*32 + (c >> 4))*2 + 1];
            const float v  = x[((size_t)b*CH + c)*NTOK + n0 + nl];
            hb[nl*HSTR + c] = (v - mu) * rs * gw[c] + gb[c];
        }
    }
    __syncthreads();
    // phase 2: per-token sum of squares (8 threads per token)
    {
        const int tok = t >> 3, l8 = t & 7;
        float ss = 0.f;
        #pragma unroll 8
        for (int i = 0; i < 64; i++) {
            const float v = hb[tok*HSTR + l8 + i*8];
            ss += v*v;
        }
        #pragma unroll
        for (int o = 1; o <= 4; o <<= 1) ss += __shfl_xor_sync(0xffffffffu, ss, o);
        if (l8 == 0) rms[tok] = rsqrtf(ss / (float)CH + EPSV);
    }
    __syncthreads();
    // phase 3: coalesced writes of g_h (fp32) and g_hnb (bf16)
    const int rowb = b*NTOK + n0;
    const float* shf = g_ada + b*6*CH;           // shift = chunk 0
    const float* scl = g_ada + b*6*CH + CH;      // scale = chunk 1
    #pragma unroll 4
    for (int i = 0; i < 32; i++) {
        const int idx = (t + i*256) * 2;         // over 16384 elems, 2 per thread
        const int tk = idx >> 9, c = idx & 511;
        const float h0 = hb[tk*HSTR + c], h1 = hb[tk*HSTR + c + 1];
        const float r = rms[tk];
        *(float2*)(g_h + (size_t)(rowb + tk)*CH + c) = make_float2(h0, h1);
        const float o0 = h0 * r * n1w[c]   * (1.f + scl[c])   + shf[c];
        const float o1 = h1 * r * n1w[c+1] * (1.f + scl[c+1]) + shf[c+1];
        *(uint32_t*)(g_hnb + (size_t)(rowb + tk)*CH + c) = pack2bf(o0, o1);
    }
}

// ---------------- RMSNorm + modulation -> bf16 (n2 path) ----------------
__global__ void k_rmsmod(const float* __restrict__ w, int shift_ch, int scale_ch) {
    const int row = blockIdx.x;
    const int b = row >> 10;
    const float* hp = g_h + (size_t)row * CH;
    const int t = threadIdx.x;
    float4 v = *(const float4*)(hp + t*4);
    float ss = v.x*v.x + v.y*v.y + v.z*v.z + v.w*v.w;
    #pragma unroll
    for (int o = 16; o; o >>= 1) ss += __shfl_xor_sync(0xffffffffu, ss, o);
    __shared__ float sh[4];
    if ((t & 31) == 0) sh[t >> 5] = ss;
    __syncthreads();
    ss = sh[0] + sh[1] + sh[2] + sh[3];
    const float r = rsqrtf(ss / (float)CH + EPSV);
    const float* shf = g_ada + b*6*CH + shift_ch*CH;
    const float* scl = g_ada + b*6*CH + scale_ch*CH;
    const int c = t*4;
    float o0 = v.x * r * w[c+0] * (1.f + scl[c+0]) + shf[c+0];
    float o1 = v.y * r * w[c+1] * (1.f + scl[c+1]) + shf[c+1];
    float o2 = v.z * r * w[c+2] * (1.f + scl[c+2]) + shf[c+2];
    float o3 = v.w * r * w[c+3] * (1.f + scl[c+3]) + shf[c+3];
    uint32_t* dp = (uint32_t*)(g_hnb + (size_t)row*CH + c);
    dp[0] = pack2bf(o0, o1);
    dp[1] = pack2bf(o2, o3);
}

// ---------------- BF16 GEMM, ldmatrix, 4-stage cp.async, 2 CTAs/SM ----------------
#define WSTR 20
__global__ __launch_bounds__(256, 2) void k_gemm(
    const __nv_bfloat16* __restrict__ A, const __nv_bfloat16* __restrict__ W,
    const float* __restrict__ bias, float* __restrict__ Cf, uint32_t* __restrict__ Cb,
    __nv_bfloat16* __restrict__ Gb, const float* __restrict__ ada,
    int gch, int mode, int M, int N, int K)
{
    extern __shared__ uint32_t sm[];
    const int tid  = threadIdx.x;
    const int lane = tid & 31;
    const int warp = tid >> 5;
    const int gid  = lane >> 2;
    const int tig  = lane & 3;
    const int row0 = (warp & 3) * 32;
    const int col0 = (warp >> 2) * 64;
    const int bm = blockIdx.y * 128, bn = blockIdx.x * 128;
    const int KT = K >> 5;
    const int lr   = lane & 7;
    const int sel8 = (lane >> 3) & 1;
    const int sel4 = (lane >> 4) & 1;

    const uint32_t sbase = (uint32_t)__cvta_generic_to_shared(sm);
    const uint32_t aoff  = ((row0 + sel8*8 + lr)*WSTR + sel4*4) * 4;
    const uint32_t boff  = ((col0 + sel8*8 + lr)*WSTR + sel4*4) * 4 + 2560*4;

    auto load_body = [&](int kt, int s) {
        uint32_t* As = sm + s * 5120;
        uint32_t* Ws = As + 2560;
        const int k0 = kt << 5;
        #pragma unroll
        for (int i = 0; i < 2; i++) {
            const int lin = tid + i*256;
            const int r = lin >> 2, c4 = lin & 3;
            cpa16(As + r*WSTR + c4*4, A + (size_t)(bm + r)*K + k0 + c4*8);
            cpa16(Ws + r*WSTR + c4*4, W + (size_t)(bn + r)*K + k0 + c4*8);
        }
    };

    load_body(0, 0);
    asm volatile("cp.async.commit_group;\n");
    load_body(1, 1);
    asm volatile("cp.async.commit_group;\n");
    load_body(2, 2);
    asm volatile("cp.async.commit_group;\n");

    float acc[2][8][4];
    #pragma unroll
    for (int i = 0; i < 2; i++)
        #pragma unroll
        for (int j = 0; j < 8; j++)
            #pragma unroll
            for (int c = 0; c < 4; c++) acc[i][j][c] = 0.f;

    for (int kt = 0; kt < KT; kt++) {
        asm volatile("cp.async.wait_group 2;\n");
        __syncthreads();
        if (kt + 3 < KT) load_body(kt + 3, (kt + 3) & 3);
        asm volatile("cp.async.commit_group;\n");

        const uint32_t stb = sbase + (uint32_t)((kt & 3) * 5120 * 4);
        #pragma unroll
        for (int kk = 0; kk < 2; kk++) {
            const uint32_t kb = kk * 32;
            uint32_t af[2][4], bf[8][2];
            const uint32_t aa = stb + aoff + kb;
            ldm4(aa,             af[0][0], af[0][1], af[0][2], af[0][3]);
            ldm4(aa + 16*WSTR*4, af[1][0], af[1][1], af[1][2], af[1][3]);
            const uint32_t bb = stb + boff + kb;
            #pragma unroll
            for (int nt2 = 0; nt2 < 4; nt2++) {
                ldm4(bb + nt2*16*WSTR*4,
                     bf[2*nt2][0], bf[2*nt2+1][0], bf[2*nt2][1], bf[2*nt2+1][1]);
            }
            #pragma unroll
            for (int mt = 0; mt < 2; mt++)
                #pragma unroll
                for (int nt = 0; nt < 8; nt++)
                    MMA_BF16(acc[mt][nt], af[mt], bf[nt]);
        }
    }

    #pragma unroll
    for (int mt = 0; mt < 2; mt++) {
        const int row = bm + row0 + mt*16 + gid;
        const int b   = row >> 10;
        const float* gp = ada + b*6*CH + gch*CH;
        #pragma unroll
        for (int nt = 0; nt < 8; nt++) {
            const int col = bn + col0 + nt*8 + tig*2;
            const float b0 = bias[col], b1 = bias[col+1];
            float v00 = acc[mt][nt][0] + b0, v01 = acc[mt][nt][1] + b1;
            float v10 = acc[mt][nt][2] + b0, v11 = acc[mt][nt][3] + b1;
            if (mode == 1) {
                Cb[((size_t)row*N + col) >> 1]     = pack2bf(v00, v01);
                Cb[((size_t)(row+8)*N + col) >> 1] = pack2bf(v10, v11);
            } else if (mode == 2) {
                const float gg0 = gp[col], gg1 = gp[col+1];
                float2 h0 = *(float2*)(Cf + (size_t)row*N + col);
                float2 h1 = *(float2*)(Cf + (size_t)(row+8)*N + col);
                h0.x += gg0*v00; h0.y += gg1*v01;
                h1.x += gg0*v10; h1.y += gg1*v11;
                *(float2*)(Cf + (size_t)row*N + col)     = h0;
                *(float2*)(Cf + (size_t)(row+8)*N + col) = h1;
            } else {
                const int j = col >> 1;
                const float s0 = (v00 / (1.f + __expf(-v00))) * v01;
                const float s1 = (v10 / (1.f + __expf(-v10))) * v11;
                Gb[(size_t)row*(N>>1) + j]     = __float2bfloat16(s0);
                Gb[(size_t)(row+8)*(N>>1) + j] = __float2bfloat16(s1);
            }
        }
    }
}

// ---------------- q/k RMSNorm + RoPE (bf16 in) -> bf16; V -> transposed bf16 ----------------
__global__ void k_qkrope(const float* __restrict__ qn_w, const float* __restrict__ kn_w) {
    const int gw   = (blockIdx.x * blockDim.x + threadIdx.x) >> 5;
    const int lane = threadIdx.x & 31;
    const int head = gw & 7;
    const int tok  = gw >> 3;
    const int b = tok >> 10;
    const int n = tok & 1023;
    const int rrow = n >> 5, rcol = n & 31;
    const uint32_t* qkvw = (const uint32_t*)g_qkvb;
    const size_t base = (size_t)tok * 768;
    float2 qv = __bfloat1622float2(*(const __nv_bfloat162*)&qkvw[base + head*32 + lane]);
    float2 kv = __bfloat1622float2(*(const __nv_bfloat162*)&qkvw[base + 256 + head*32 + lane]);
    float2 vv = __bfloat1622float2(*(const __nv_bfloat162*)&qkvw[base + 512 + head*32 + lane]);
    float q0 = qv.x, q1 = qv.y, k0 = kv.x, k1 = kv.y;
    const int j = lane * 2;
    float sq = q0*q0 + q1*q1, sk = k0*k0 + k1*k1;
    #pragma unroll
    for (int o = 16; o; o >>= 1) {
        sq += __shfl_xor_sync(0xffffffffu, sq, o);
        sk += __shfl_xor_sync(0xffffffffu, sk, o);
    }
    const float rq = rsqrtf(sq / 64.f + EPSV);
    const float rk = rsqrtf(sk / 64.f + EPSV);
    q0 *= rq * qn_w[j];  q1 *= rq * qn_w[j+1];
    k0 *= rk * kn_w[j];  k1 *= rk * kn_w[j+1];
    const int half = (j >= 32);
    const int idx  = (half ? (j - 32) : j) >> 1;
    const float freq = exp2f(-(float)idx * (13.287712379549449f / 16.f));
    const float f = (half ? (float)rcol : (float)rrow) * freq;
    const float cf = cosf(f), sf = sinf(f);
    const float qa = q0*cf - q1*sf, qb = q1*cf + q0*sf;
    const float ka = k0*cf - k1*sf, kb = k1*cf + k0*sf;
    const float qs = 0.125f;
    uint32_t* qkw = (uint32_t*)g_qkb;
    qkw[(size_t)tok*512 + head*32 + lane]       = pack2bf(qa*qs, qb*qs);
    qkw[(size_t)tok*512 + 256 + head*32 + lane] = pack2bf(ka, kb);
    const int bh = b*8 + head;
    g_vtb[((size_t)bh*64 + j)  *NTOK + n] = __float2bfloat16(vv.x);
    g_vtb[((size_t)bh*64 + j+1)*NTOK + n] = __float2bfloat16(vv.y);
}

// ---------------- flash attention: P stays in registers (D->A fragment identity) ----------------
#define QSTR 36
__global__ __launch_bounds__(256) void k_attn_mma() {
    extern __shared__ uint32_t smw[];        // 2 stages x 128 rows x QSTR
    const int bh = blockIdx.x;
    const int b = bh >> 3, hh = bh & 7;
    const int q0 = blockIdx.y * 128;
    const int tid = threadIdx.x, lane = tid & 31, warp = tid >> 5;
    const int lr = lane & 7, sel8 = (lane >> 3) & 1, sel4 = (lane >> 4) & 1;
    const int gid = lane >> 2, tig = lane & 3;
    const __nv_bfloat16* qk = g_qkb + (size_t)b * NTOK * 1024;
    const __nv_bfloat16* vt = g_vtb + (size_t)bh * 64 * NTOK;

    const uint32_t sbase = (uint32_t)__cvta_generic_to_shared(smw);
    const uint32_t qoff  = ((warp*16 + sel8*8 + lr)*QSTR + sel4*4) * 4;
    const uint32_t kvoff = ((sel8*8 + lr)*QSTR + sel4*4) * 4;

    // stage Q into stage-0 region, grab fragments, then release
    #pragma unroll
    for (int i = 0; i < 4; i++) {
        const int lin = tid + i*256;
        const int r = lin >> 3, c4 = lin & 7;
        cpa16(smw + r*QSTR + c4*4, qk + (size_t)(q0 + r)*1024 + hh*64 + c4*8);
    }
    asm volatile("cp.async.commit_group;\n");
    asm volatile("cp.async.wait_group 0;\n");
    __syncthreads();
    uint32_t qf[4][4];
    #pragma unroll
    for (int kk = 0; kk < 4; kk++)
        ldm4(sbase + qoff + kk*32, qf[kk][0], qf[kk][1], qf[kk][2], qf[kk][3]);
    __syncthreads();

    auto load_kv = [&](int kc, int s) {
        uint32_t* Ks = smw + s*128*QSTR;
        uint32_t* Vs = Ks + 64*QSTR;
        #pragma unroll
        for (int i = 0; i < 2; i++) {
            const int lin = tid + i*256;
            const int r = lin >> 3, c4 = lin & 7;
            cpa16(Ks + r*QSTR + c4*4, qk + (size_t)(kc + r)*1024 + 512 + hh*64 + c4*8);
            cpa16(Vs + r*QSTR + c4*4, vt + (size_t)r*NTOK + kc + c4*8);
        }
    };

    float l0 = 0.f, l1 = 0.f;
    float oacc[8][4];
    #pragma unroll
    for (int nt = 0; nt < 8; nt++)
        #pragma unroll
        for (int c = 0; c < 4; c++) oacc[nt][c] = 0.f;

    load_kv(0, 0);
    asm volatile("cp.async.commit_group;\n");

    for (int it = 0; it < NTOK/64; it++) {
        const int s = it & 1;
        if (it + 1 < NTOK/64) {
            load_kv((it+1)*64, s ^ 1);
            asm volatile("cp.async.commit_group;\n");
            asm volatile("cp.async.wait_group 1;\n");
        } else {
            asm volatile("cp.async.wait_group 0;\n");
        }
        __syncthreads();
        const uint32_t kbase = sbase + (uint32_t)(s*128*QSTR*4);
        const uint32_t vbase = kbase + 64*QSTR*4;

        // S = Q @ K^T
        float sacc[8][4];
        #pragma unroll
        for (int nt = 0; nt < 8; nt++)
            #pragma unroll
            for (int c = 0; c < 4; c++) sacc[nt][c] = 0.f;
        #pragma unroll
        for (int kk = 0; kk < 4; kk++) {
            uint32_t bf[8][2];
            const uint32_t kb = kbase + kvoff + kk*32;
            #pragma unroll
            for (int nt2 = 0; nt2 < 4; nt2++)
                ldm4(kb + nt2*16*QSTR*4,
                     bf[2*nt2][0], bf[2*nt2+1][0], bf[2*nt2][1], bf[2*nt2+1][1]);
            #pragma unroll
            for (int nt = 0; nt < 8; nt++)
                MMA_BF16(sacc[nt], qf[kk], bf[nt]);
        }

        // P = exp(S - 8) packed straight into A-fragment registers
        uint32_t pa[8], pb[8];
        #pragma unroll
        for (int nt = 0; nt < 8; nt++) {
            const float p00 = __expf(sacc[nt][0] - 8.f);
            const float p01 = __expf(sacc[nt][1] - 8.f);
            const float p10 = __expf(sacc[nt][2] - 8.f);
            const float p11 = __expf(sacc[nt][3] - 8.f);
            l0 += p00 + p01;  l1 += p10 + p11;
            pa[nt] = pack2bf(p00, p01);
            pb[nt] = pack2bf(p10, p11);
        }

        // O += P @ V  (A fragment = {pa[2kk], pb[2kk], pa[2kk+1], pb[2kk+1]})
        #pragma unroll
        for (int kk = 0; kk < 4; kk++) {
            uint32_t af[4] = { pa[2*kk], pb[2*kk], pa[2*kk+1], pb[2*kk+1] };
            uint32_t bf[8][2];
            const uint32_t vb = vbase + kvoff + kk*32;
            #pragma unroll
            for (int nt2 = 0; nt2 < 4; nt2++)
                ldm4(vb + nt2*16*QSTR*4,
                     bf[2*nt2][0], bf[2*nt2+1][0], bf[2*nt2][1], bf[2*nt2+1][1]);
            #pragma unroll
            for (int nt = 0; nt < 8; nt++)
                MMA_BF16(oacc[nt], af, bf[nt]);
        }
        __syncthreads();
    }

    #pragma unroll
    for (int o = 1; o <= 2; o <<= 1) {
        l0 += __shfl_xor_sync(0xffffffffu, l0, o);
        l1 += __shfl_xor_sync(0xffffffffu, l1, o);
    }
    const float inv0 = 1.f / l0, inv1 = 1.f / l1;
    uint32_t* ow = (uint32_t*)g_attb;
    const size_t row = (size_t)b*NTOK + q0 + warp*16 + gid;
    #pragma unroll
    for (int nt = 0; nt < 8; nt++) {
        const int cw = hh*32 + nt*4 + tig;
        ow[row*256 + cw]     = pack2bf(oacc[nt][0]*inv0, oacc[nt][1]*inv0);
        ow[(row+8)*256 + cw] = pack2bf(oacc[nt][2]*inv1, oacc[nt][3]*inv1);
    }
}

// ---------------- final: out[b,c,n] = x + h^T ----------------
__global__ void k_final(const float* __restrict__ x, float* __restrict__ out) {
    __shared__ float th[32][33];
    const int b  = blockIdx.y;
    const int n0 = blockIdx.x * 32;
    const int tx = threadIdx.x, ty = threadIdx.y;
    for (int c0 = 0; c0 < CH; c0 += 32) {
        __syncthreads();
        th[ty][tx] = g_h[((size_t)b*NTOK + n0 + ty)*CH + c0 + tx];
        __syncthreads();
        const size_t oidx = ((size_t)b*CH + c0 + ty)*NTOK + n0 + tx;
        out[oidx] = x[oidx] + th[tx][ty];
    }
}

// ---------------- launcher ----------------
extern "C" void kernel_launch(void* const* d_in, const int* in_sizes, int n_in,
                              void* d_out, int out_size) {
    const float* x      = (const float*)d_in[0];
    const float* temb   = (const float*)d_in[1];
    const float* gn_w   = (const float*)d_in[2];
    const float* gn_b   = (const float*)d_in[3];
    const float* ada_w  = (const float*)d_in[4];
    const float* ada_b  = (const float*)d_in[5];
    const float* n1_w   = (const float*)d_in[6];
    const float* n2_w   = (const float*)d_in[7];
    const float* qkv_w  = (const float*)d_in[8];
    const float* qkv_b  = (const float*)d_in[9];
    const float* qn_w   = (const float*)d_in[10];
    const float* kn_w   = (const float*)d_in[11];
    const float* proj_w = (const float*)d_in[12];
    const float* proj_b = (const float*)d_in[13];
    const float* w12    = (const float*)d_in[14];
    const float* b12    = (const float*)d_in[15];
    const float* w_out  = (const float*)d_in[16];
    const float* b_out  = (const float*)d_in[17];
    float* out = (float*)d_out;

    float *p_h, *p_ada, *p_b12p;
    __nv_bfloat16 *p_hnb, *p_qkvb, *p_attb, *p_gateb;
    __nv_bfloat16 *p_wqkv, *p_wproj, *p_w12c, *p_woc;
    cudaGetSymbolAddress((void**)&p_h,     g_h);
    cudaGetSymbolAddress((void**)&p_ada,   g_ada);
    cudaGetSymbolAddress((void**)&p_b12p,  g_b12p);
    cudaGetSymbolAddress((void**)&p_hnb,   g_hnb);
    cudaGetSymbolAddress((void**)&p_qkvb,  g_qkvb);
    cudaGetSymbolAddress((void**)&p_attb,  g_attb);
    cudaGetSymbolAddress((void**)&p_gateb, g_gateb);
    cudaGetSymbolAddress((void**)&p_wqkv,  g_wqkv);
    cudaGetSymbolAddress((void**)&p_wproj, g_wproj);
    cudaGetSymbolAddress((void**)&p_w12c,  g_w12c);
    cudaGetSymbolAddress((void**)&p_woc,   g_woc);

    const int gemm_smem  = 4*5120*4;          // 81920 B
    const int attn_smem  = 256*QSTR*4;        // 36864 B
    const int gnrms_smem = (32*HSTR + 32)*4;  // 65792 B
    cudaFuncSetAttribute(k_gemm,     cudaFuncAttributeMaxDynamicSharedMemorySize, gemm_smem);
    cudaFuncSetAttribute(k_attn_mma, cudaFuncAttributeMaxDynamicSharedMemorySize, attn_smem);
    cudaFuncSetAttribute(k_gnrms,    cudaFuncAttributeMaxDynamicSharedMemorySize, gnrms_smem);

    k_cvtall <<<(1048576 + FFN + 255)/256, 256>>>(qkv_w, proj_w, w_out, w12, b12);

    // adaLN + GroupNorm (+ fused rmsnorm/mod for attention branch)
    k_ada    <<<dim3(24, BDIM), 128>>>(temb, ada_w, ada_b);
    k_gnstats<<<BDIM*32, 256>>>(x);
    k_gnrms  <<<dim3(NTOK/32, BDIM), 256, gnrms_smem>>>(x, gn_w, gn_b, n1_w);

    // attention branch
    k_gemm   <<<dim3((3*CH)/128, NT/128), 256, gemm_smem>>>(
        p_hnb, p_wqkv, qkv_b, nullptr, (uint32_t*)p_qkvb, nullptr, p_ada, 0, 1, NT, 3*CH, CH);
    k_qkrope <<<(NT*NHEADS*32)/128, 128>>>(qn_w, kn_w);
    k_attn_mma<<<dim3(BDIM*NHEADS, NTOK/128), 256, attn_smem>>>();
    k_gemm   <<<dim3(CH/128, NT/128), 256, gemm_smem>>>(
        p_attb, p_wproj, proj_b, p_h, nullptr, nullptr, p_ada, 2, 2, NT, CH, CH);

    // FFN branch
    k_rmsmod <<<NT, 128>>>(n2_w, 3, 4);
    k_gemm   <<<dim3((2*FFN)/128, NT/128), 256, gemm_smem>>>(
        p_hnb, p_w12c, p_b12p, nullptr, nullptr, p_gateb, p_ada, 0, 3, NT, 2*FFN, CH);
    k_gemm   <<<dim3(CH/128, NT/128), 256, gemm_smem>>>(
        p_gateb, p_woc, b_out, p_h, nullptr, nullptr, p_ada, 5, 2, NT, CH, FFN);

    // epilogue
    k_final  <<<dim3(NTOK/32, BDIM), dim3(32,32)>>>(x, out);
}

// round 9
// speedup vs baseline: 5.9898x; 1.0699x over previous
#include <cuda_runtime.h>
#include <cuda_bf16.h>
#include <cstdint>

// ---------------- problem constants ----------------
#define BDIM   16
#define CH     512
#define NTOK   1024
#define NT     (BDIM*NTOK)
#define NHEADS 8
#define HDIM   64
#define FFN    2048
#define EPSV   1e-6f

// ---------------- scratch ----------------
__device__ float g_ada [BDIM*6*CH];
__device__ float g_h   [NT*CH];
__device__ float g_stats[BDIM*32*2];
__device__ float g_b12p[2*FFN];
__device__ __nv_bfloat16 g_hnb [NT*CH];
__device__ __nv_bfloat16 g_qkvb[NT*3*CH];
__device__ __nv_bfloat16 g_qkb [NT*2*CH];
__device__ __nv_bfloat16 g_vtb [BDIM*NHEADS*HDIM*NTOK];
__device__ __nv_bfloat16 g_attb[NT*CH];
__device__ __nv_bfloat16 g_gateb[NT*FFN];
__device__ __nv_bfloat16 g_wqkv [3*CH*CH];
__device__ __nv_bfloat16 g_wproj[CH*CH];
__device__ __nv_bfloat16 g_w12c [2*FFN*CH];
__device__ __nv_bfloat16 g_woc  [CH*FFN];

// ---------------- helpers ----------------
__device__ __forceinline__ uint32_t pack2bf(float lo, float hi) {
    uint32_t r;
    asm("cvt.rn.bf16x2.f32 %0, %1, %2;" : "=r"(r) : "f"(hi), "f"(lo));
    return r;
}
__device__ __forceinline__ void cpa16(void* s, const void* g) {
    uint32_t sa = (uint32_t)__cvta_generic_to_shared(s);
    asm volatile("cp.async.cg.shared.global [%0], [%1], 16;\n" :: "r"(sa), "l"(g));
}
__device__ __forceinline__ void ldm4(uint32_t addr, uint32_t& r0, uint32_t& r1,
                                     uint32_t& r2, uint32_t& r3) {
    asm volatile("ldmatrix.sync.aligned.m8n8.x4.shared.b16 {%0,%1,%2,%3}, [%4];"
                 : "=r"(r0), "=r"(r1), "=r"(r2), "=r"(r3) : "r"(addr));
}
#define MMA_BF16(d, a, b) \
    asm volatile("mma.sync.aligned.m16n8k16.row.col.f32.bf16.bf16.f32 " \
                 "{%0,%1,%2,%3}, {%4,%5,%6,%7}, {%8,%9}, {%0,%1,%2,%3};" \
                 : "+f"(d[0]), "+f"(d[1]), "+f"(d[2]), "+f"(d[3]) \
                 : "r"(a[0]), "r"(a[1]), "r"(a[2]), "r"(a[3]), "r"(b[0]), "r"(b[1]))

// ---------------- merged weight conversion ----------------
__device__ __forceinline__ void cvt4(const float* __restrict__ s,
                                     __nv_bfloat16* __restrict__ d, int i) {
    float4 v = *(const float4*)(s + i);
    *(uint32_t*)(d + i)     = pack2bf(v.x, v.y);
    *(uint32_t*)(d + i + 2) = pack2bf(v.z, v.w);
}
__global__ void k_cvtall(const float* __restrict__ qkv_w, const float* __restrict__ proj_w,
                         const float* __restrict__ w_out, const float* __restrict__ w12,
                         const float* __restrict__ b12) {
    const int gi = blockIdx.x * blockDim.x + threadIdx.x;
    if (gi < 196608) {
        cvt4(qkv_w, g_wqkv, gi * 4);
    } else if (gi < 262144) {
        cvt4(proj_w, g_wproj, (gi - 196608) * 4);
    } else if (gi < 524288) {
        cvt4(w_out, g_woc, (gi - 262144) * 4);
    } else if (gi < 1048576) {
        const int i = (gi - 524288) * 4;
        const int r = i >> 9;
        const int k = i & (CH - 1);
        const int sr = (r & 1) ? (FFN + (r >> 1)) : (r >> 1);
        float4 v = *(const float4*)(w12 + (size_t)sr*CH + k);
        *(uint32_t*)(g_w12c + i)     = pack2bf(v.x, v.y);
        *(uint32_t*)(g_w12c + i + 2) = pack2bf(v.z, v.w);
    } else if (gi < 1048576 + FFN) {
        const int j = gi - 1048576;
        g_b12p[2*j]   = b12[j];
        g_b12p[2*j+1] = b12[FFN + j];
    }
}

// ---------------- adaLN ----------------
__global__ void k_ada(const float* __restrict__ temb, const float* __restrict__ ada_w,
                      const float* __restrict__ ada_b) {
    __shared__ float s[CH];
    const int b = blockIdx.y;
    for (int i = threadIdx.x; i < CH; i += blockDim.x) {
        float v = temb[b*CH + i];
        s[i] = v / (1.f + __expf(-v));
    }
    __syncthreads();
    const int n = blockIdx.x * blockDim.x + threadIdx.x;
    const float* wr = ada_w + (size_t)n * CH;
    float acc = 0.f;
    #pragma unroll 8
    for (int k = 0; k < CH; k++) acc += wr[k] * s[k];
    g_ada[b*6*CH + n] = acc + ada_b[n];
}

// ---------------- GroupNorm stats ----------------
__global__ void k_gnstats(const float* __restrict__ x) {
    const int bg = blockIdx.x;
    const float* p = x + (size_t)bg * 16 * NTOK;
    float s = 0.f, s2 = 0.f;
    for (int i = threadIdx.x; i < 16*NTOK; i += blockDim.x) {
        float v = p[i]; s += v; s2 += v*v;
    }
    #pragma unroll
    for (int o = 16; o; o >>= 1) {
        s  += __shfl_xor_sync(0xffffffffu, s,  o);
        s2 += __shfl_xor_sync(0xffffffffu, s2, o);
    }
    __shared__ float sh[64];
    const int w = threadIdx.x >> 5, l = threadIdx.x & 31;
    if (l == 0) { sh[w] = s; sh[32 + w] = s2; }
    __syncthreads();
    if (threadIdx.x < 32) {
        const int nw = blockDim.x >> 5;
        s  = (threadIdx.x < nw) ? sh[threadIdx.x]      : 0.f;
        s2 = (threadIdx.x < nw) ? sh[32 + threadIdx.x] : 0.f;
        #pragma unroll
        for (int o = 16; o; o >>= 1) {
            s  += __shfl_xor_sync(0xffffffffu, s,  o);
            s2 += __shfl_xor_sync(0xffffffffu, s2, o);
        }
        if (threadIdx.x == 0) {
            const float inv = 1.f / (16.f * NTOK);
            float mu  = s * inv;
            float var = s2 * inv - mu * mu;
            g_stats[bg*2]     = mu;
            g_stats[bg*2 + 1] = rsqrtf(var + EPSV);
        }
    }
}

// ---------------- fused GroupNorm-apply + transpose + RMSNorm(n1) + mod ----------------
// one block = 32 tokens, 512 threads
#define HSTR 513
__global__ __launch_bounds__(512) void k_gnrms(
    const float* __restrict__ x, const float* __restrict__ gw, const float* __restrict__ gb,
    const float* __restrict__ n1w) {
    extern __shared__ float hb[];            // 32*HSTR + 32
    float* rms = hb + 32*HSTR;
    const int b  = blockIdx.y;
    const int n0 = blockIdx.x * 32;
    const int t  = threadIdx.x;
    // phase 1: gather x (transposed) + groupnorm into smem
    for (int c0 = 0; c0 < CH; c0 += 64) {
        #pragma unroll
        for (int i = 0; i < 4; i++) {
            const int cl = (t >> 5) + i*16;  // 0..63
            const int nl = t & 31;
            const int c  = c0 + cl;
            const float mu = g_stats[(b*32 + (c >> 4))*2];
            const float rs = g_stats[(b*32 + (c >> 4))*2 + 1];
            const float v  = x[((size_t)b*CH + c)*NTOK + n0 + nl];
            hb[nl*HSTR + c] = (v - mu) * rs * gw[c] + gb[c];
        }
    }
    __syncthreads();
    // phase 2: per-token sum of squares (16 threads per token)
    {
        const int tok = t >> 4, l16 = t & 15;
        float ss = 0.f;
        #pragma unroll 8
        for (int i = 0; i < 32; i++) {
            const float v = hb[tok*HSTR + l16 + i*16];
            ss += v*v;
        }
        #pragma unroll
        for (int o = 1; o <= 8; o <<= 1) ss += __shfl_xor_sync(0xffffffffu, ss, o);
        if (l16 == 0) rms[tok] = rsqrtf(ss / (float)CH + EPSV);
    }
    __syncthreads();
    // phase 3: coalesced writes of g_h (fp32) and g_hnb (bf16)
    const int rowb = b*NTOK + n0;
    const float* shf = g_ada + b*6*CH;
    const float* scl = g_ada + b*6*CH + CH;
    #pragma unroll 4
    for (int i = 0; i < 16; i++) {
        const int idx = (t + i*512) * 2;
        const int tk = idx >> 9, c = idx & 511;
        const float h0 = hb[tk*HSTR + c], h1 = hb[tk*HSTR + c + 1];
        const float r = rms[tk];
        *(float2*)(g_h + (size_t)(rowb + tk)*CH + c) = make_float2(h0, h1);
        const float o0 = h0 * r * n1w[c]   * (1.f + scl[c])   + shf[c];
        const float o1 = h1 * r * n1w[c+1] * (1.f + scl[c+1]) + shf[c+1];
        *(uint32_t*)(g_hnb + (size_t)(rowb + tk)*CH + c) = pack2bf(o0, o1);
    }
}

// ---------------- RMSNorm + modulation -> bf16 (n2 path) ----------------
__global__ void k_rmsmod(const float* __restrict__ w, int shift_ch, int scale_ch) {
    const int row = blockIdx.x;
    const int b = row >> 10;
    const float* hp = g_h + (size_t)row * CH;
    const int t = threadIdx.x;
    float4 v = *(const float4*)(hp + t*4);
    float ss = v.x*v.x + v.y*v.y + v.z*v.z + v.w*v.w;
    #pragma unroll
    for (int o = 16; o; o >>= 1) ss += __shfl_xor_sync(0xffffffffu, ss, o);
    __shared__ float sh[4];
    if ((t & 31) == 0) sh[t >> 5] = ss;
    __syncthreads();
    ss = sh[0] + sh[1] + sh[2] + sh[3];
    const float r = rsqrtf(ss / (float)CH + EPSV);
    const float* shf = g_ada + b*6*CH + shift_ch*CH;
    const float* scl = g_ada + b*6*CH + scale_ch*CH;
    const int c = t*4;
    float o0 = v.x * r * w[c+0] * (1.f + scl[c+0]) + shf[c+0];
    float o1 = v.y * r * w[c+1] * (1.f + scl[c+1]) + shf[c+1];
    float o2 = v.z * r * w[c+2] * (1.f + scl[c+2]) + shf[c+2];
    float o3 = v.w * r * w[c+3] * (1.f + scl[c+3]) + shf[c+3];
    uint32_t* dp = (uint32_t*)(g_hnb + (size_t)row*CH + c);
    dp[0] = pack2bf(o0, o1);
    dp[1] = pack2bf(o2, o3);
}

// ---------------- BF16 GEMM, ldmatrix, 4-stage cp.async ----------------
// modes: 1 = bf16 store; 2 = g_h += gate*(acc+bias); 3 = fused swiglu;
//        4 = final: out = x + (g_h + gate*(acc+bias))^T  (transposed via smem)
#define WSTR 20
__global__ __launch_bounds__(256, 2) void k_gemm(
    const __nv_bfloat16* __restrict__ A, const __nv_bfloat16* __restrict__ W,
    const float* __restrict__ bias, float* __restrict__ Cf, uint32_t* __restrict__ Cb,
    __nv_bfloat16* __restrict__ Gb, const float* __restrict__ ada,
    const float* __restrict__ Xin, float* __restrict__ Oout,
    int gch, int mode, int M, int N, int K)
{
    extern __shared__ uint32_t sm[];
    const int tid  = threadIdx.x;
    const int lane = tid & 31;
    const int warp = tid >> 5;
    const int gid  = lane >> 2;
    const int tig  = lane & 3;
    const int row0 = (warp & 3) * 32;
    const int col0 = (warp >> 2) * 64;
    const int bm = blockIdx.y * 128, bn = blockIdx.x * 128;
    const int KT = K >> 5;
    const int lr   = lane & 7;
    const int sel8 = (lane >> 3) & 1;
    const int sel4 = (lane >> 4) & 1;

    const uint32_t sbase = (uint32_t)__cvta_generic_to_shared(sm);
    const uint32_t aoff  = ((row0 + sel8*8 + lr)*WSTR + sel4*4) * 4;
    const uint32_t boff  = ((col0 + sel8*8 + lr)*WSTR + sel4*4) * 4 + 2560*4;

    auto load_body = [&](int kt, int s) {
        uint32_t* As = sm + s * 5120;
        uint32_t* Ws = As + 2560;
        const int k0 = kt << 5;
        #pragma unroll
        for (int i = 0; i < 2; i++) {
            const int lin = tid + i*256;
            const int r = lin >> 2, c4 = lin & 3;
            cpa16(As + r*WSTR + c4*4, A + (size_t)(bm + r)*K + k0 + c4*8);
            cpa16(Ws + r*WSTR + c4*4, W + (size_t)(bn + r)*K + k0 + c4*8);
        }
    };

    load_body(0, 0);
    asm volatile("cp.async.commit_group;\n");
    load_body(1, 1);
    asm volatile("cp.async.commit_group;\n");
    load_body(2, 2);
    asm volatile("cp.async.commit_group;\n");

    float acc[2][8][4];
    #pragma unroll
    for (int i = 0; i < 2; i++)
        #pragma unroll
        for (int j = 0; j < 8; j++)
            #pragma unroll
            for (int c = 0; c < 4; c++) acc[i][j][c] = 0.f;

    for (int kt = 0; kt < KT; kt++) {
        asm volatile("cp.async.wait_group 2;\n");
        __syncthreads();
        if (kt + 3 < KT) load_body(kt + 3, (kt + 3) & 3);
        asm volatile("cp.async.commit_group;\n");

        const uint32_t stb = sbase + (uint32_t)((kt & 3) * 5120 * 4);
        #pragma unroll
        for (int kk = 0; kk < 2; kk++) {
            const uint32_t kb = kk * 32;
            uint32_t af[2][4], bf[8][2];
            const uint32_t aa = stb + aoff + kb;
            ldm4(aa,             af[0][0], af[0][1], af[0][2], af[0][3]);
            ldm4(aa + 16*WSTR*4, af[1][0], af[1][1], af[1][2], af[1][3]);
            const uint32_t bb = stb + boff + kb;
            #pragma unroll
            for (int nt2 = 0; nt2 < 4; nt2++) {
                ldm4(bb + nt2*16*WSTR*4,
                     bf[2*nt2][0], bf[2*nt2+1][0], bf[2*nt2][1], bf[2*nt2+1][1]);
            }
            #pragma unroll
            for (int mt = 0; mt < 2; mt++)
                #pragma unroll
                for (int nt = 0; nt < 8; nt++)
                    MMA_BF16(acc[mt][nt], af[mt], bf[nt]);
        }
    }

    if (mode == 4) {
        // final fused epilogue: h = g_h + gate*(acc+bias); out = x + h^T
        asm volatile("cp.async.wait_group 0;\n");
        __syncthreads();                      // smem free for staging
        float* hs = (float*)sm;               // 128 x 132
        #pragma unroll
        for (int mt = 0; mt < 2; mt++) {
            const int rl = row0 + mt*16 + gid;
            const int row = bm + rl;
            const int b = row >> 10;
            const float* gp = ada + b*6*CH + gch*CH;
            #pragma unroll
            for (int nt = 0; nt < 8; nt++) {
                const int cl = col0 + nt*8 + tig*2;
                const int col = bn + cl;
                const float b0 = bias[col], b1 = bias[col+1];
                float2 h0 = *(float2*)(Cf + (size_t)row*N + col);
                float2 h1 = *(float2*)(Cf + (size_t)(row+8)*N + col);
                hs[rl*132 + cl]       = h0.x + gp[col]  *(acc[mt][nt][0] + b0);
                hs[rl*132 + cl+1]     = h0.y + gp[col+1]*(acc[mt][nt][1] + b1);
                hs[(rl+8)*132 + cl]   = h1.x + gp[col]  *(acc[mt][nt][2] + b0);
                hs[(rl+8)*132 + cl+1] = h1.y + gp[col+1]*(acc[mt][nt][3] + b1);
            }
        }
        __syncthreads();
        const int b = bm >> 10;
        const int nbase = bm & 1023;
        #pragma unroll
        for (int i = 0; i < 16; i++) {
            const int lin = tid + i*256;      // 4096 float4 groups
            const int cr = lin >> 5, g = lin & 31;
            const size_t oidx = ((size_t)b*CH + bn + cr)*NTOK + nbase + g*4;
            float4 xs = *(const float4*)(Xin + oidx);
            xs.x += hs[(g*4+0)*132 + cr];
            xs.y += hs[(g*4+1)*132 + cr];
            xs.z += hs[(g*4+2)*132 + cr];
            xs.w += hs[(g*4+3)*132 + cr];
            *(float4*)(Oout + oidx) = xs;
        }
        return;
    }

    #pragma unroll
    for (int mt = 0; mt < 2; mt++) {
        const int row = bm + row0 + mt*16 + gid;
        const int b   = row >> 10;
        const float* gp = ada + b*6*CH + gch*CH;
        #pragma unroll
        for (int nt = 0; nt < 8; nt++) {
            const int col = bn + col0 + nt*8 + tig*2;
            const float b0 = bias[col], b1 = bias[col+1];
            float v00 = acc[mt][nt][0] + b0, v01 = acc[mt][nt][1] + b1;
            float v10 = acc[mt][nt][2] + b0, v11 = acc[mt][nt][3] + b1;
            if (mode == 1) {
                Cb[((size_t)row*N + col) >> 1]     = pack2bf(v00, v01);
                Cb[((size_t)(row+8)*N + col) >> 1] = pack2bf(v10, v11);
            } else if (mode == 2) {
                const float gg0 = gp[col], gg1 = gp[col+1];
                float2 h0 = *(float2*)(Cf + (size_t)row*N + col);
                float2 h1 = *(float2*)(Cf + (size_t)(row+8)*N + col);
                h0.x += gg0*v00; h0.y += gg1*v01;
                h1.x += gg0*v10; h1.y += gg1*v11;
                *(float2*)(Cf + (size_t)row*N + col)     = h0;
                *(float2*)(Cf + (size_t)(row+8)*N + col) = h1;
            } else {
                const int j = col >> 1;
                const float s0 = (v00 / (1.f + __expf(-v00))) * v01;
                const float s1 = (v10 / (1.f + __expf(-v10))) * v11;
                Gb[(size_t)row*(N>>1) + j]     = __float2bfloat16(s0);
                Gb[(size_t)(row+8)*(N>>1) + j] = __float2bfloat16(s1);
            }
        }
    }
}

// ---------------- q/k RMSNorm + RoPE (bf16 in) -> bf16 ----------------
__global__ void k_qkrope(const float* __restrict__ qn_w, const float* __restrict__ kn_w) {
    const int gw   = (blockIdx.x * blockDim.x + threadIdx.x) >> 5;
    const int lane = threadIdx.x & 31;
    const int head = gw & 7;
    const int tok  = gw >> 3;
    const int n = tok & 1023;
    const int rrow = n >> 5, rcol = n & 31;
    const uint32_t* qkvw = (const uint32_t*)g_qkvb;
    const size_t base = (size_t)tok * 768;
    float2 qv = __bfloat1622float2(*(const __nv_bfloat162*)&qkvw[base + head*32 + lane]);
    float2 kv = __bfloat1622float2(*(const __nv_bfloat162*)&qkvw[base + 256 + head*32 + lane]);
    float q0 = qv.x, q1 = qv.y, k0 = kv.x, k1 = kv.y;
    const int j = lane * 2;
    float sq = q0*q0 + q1*q1, sk = k0*k0 + k1*k1;
    #pragma unroll
    for (int o = 16; o; o >>= 1) {
        sq += __shfl_xor_sync(0xffffffffu, sq, o);
        sk += __shfl_xor_sync(0xffffffffu, sk, o);
    }
    const float rq = rsqrtf(sq / 64.f + EPSV);
    const float rk = rsqrtf(sk / 64.f + EPSV);
    q0 *= rq * qn_w[j];  q1 *= rq * qn_w[j+1];
    k0 *= rk * kn_w[j];  k1 *= rk * kn_w[j+1];
    const int half = (j >= 32);
    const int idx  = (half ? (j - 32) : j) >> 1;
    const float freq = exp2f(-(float)idx * (13.287712379549449f / 16.f));
    const float f = (half ? (float)rcol : (float)rrow) * freq;
    const float cf = cosf(f), sf = sinf(f);
    const float qa = q0*cf - q1*sf, qb = q1*cf + q0*sf;
    const float ka = k0*cf - k1*sf, kb = k1*cf + k0*sf;
    const float qs = 0.125f;
    uint32_t* qkw = (uint32_t*)g_qkb;
    qkw[(size_t)tok*512 + head*32 + lane]       = pack2bf(qa*qs, qb*qs);
    qkw[(size_t)tok*512 + 256 + head*32 + lane] = pack2bf(ka, kb);
}

// ---------------- V transpose: [tok][d] -> [b,h,d][tok], tiled ----------------
#define VSTR 72
__global__ __launch_bounds__(256) void k_vtrans() {
    __shared__ __nv_bfloat16 vt[128*VSTR];
    const int bh = blockIdx.x;               // b*8 + head
    const int b = bh >> 3, hh = bh & 7;
    const int t0 = blockIdx.y * 128;         // token chunk
    const int t = threadIdx.x;
    const __nv_bfloat16* src = g_qkvb + (size_t)(b*NTOK + t0) * 1536 + 1024 + hh*64;
    // load 128 tok x 64 d (uint4 = 8 bf16)
    #pragma unroll
    for (int i = 0; i < 4; i++) {
        const int lin = t + i*256;           // 1024
        const int r = lin >> 3, c8 = lin & 7;
        *(uint4*)(vt + r*VSTR + c8*8) = *(const uint4*)(src + (size_t)r*1536 + c8*8);
    }
    __syncthreads();
    // write 64 d-rows x 128 tok (each thread: 8 consecutive toks for one d)
    __nv_bfloat16* dst = g_vtb + (size_t)bh * 64 * NTOK + t0;
    #pragma unroll
    for (int i = 0; i < 4; i++) {
        const int lin = t + i*256;           // 1024
        const int d = lin >> 4, t8 = (lin & 15) * 8;
        uint16_t v[8];
        #pragma unroll
        for (int j = 0; j < 8; j++)
            v[j] = *(const uint16_t*)(vt + (t8 + j)*VSTR + d);
        uint4 o;
        o.x = (uint32_t)v[0] | ((uint32_t)v[1] << 16);
        o.y = (uint32_t)v[2] | ((uint32_t)v[3] << 16);
        o.z = (uint32_t)v[4] | ((uint32_t)v[5] << 16);
        o.w = (uint32_t)v[6] | ((uint32_t)v[7] << 16);
        *(uint4*)(dst + (size_t)d*NTOK + t8) = o;
    }
}

// ---------------- flash attention: P stays in registers ----------------
#define QSTR 36
__global__ __launch_bounds__(256) void k_attn_mma() {
    extern __shared__ uint32_t smw[];
    const int bh = blockIdx.x;
    const int b = bh >> 3, hh = bh & 7;
    const int q0 = blockIdx.y * 128;
    const int tid = threadIdx.x, lane = tid & 31, warp = tid >> 5;
    const int lr = lane & 7, sel8 = (lane >> 3) & 1, sel4 = (lane >> 4) & 1;
    const int gid = lane >> 2, tig = lane & 3;
    const __nv_bfloat16* qk = g_qkb + (size_t)b * NTOK * 1024;
    const __nv_bfloat16* vt = g_vtb + (size_t)bh * 64 * NTOK;

    const uint32_t sbase = (uint32_t)__cvta_generic_to_shared(smw);
    const uint32_t qoff  = ((warp*16 + sel8*8 + lr)*QSTR + sel4*4) * 4;
    const uint32_t kvoff = ((sel8*8 + lr)*QSTR + sel4*4) * 4;

    #pragma unroll
    for (int i = 0; i < 4; i++) {
        const int lin = tid + i*256;
        const int r = lin >> 3, c4 = lin & 7;
        cpa16(smw + r*QSTR + c4*4, qk + (size_t)(q0 + r)*1024 + hh*64 + c4*8);
    }
    asm volatile("cp.async.commit_group;\n");
    asm volatile("cp.async.wait_group 0;\n");
    __syncthreads();
    uint32_t qf[4][4];
    #pragma unroll
    for (int kk = 0; kk < 4; kk++)
        ldm4(sbase + qoff + kk*32, qf[kk][0], qf[kk][1], qf[kk][2], qf[kk][3]);
    __syncthreads();

    auto load_kv = [&](int kc, int s) {
        uint32_t* Ks = smw + s*128*QSTR;
        uint32_t* Vs = Ks + 64*QSTR;
        #pragma unroll
        for (int i = 0; i < 2; i++) {
            const int lin = tid + i*256;
            const int r = lin >> 3, c4 = lin & 7;
            cpa16(Ks + r*QSTR + c4*4, qk + (size_t)(kc + r)*1024 + 512 + hh*64 + c4*8);
            cpa16(Vs + r*QSTR + c4*4, vt + (size_t)r*NTOK + kc + c4*8);
        }
    };

    float l0 = 0.f, l1 = 0.f;
    float oacc[8][4];
    #pragma unroll
    for (int nt = 0; nt < 8; nt++)
        #pragma unroll
        for (int c = 0; c < 4; c++) oacc[nt][c] = 0.f;

    load_kv(0, 0);
    asm volatile("cp.async.commit_group;\n");

    for (int it = 0; it < NTOK/64; it++) {
        const int s = it & 1;
        if (it + 1 < NTOK/64) {
            load_kv((it+1)*64, s ^ 1);
            asm volatile("cp.async.commit_group;\n");
            asm volatile("cp.async.wait_group 1;\n");
        } else {
            asm volatile("cp.async.wait_group 0;\n");
        }
        __syncthreads();
        const uint32_t kbase = sbase + (uint32_t)(s*128*QSTR*4);
        const uint32_t vbase = kbase + 64*QSTR*4;

        float sacc[8][4];
        #pragma unroll
        for (int nt = 0; nt < 8; nt++)
            #pragma unroll
            for (int c = 0; c < 4; c++) sacc[nt][c] = 0.f;
        #pragma unroll
        for (int kk = 0; kk < 4; kk++) {
            uint32_t bf[8][2];
            const uint32_t kb = kbase + kvoff + kk*32;
            #pragma unroll
            for (int nt2 = 0; nt2 < 4; nt2++)
                ldm4(kb + nt2*16*QSTR*4,
                     bf[2*nt2][0], bf[2*nt2+1][0], bf[2*nt2][1], bf[2*nt2+1][1]);
            #pragma unroll
            for (int nt = 0; nt < 8; nt++)
                MMA_BF16(sacc[nt], qf[kk], bf[nt]);
        }

        uint32_t pa[8], pb[8];
        #pragma unroll
        for (int nt = 0; nt < 8; nt++) {
            const float p00 = __expf(sacc[nt][0] - 8.f);
            const float p01 = __expf(sacc[nt][1] - 8.f);
            const float p10 = __expf(sacc[nt][2] - 8.f);
            const float p11 = __expf(sacc[nt][3] - 8.f);
            l0 += p00 + p01;  l1 += p10 + p11;
            pa[nt] = pack2bf(p00, p01);
            pb[nt] = pack2bf(p10, p11);
        }

        #pragma unroll
        for (int kk = 0; kk < 4; kk++) {
            uint32_t af[4] = { pa[2*kk], pb[2*kk], pa[2*kk+1], pb[2*kk+1] };
            uint32_t bf[8][2];
            const uint32_t vb = vbase + kvoff + kk*32;
            #pragma unroll
            for (int nt2 = 0; nt2 < 4; nt2++)
                ldm4(vb + nt2*16*QSTR*4,
                     bf[2*nt2][0], bf[2*nt2+1][0], bf[2*nt2][1], bf[2*nt2+1][1]);
            #pragma unroll
            for (int nt = 0; nt < 8; nt++)
                MMA_BF16(oacc[nt], af, bf[nt]);
        }
        __syncthreads();
    }

    #pragma unroll
    for (int o = 1; o <= 2; o <<= 1) {
        l0 += __shfl_xor_sync(0xffffffffu, l0, o);
        l1 += __shfl_xor_sync(0xffffffffu, l1, o);
    }
    const float inv0 = 1.f / l0, inv1 = 1.f / l1;
    uint32_t* ow = (uint32_t*)g_attb;
    const size_t row = (size_t)b*NTOK + q0 + warp*16 + gid;
    #pragma unroll
    for (int nt = 0; nt < 8; nt++) {
        const int cw = hh*32 + nt*4 + tig;
        ow[row*256 + cw]     = pack2bf(oacc[nt][0]*inv0, oacc[nt][1]*inv0);
        ow[(row+8)*256 + cw] = pack2bf(oacc[nt][2]*inv1, oacc[nt][3]*inv1);
    }
}

// ---------------- launcher ----------------
extern "C" void kernel_launch(void* const* d_in, const int* in_sizes, int n_in,
                              void* d_out, int out_size) {
    const float* x      = (const float*)d_in[0];
    const float* temb   = (const float*)d_in[1];
    const float* gn_w   = (const float*)d_in[2];
    const float* gn_b   = (const float*)d_in[3];
    const float* ada_w  = (const float*)d_in[4];
    const float* ada_b  = (const float*)d_in[5];
    const float* n1_w   = (const float*)d_in[6];
    const float* n2_w   = (const float*)d_in[7];
    const float* qkv_w  = (const float*)d_in[8];
    const float* qkv_b  = (const float*)d_in[9];
    const float* qn_w   = (const float*)d_in[10];
    const float* kn_w   = (const float*)d_in[11];
    const float* proj_w = (const float*)d_in[12];
    const float* proj_b = (const float*)d_in[13];
    const float* w12    = (const float*)d_in[14];
    const float* b12    = (const float*)d_in[15];
    const float* w_out  = (const float*)d_in[16];
    const float* b_out  = (const float*)d_in[17];
    float* out = (float*)d_out;

    float *p_h, *p_ada, *p_b12p;
    __nv_bfloat16 *p_hnb, *p_qkvb, *p_attb, *p_gateb;
    __nv_bfloat16 *p_wqkv, *p_wproj, *p_w12c, *p_woc;
    cudaGetSymbolAddress((void**)&p_h,     g_h);
    cudaGetSymbolAddress((void**)&p_ada,   g_ada);
    cudaGetSymbolAddress((void**)&p_b12p,  g_b12p);
    cudaGetSymbolAddress((void**)&p_hnb,   g_hnb);
    cudaGetSymbolAddress((void**)&p_qkvb,  g_qkvb);
    cudaGetSymbolAddress((void**)&p_attb,  g_attb);
    cudaGetSymbolAddress((void**)&p_gateb, g_gateb);
    cudaGetSymbolAddress((void**)&p_wqkv,  g_wqkv);
    cudaGetSymbolAddress((void**)&p_wproj, g_wproj);
    cudaGetSymbolAddress((void**)&p_w12c,  g_w12c);
    cudaGetSymbolAddress((void**)&p_woc,   g_woc);

    const int gemm_smem  = 4*5120*4;          // 81920 B
    const int attn_smem  = 256*QSTR*4;        // 36864 B
    const int gnrms_smem = (32*HSTR + 32)*4;  // 65792 B
    cudaFuncSetAttribute(k_gemm,     cudaFuncAttributeMaxDynamicSharedMemorySize, gemm_smem);
    cudaFuncSetAttribute(k_attn_mma, cudaFuncAttributeMaxDynamicSharedMemorySize, attn_smem);
    cudaFuncSetAttribute(k_gnrms,    cudaFuncAttributeMaxDynamicSharedMemorySize, gnrms_smem);

    k_cvtall <<<(1048576 + FFN + 255)/256, 256>>>(qkv_w, proj_w, w_out, w12, b12);

    // adaLN + GroupNorm (+ fused rmsnorm/mod for attention branch)
    k_ada    <<<dim3(24, BDIM), 128>>>(temb, ada_w, ada_b);
    k_gnstats<<<BDIM*32, 256>>>(x);
    k_gnrms  <<<dim3(NTOK/32, BDIM), 512, gnrms_smem>>>(x, gn_w, gn_b, n1_w);

    // attention branch
    k_gemm   <<<dim3((3*CH)/128, NT/128), 256, gemm_smem>>>(
        p_hnb, p_wqkv, qkv_b, nullptr, (uint32_t*)p_qkvb, nullptr, p_ada,
        nullptr, nullptr, 0, 1, NT, 3*CH, CH);
    k_qkrope <<<(NT*NHEADS*32)/128, 128>>>(qn_w, kn_w);
    k_vtrans <<<dim3(BDIM*NHEADS, NTOK/128), 256>>>();
    k_attn_mma<<<dim3(BDIM*NHEADS, NTOK/128), 256, attn_smem>>>();
    k_gemm   <<<dim3(CH/128, NT/128), 256, gemm_smem>>>(
        p_attb, p_wproj, proj_b, p_h, nullptr, nullptr, p_ada,
        nullptr, nullptr, 2, 2, NT, CH, CH);

    // FFN branch
    k_rmsmod <<<NT, 128>>>(n2_w, 3, 4);
    k_gemm   <<<dim3((2*FFN)/128, NT/128), 256, gemm_smem>>>(
        p_hnb, p_w12c, p_b12p, nullptr, nullptr, p_gateb, p_ada,
        nullptr, nullptr, 0, 3, NT, 2*FFN, CH);
    // w_out GEMM with fused final epilogue (transposed out = x + h^T)
    k_gemm   <<<dim3(CH/128, NT/128), 256, gemm_smem>>>(
        p_gateb, p_woc, b_out, p_h, nullptr, nullptr, p_ada,
        x, out, 5, 4, NT, CH, FFN);
}